// round 5
// baseline (speedup 1.0000x reference)
#include <cuda_runtime.h>
#include <math.h>

// Problem constants (fixed by the dataset)
#define NMAX 100000
#define EMAX 800000

// Scratch (device globals: allocation-free per harness rules)
__device__ float g_Wedge[(size_t)EMAX * 256];   // 819.2 MB: per-edge 16x16 matrices
__device__ float g_h[3][NMAX * 16];             // slot 0 = h0, slots 1/2 = ping-pong h

// ---------------------------------------------------------------------------
// Edge MLP: e1 = relu(ea@W1+b1); e2 = relu(e1@W2+b2); Wedge = e2@W3+b3
// One warp per edge. All weights cached in shared memory (84.5 KB dynamic).
// ---------------------------------------------------------------------------
__global__ __launch_bounds__(256)
void edge_mlp_kernel(const float* __restrict__ edge_attr,
                     const float* __restrict__ W1, const float* __restrict__ b1,
                     const float* __restrict__ W2, const float* __restrict__ b2,
                     const float* __restrict__ W3, const float* __restrict__ b3,
                     int E)
{
    extern __shared__ float sm[];
    float* W3s = sm;            // 16384 floats
    float* W2s = sm + 16384;    // 4096
    float* W1s = sm + 20480;    // 256
    float* b1s = sm + 20736;    // 64
    float* b2s = sm + 20800;    // 64
    float* b3s = sm + 20864;    // 256  (total 21120 floats = 84480 B)

    int tid = threadIdx.x;
    for (int i = tid; i < 16384; i += 256) W3s[i] = W3[i];
    for (int i = tid; i < 4096;  i += 256) W2s[i] = W2[i];
    if (tid < 256) W1s[tid] = W1[tid];
    if (tid < 64) { b1s[tid] = b1[tid]; b2s[tid] = b2[tid]; }
    if (tid < 256) b3s[tid] = b3[tid];
    __syncthreads();

    int lane = tid & 31;
    int e = (blockIdx.x * 256 + tid) >> 5;
    if (e >= E) return;

    // ---- stage 1: 4 -> 64, lane owns m = 2*lane, 2*lane+1 ----
    float ea = (lane < 4) ? edge_attr[e * 4 + lane] : 0.f;
    float a0 = __shfl_sync(0xffffffffu, ea, 0);
    float a1 = __shfl_sync(0xffffffffu, ea, 1);
    float a2 = __shfl_sync(0xffffffffu, ea, 2);
    float a3 = __shfl_sync(0xffffffffu, ea, 3);
    int m0 = 2 * lane, m1 = 2 * lane + 1;
    float h1_0 = b1s[m0] + a0 * W1s[m0] + a1 * W1s[64 + m0] + a2 * W1s[128 + m0] + a3 * W1s[192 + m0];
    float h1_1 = b1s[m1] + a0 * W1s[m1] + a1 * W1s[64 + m1] + a2 * W1s[128 + m1] + a3 * W1s[192 + m1];
    h1_0 = fmaxf(h1_0, 0.f);
    h1_1 = fmaxf(h1_1, 0.f);

    // ---- stage 2: 64 -> 64 ----
    float h2_0 = b2s[m0], h2_1 = b2s[m1];
    const float2* W2s2 = (const float2*)W2s;
#pragma unroll
    for (int k = 0; k < 64; ++k) {
        float hk = __shfl_sync(0xffffffffu, (k & 1) ? h1_1 : h1_0, k >> 1);
        float2 w = W2s2[k * 32 + lane];
        h2_0 += hk * w.x;
        h2_1 += hk * w.y;
    }
    h2_0 = fmaxf(h2_0, 0.f);
    h2_1 = fmaxf(h2_1, 0.f);

    // ---- stage 3: 64 -> 256, lane owns io = lane + 32*j (conflict-free LDS,
    //      coalesced STG) ----
    float acc[8];
#pragma unroll
    for (int j = 0; j < 8; ++j) acc[j] = b3s[lane + 32 * j];
#pragma unroll
    for (int m = 0; m < 64; ++m) {
        float hm = __shfl_sync(0xffffffffu, (m & 1) ? h2_1 : h2_0, m >> 1);
#pragma unroll
        for (int j = 0; j < 8; ++j) acc[j] += hm * W3s[m * 256 + lane + 32 * j];
    }
    float* out = g_Wedge + (size_t)e * 256;
#pragma unroll
    for (int j = 0; j < 8; ++j) out[lane + 32 * j] = acc[j];
}

// ---------------------------------------------------------------------------
// h0 = [x | zeros]
// ---------------------------------------------------------------------------
__global__ void init_h_kernel(const float* __restrict__ x, int N)
{
    int idx = blockIdx.x * blockDim.x + threadIdx.x;
    if (idx >= N * 16) return;
    int n = idx >> 4, i = idx & 15;
    g_h[0][idx] = (i < 8) ? x[n * 8 + i] : 0.f;
}

// ---------------------------------------------------------------------------
// h_out = bias + h_in @ root   (messages accumulated on top afterwards)
// ---------------------------------------------------------------------------
__global__ void node_init_kernel(int in_slot, int out_slot,
                                 const float* __restrict__ root,
                                 const float* __restrict__ bias, int N)
{
    __shared__ float rs[256];
    __shared__ float bs[16];
    int tid = threadIdx.x;
    if (tid < 256) rs[tid] = root[tid];
    if (tid < 16)  bs[tid] = bias[tid];
    __syncthreads();
    int idx = blockIdx.x * blockDim.x + tid;
    if (idx >= N * 16) return;
    int n = idx >> 4, o = idx & 15;
    const float* hr = g_h[in_slot] + n * 16;
    float acc = bs[o];
#pragma unroll
    for (int i = 0; i < 16; ++i) acc += hr[i] * rs[i * 16 + o];
    g_h[out_slot][idx] = acc;
}

// ---------------------------------------------------------------------------
// Message pass: h_out[dst] += h_in[src] @ Wedge[e].  One warp per edge.
// ---------------------------------------------------------------------------
__global__ __launch_bounds__(256)
void msg_kernel(int in_slot, int out_slot, const int* __restrict__ edge_index, int E)
{
    int lane = threadIdx.x & 31;
    int e = (blockIdx.x * 256 + threadIdx.x) >> 5;
    if (e >= E) return;
    int src = edge_index[2 * e];
    int dst = edge_index[2 * e + 1];

    const float* h_in = g_h[in_slot];
    float hv = (lane < 16) ? h_in[src * 16 + lane] : 0.f;

    const float* W = g_Wedge + (size_t)e * 256;
    int hi = lane >> 4;          // 0 or 1: which i-parity this half-warp covers
    float p = 0.f;
#pragma unroll
    for (int k = 0; k < 8; ++k) {
        float w  = W[32 * k + lane];                       // io = 32k+lane: i=2k+hi, o=lane&15
        float hk = __shfl_sync(0xffffffffu, hv, 2 * k + hi);
        p += hk * w;
    }
    p += __shfl_xor_sync(0xffffffffu, p, 16);              // sum both i-parities
    if (lane < 16) atomicAdd(&g_h[out_slot][dst * 16 + lane], p);
}

// ---------------------------------------------------------------------------
// Readout: res = sum_n sigmoid(relu([h,h0]@Wi1+bi1)@Wi2+bi2) * (relu(h@Wj1+bj1)@Wj2+bj2)
// One warp per node, block-reduced, one atomic per block.
// ---------------------------------------------------------------------------
__global__ void zero_out_kernel(float* out)
{
    if (threadIdx.x == 0 && blockIdx.x == 0) out[0] = 0.f;
}

__global__ __launch_bounds__(256)
void readout_kernel(int h_slot,
                    const float* __restrict__ Wi1, const float* __restrict__ bi1,
                    const float* __restrict__ Wi2, const float* __restrict__ bi2,
                    const float* __restrict__ Wj1, const float* __restrict__ bj1,
                    const float* __restrict__ Wj2, const float* __restrict__ bj2,
                    float* __restrict__ out, int N)
{
    __shared__ float Wi1s[4096], Wj1s[2048];
    __shared__ float bi1s[128], bj1s[128], Wi2s[128], Wj2s[128];
    __shared__ float warpsum[8];

    int tid = threadIdx.x;
    for (int i = tid; i < 4096; i += 256) Wi1s[i] = Wi1[i];
    for (int i = tid; i < 2048; i += 256) Wj1s[i] = Wj1[i];
    if (tid < 128) {
        bi1s[tid] = bi1[tid]; bj1s[tid] = bj1[tid];
        Wi2s[tid] = Wi2[tid]; Wj2s[tid] = Wj2[tid];
    }
    __syncthreads();

    int lane = tid & 31, w = tid >> 5;
    int n = blockIdx.x * 8 + w;
    float contrib = 0.f;

    if (n < N) {
        const float* h  = g_h[h_slot] + n * 16;
        const float* h0 = g_h[0] + n * 16;
        float hv  = (lane < 16) ? h[lane]  : 0.f;
        float h0v = (lane < 16) ? h0[lane] : 0.f;

        // gate path: cat(h,h0) @ Wi1 (32x128), lane owns r = lane + 32*j
        float a0 = bi1s[lane], a1 = bi1s[lane + 32], a2 = bi1s[lane + 64], a3 = bi1s[lane + 96];
#pragma unroll
        for (int c = 0; c < 32; ++c) {
            float cc = __shfl_sync(0xffffffffu, (c < 16) ? hv : h0v, c & 15);
            a0 += cc * Wi1s[c * 128 + lane];
            a1 += cc * Wi1s[c * 128 + lane + 32];
            a2 += cc * Wi1s[c * 128 + lane + 64];
            a3 += cc * Wi1s[c * 128 + lane + 96];
        }
        a0 = fmaxf(a0, 0.f); a1 = fmaxf(a1, 0.f); a2 = fmaxf(a2, 0.f); a3 = fmaxf(a3, 0.f);
        float g = a0 * Wi2s[lane] + a1 * Wi2s[lane + 32] + a2 * Wi2s[lane + 64] + a3 * Wi2s[lane + 96];

        // value path: h @ Wj1 (16x128)
        float v0 = bj1s[lane], v1 = bj1s[lane + 32], v2 = bj1s[lane + 64], v3 = bj1s[lane + 96];
#pragma unroll
        for (int c = 0; c < 16; ++c) {
            float cc = __shfl_sync(0xffffffffu, hv, c);
            v0 += cc * Wj1s[c * 128 + lane];
            v1 += cc * Wj1s[c * 128 + lane + 32];
            v2 += cc * Wj1s[c * 128 + lane + 64];
            v3 += cc * Wj1s[c * 128 + lane + 96];
        }
        v0 = fmaxf(v0, 0.f); v1 = fmaxf(v1, 0.f); v2 = fmaxf(v2, 0.f); v3 = fmaxf(v3, 0.f);
        float vv = v0 * Wj2s[lane] + v1 * Wj2s[lane + 32] + v2 * Wj2s[lane + 64] + v3 * Wj2s[lane + 96];

#pragma unroll
        for (int s = 16; s > 0; s >>= 1) {
            g  += __shfl_xor_sync(0xffffffffu, g, s);
            vv += __shfl_xor_sync(0xffffffffu, vv, s);
        }
        if (lane == 0) {
            float gate = 1.f / (1.f + expf(-(g + bi2[0])));
            contrib = gate * (vv + bj2[0]);
        }
    }
    if (lane == 0) warpsum[w] = contrib;
    __syncthreads();
    if (tid == 0) {
        float s = 0.f;
#pragma unroll
        for (int i = 0; i < 8; ++i) s += warpsum[i];
        atomicAdd(out, s);
    }
}

// ---------------------------------------------------------------------------
extern "C" void kernel_launch(void* const* d_in, const int* in_sizes, int n_in,
                              void* d_out, int out_size)
{
    const float* x          = (const float*)d_in[0];
    const int*   edge_index = (const int*)  d_in[1];
    const float* edge_attr  = (const float*)d_in[2];
    const float* W1  = (const float*)d_in[3];
    const float* b1  = (const float*)d_in[4];
    const float* W2  = (const float*)d_in[5];
    const float* b2  = (const float*)d_in[6];
    const float* W3  = (const float*)d_in[7];
    const float* b3  = (const float*)d_in[8];
    const float* root = (const float*)d_in[9];
    const float* bias = (const float*)d_in[10];
    const float* Wi1 = (const float*)d_in[11];
    const float* bi1 = (const float*)d_in[12];
    const float* Wi2 = (const float*)d_in[13];
    const float* bi2 = (const float*)d_in[14];
    const float* Wj1 = (const float*)d_in[15];
    const float* bj1 = (const float*)d_in[16];
    const float* Wj2 = (const float*)d_in[17];
    const float* bj2 = (const float*)d_in[18];

    int N = in_sizes[0] / 8;  if (N > NMAX) N = NMAX;
    int E = in_sizes[1] / 2;  if (E > EMAX) E = EMAX;
    float* out = (float*)d_out;

    const int SMEM_MLP = 21120 * (int)sizeof(float);  // 84480 B
    cudaFuncSetAttribute(edge_mlp_kernel,
                         cudaFuncAttributeMaxDynamicSharedMemorySize, SMEM_MLP);

    int node_blocks = (N * 16 + 255) / 256;
    int edge_blocks = (E + 7) / 8;          // 8 warps/block, 1 edge/warp

    // 1) Per-edge 16x16 message matrices (the big GEMM), materialized once.
    edge_mlp_kernel<<<edge_blocks, 256, SMEM_MLP>>>(edge_attr, W1, b1, W2, b2, W3, b3, E);

    // 2) h0
    init_h_kernel<<<node_blocks, 256>>>(x, N);

    // 3) Three propagation rounds: slot sequence 0 -> 1 -> 2 -> 1
    int in_slot = 0;
    int out_slots[3] = {1, 2, 1};
    for (int t = 0; t < 3; ++t) {
        int o = out_slots[t];
        node_init_kernel<<<node_blocks, 256>>>(in_slot, o, root, bias, N);
        msg_kernel<<<edge_blocks, 256>>>(in_slot, o, edge_index, E);
        in_slot = o;
    }

    // 4) Gated readout -> scalar
    zero_out_kernel<<<1, 32>>>(out);
    readout_kernel<<<(N + 7) / 8, 256>>>(in_slot, Wi1, bi1, Wi2, bi2,
                                         Wj1, bj1, Wj2, bj2, out, N);
}

// round 7
// speedup vs baseline: 1.9957x; 1.9957x over previous
#include <cuda_runtime.h>
#include <math.h>
#include <stdint.h>

// Problem constants (fixed by the dataset)
#define NMAX 100000
#define EMAX 800000

// Scratch (device globals: allocation-free per harness rules)
__device__ float  g_Wedge[(size_t)EMAX * 256];   // 819 MB per-edge 16x16 matrices
__device__ float  g_h[3][NMAX * 16];             // slot0 = h0, 1/2 ping-pong
__device__ float  g_e2f[(size_t)EMAX * 64];      // e2 fp32 (stage-2 output), 205 MB
__device__ float2 g_Btf[64 * 256];               // W3 as tf32 limb pairs {hi, lo}

// ---------------------------------------------------------------------------
// tf32 helpers (mma.sync is sm_80+, compiles for plain compute_100)
// ---------------------------------------------------------------------------
__device__ __forceinline__ void tf32_split(float x, uint32_t& hi, uint32_t& lo) {
    asm("cvt.rna.tf32.f32 %0, %1;" : "=r"(hi) : "f"(x));
    float r = x - __uint_as_float(hi);
    asm("cvt.rna.tf32.f32 %0, %1;" : "=r"(lo) : "f"(r));
}

__device__ __forceinline__ void mma_tf32(float* c, const uint32_t* a,
                                         uint32_t b0, uint32_t b1) {
    asm volatile(
        "mma.sync.aligned.m16n8k8.row.col.f32.tf32.tf32.f32 "
        "{%0,%1,%2,%3}, {%4,%5,%6,%7}, {%8,%9}, {%0,%1,%2,%3};"
        : "+f"(c[0]), "+f"(c[1]), "+f"(c[2]), "+f"(c[3])
        : "r"(a[0]), "r"(a[1]), "r"(a[2]), "r"(a[3]), "r"(b0), "r"(b1));
}

// ---------------------------------------------------------------------------
// Stage 1+2 of edge MLP: e2 = relu(relu(ea@W1+b1)@W2+b2) -> fp32 [E,64]
// One warp per edge; lane owns outputs m0=2*lane, m1=2*lane+1.
// ---------------------------------------------------------------------------
__global__ __launch_bounds__(256)
void edge_stage12_kernel(const float* __restrict__ edge_attr,
                         const float* __restrict__ W1, const float* __restrict__ b1,
                         const float* __restrict__ W2, const float* __restrict__ b2,
                         int E)
{
    __shared__ float W1s[256], W2s[4096], b1s[64], b2s[64];
    int tid = threadIdx.x;
    for (int i = tid; i < 4096; i += 256) W2s[i] = W2[i];
    if (tid < 256) W1s[tid] = W1[tid];
    if (tid < 64) { b1s[tid] = b1[tid]; b2s[tid] = b2[tid]; }
    __syncthreads();

    int lane = tid & 31;
    int e = (blockIdx.x * 256 + tid) >> 5;
    if (e >= E) return;

    float ea = (lane < 4) ? edge_attr[e * 4 + lane] : 0.f;
    float a0 = __shfl_sync(0xffffffffu, ea, 0);
    float a1 = __shfl_sync(0xffffffffu, ea, 1);
    float a2 = __shfl_sync(0xffffffffu, ea, 2);
    float a3 = __shfl_sync(0xffffffffu, ea, 3);
    int m0 = 2 * lane, m1 = 2 * lane + 1;
    float h1_0 = b1s[m0] + a0 * W1s[m0] + a1 * W1s[64 + m0] + a2 * W1s[128 + m0] + a3 * W1s[192 + m0];
    float h1_1 = b1s[m1] + a0 * W1s[m1] + a1 * W1s[64 + m1] + a2 * W1s[128 + m1] + a3 * W1s[192 + m1];
    h1_0 = fmaxf(h1_0, 0.f);
    h1_1 = fmaxf(h1_1, 0.f);

    float h2_0 = b2s[m0], h2_1 = b2s[m1];
    const float2* W2s2 = (const float2*)W2s;
#pragma unroll
    for (int k = 0; k < 64; ++k) {
        float hk = __shfl_sync(0xffffffffu, (k & 1) ? h1_1 : h1_0, k >> 1);
        float2 w = W2s2[k * 32 + lane];
        h2_0 += hk * w.x;
        h2_1 += hk * w.y;
    }
    h2_0 = fmaxf(h2_0, 0.f);
    h2_1 = fmaxf(h2_1, 0.f);

    ((float2*)g_e2f)[(size_t)e * 32 + lane] = make_float2(h2_0, h2_1);
}

// W3 [64,256] fp32 -> tf32 limb pairs (same k-major layout; no transpose needed)
__global__ void w3_split_kernel(const float* __restrict__ W3)
{
    int idx = blockIdx.x * blockDim.x + threadIdx.x;
    if (idx >= 64 * 256) return;
    uint32_t hi, lo;
    tf32_split(W3[idx], hi, lo);
    g_Btf[idx] = make_float2(__uint_as_float(hi), __uint_as_float(lo));
}

// ---------------------------------------------------------------------------
// Stage 3 via mma.sync tf32: Wedge = e2 @ W3 + b3
// Block: 128 edges x 256 outputs, K=64. 8 warps = 8 m16 tiles; 2 n-halves.
// 3 limb products per mma step (hh, lh, hl) => fp32-grade accuracy.
// ---------------------------------------------------------------------------
// smem: Bs float2[64][260] (133120 B) | As float[128][68] (34816 B) | b3 (1024 B)
#define G_BS_F2   (64 * 260)
#define G_AS_OFF  (G_BS_F2 * 8)
#define G_B3_OFF  (G_AS_OFF + 128 * 68 * 4)
#define G_SMEM    (G_B3_OFF + 256 * 4)   // 168960 B

__global__ __launch_bounds__(256, 1)
void wedge_gemm_kernel(const float* __restrict__ b3, int E)
{
    extern __shared__ char smem[];
    float2* Bs = (float2*)smem;                    // [64][260] {hi,lo}
    float*  As = (float*)(smem + G_AS_OFF);        // [128][68]
    float*  b3s = (float*)(smem + G_B3_OFF);

    int tid = threadIdx.x;
    // B: conflict-free padded layout (260 mod 16 == 4)
    for (int i = tid; i < 64 * 256; i += 256) {
        int k = i >> 8, n = i & 255;
        Bs[k * 260 + n] = g_Btf[i];
    }
    if (tid < 256) b3s[tid] = b3[tid];

    size_t ebase = (size_t)blockIdx.x * 128;
    for (int i = tid; i < 128 * 64; i += 256) {
        int r = i >> 6, cc = i & 63;
        float v = (ebase + (size_t)r < (size_t)E) ? g_e2f[(ebase + r) * 64 + cc] : 0.f;
        As[r * 68 + cc] = v;
    }
    __syncthreads();

    int lane = tid & 31, wid = tid >> 5;
    int g = lane >> 2, tg = lane & 3;
    int r0 = wid * 16 + g;

#pragma unroll
    for (int half = 0; half < 2; ++half) {
        float c[16][4];
#pragma unroll
        for (int nt = 0; nt < 16; ++nt) {
            c[nt][0] = 0.f; c[nt][1] = 0.f; c[nt][2] = 0.f; c[nt][3] = 0.f;
        }

#pragma unroll
        for (int ks = 0; ks < 8; ++ks) {
            int acol = ks * 8 + tg;
            float af0 = As[r0 * 68 + acol];
            float af1 = As[(r0 + 8) * 68 + acol];
            float af2 = As[r0 * 68 + acol + 4];
            float af3 = As[(r0 + 8) * 68 + acol + 4];
            uint32_t ah[4], al[4];
            tf32_split(af0, ah[0], al[0]);
            tf32_split(af1, ah[1], al[1]);
            tf32_split(af2, ah[2], al[2]);
            tf32_split(af3, ah[3], al[3]);

            const float2* brow0 = Bs + (ks * 8 + tg) * 260 + half * 128 + g;
            const float2* brow1 = Bs + (ks * 8 + tg + 4) * 260 + half * 128 + g;
#pragma unroll
            for (int nt = 0; nt < 16; ++nt) {
                float2 b0v = brow0[nt * 8];
                float2 b1v = brow1[nt * 8];
                uint32_t bh0 = __float_as_uint(b0v.x), bl0 = __float_as_uint(b0v.y);
                uint32_t bh1 = __float_as_uint(b1v.x), bl1 = __float_as_uint(b1v.y);
                mma_tf32(c[nt], ah, bh0, bh1);   // hi * hi
                mma_tf32(c[nt], al, bh0, bh1);   // lo * hi
                mma_tf32(c[nt], ah, bl0, bl1);   // hi * lo
            }
        }

        // store C (+b3): c0/c1 -> row r0, c2/c3 -> row r0+8
        size_t e0 = ebase + (size_t)r0;
        size_t e1 = e0 + 8;
        bool v0 = e0 < (size_t)E, v1 = e1 < (size_t)E;
#pragma unroll
        for (int nt = 0; nt < 16; ++nt) {
            int n0 = half * 128 + nt * 8 + 2 * tg;
            float bb0 = b3s[n0], bb1 = b3s[n0 + 1];
            if (v0) *(float2*)(g_Wedge + e0 * 256 + n0) =
                        make_float2(c[nt][0] + bb0, c[nt][1] + bb1);
            if (v1) *(float2*)(g_Wedge + e1 * 256 + n0) =
                        make_float2(c[nt][2] + bb0, c[nt][3] + bb1);
        }
    }
}

// ---------------------------------------------------------------------------
// h0 = [x | zeros]
// ---------------------------------------------------------------------------
__global__ void init_h_kernel(const float* __restrict__ x, int N)
{
    int idx = blockIdx.x * blockDim.x + threadIdx.x;
    if (idx >= N * 16) return;
    int n = idx >> 4, i = idx & 15;
    g_h[0][idx] = (i < 8) ? x[n * 8 + i] : 0.f;
}

// h_out = bias + h_in @ root
__global__ void node_init_kernel(int in_slot, int out_slot,
                                 const float* __restrict__ root,
                                 const float* __restrict__ bias, int N)
{
    __shared__ float rs[256];
    __shared__ float bs[16];
    int tid = threadIdx.x;
    if (tid < 256) rs[tid] = root[tid];
    if (tid < 16)  bs[tid] = bias[tid];
    __syncthreads();
    int idx = blockIdx.x * blockDim.x + tid;
    if (idx >= N * 16) return;
    int n = idx >> 4, o = idx & 15;
    const float* hr = g_h[in_slot] + n * 16;
    float acc = bs[o];
#pragma unroll
    for (int i = 0; i < 16; ++i) acc += hr[i] * rs[i * 16 + o];
    g_h[out_slot][idx] = acc;
}

// Message pass: h_out[dst] += h_in[src] @ Wedge[e]. One warp per edge.
__global__ __launch_bounds__(256)
void msg_kernel(int in_slot, int out_slot, const int* __restrict__ edge_index, int E)
{
    int lane = threadIdx.x & 31;
    int e = (blockIdx.x * 256 + threadIdx.x) >> 5;
    if (e >= E) return;
    int src = edge_index[2 * e];
    int dst = edge_index[2 * e + 1];

    const float* h_in = g_h[in_slot];
    float hv = (lane < 16) ? h_in[src * 16 + lane] : 0.f;

    const float* W = g_Wedge + (size_t)e * 256;
    int hi = lane >> 4;
    float p = 0.f;
#pragma unroll
    for (int k = 0; k < 8; ++k) {
        float w  = W[32 * k + lane];
        float hk = __shfl_sync(0xffffffffu, hv, 2 * k + hi);
        p += hk * w;
    }
    p += __shfl_xor_sync(0xffffffffu, p, 16);
    if (lane < 16) atomicAdd(&g_h[out_slot][dst * 16 + lane], p);
}

// ---------------------------------------------------------------------------
// Readout
// ---------------------------------------------------------------------------
__global__ void zero_out_kernel(float* out)
{
    if (threadIdx.x == 0 && blockIdx.x == 0) out[0] = 0.f;
}

__global__ __launch_bounds__(256)
void readout_kernel(int h_slot,
                    const float* __restrict__ Wi1, const float* __restrict__ bi1,
                    const float* __restrict__ Wi2, const float* __restrict__ bi2,
                    const float* __restrict__ Wj1, const float* __restrict__ bj1,
                    const float* __restrict__ Wj2, const float* __restrict__ bj2,
                    float* __restrict__ out, int N)
{
    __shared__ float Wi1s[4096], Wj1s[2048];
    __shared__ float bi1s[128], bj1s[128], Wi2s[128], Wj2s[128];
    __shared__ float warpsum[8];

    int tid = threadIdx.x;
    for (int i = tid; i < 4096; i += 256) Wi1s[i] = Wi1[i];
    for (int i = tid; i < 2048; i += 256) Wj1s[i] = Wj1[i];
    if (tid < 128) {
        bi1s[tid] = bi1[tid]; bj1s[tid] = bj1[tid];
        Wi2s[tid] = Wi2[tid]; Wj2s[tid] = Wj2[tid];
    }
    __syncthreads();

    int lane = tid & 31, w = tid >> 5;
    int n = blockIdx.x * 8 + w;
    float contrib = 0.f;

    if (n < N) {
        const float* h  = g_h[h_slot] + n * 16;
        const float* h0 = g_h[0] + n * 16;
        float hv  = (lane < 16) ? h[lane]  : 0.f;
        float h0v = (lane < 16) ? h0[lane] : 0.f;

        float a0 = bi1s[lane], a1 = bi1s[lane + 32], a2 = bi1s[lane + 64], a3 = bi1s[lane + 96];
#pragma unroll
        for (int c = 0; c < 32; ++c) {
            float cc = __shfl_sync(0xffffffffu, (c < 16) ? hv : h0v, c & 15);
            a0 += cc * Wi1s[c * 128 + lane];
            a1 += cc * Wi1s[c * 128 + lane + 32];
            a2 += cc * Wi1s[c * 128 + lane + 64];
            a3 += cc * Wi1s[c * 128 + lane + 96];
        }
        a0 = fmaxf(a0, 0.f); a1 = fmaxf(a1, 0.f); a2 = fmaxf(a2, 0.f); a3 = fmaxf(a3, 0.f);
        float g = a0 * Wi2s[lane] + a1 * Wi2s[lane + 32] + a2 * Wi2s[lane + 64] + a3 * Wi2s[lane + 96];

        float v0 = bj1s[lane], v1 = bj1s[lane + 32], v2 = bj1s[lane + 64], v3 = bj1s[lane + 96];
#pragma unroll
        for (int c = 0; c < 16; ++c) {
            float cc = __shfl_sync(0xffffffffu, hv, c);
            v0 += cc * Wj1s[c * 128 + lane];
            v1 += cc * Wj1s[c * 128 + lane + 32];
            v2 += cc * Wj1s[c * 128 + lane + 64];
            v3 += cc * Wj1s[c * 128 + lane + 96];
        }
        v0 = fmaxf(v0, 0.f); v1 = fmaxf(v1, 0.f); v2 = fmaxf(v2, 0.f); v3 = fmaxf(v3, 0.f);
        float vv = v0 * Wj2s[lane] + v1 * Wj2s[lane + 32] + v2 * Wj2s[lane + 64] + v3 * Wj2s[lane + 96];

#pragma unroll
        for (int s = 16; s > 0; s >>= 1) {
            g  += __shfl_xor_sync(0xffffffffu, g, s);
            vv += __shfl_xor_sync(0xffffffffu, vv, s);
        }
        if (lane == 0) {
            float gate = 1.f / (1.f + expf(-(g + bi2[0])));
            contrib = gate * (vv + bj2[0]);
        }
    }
    if (lane == 0) warpsum[w] = contrib;
    __syncthreads();
    if (tid == 0) {
        float s = 0.f;
#pragma unroll
        for (int i = 0; i < 8; ++i) s += warpsum[i];
        atomicAdd(out, s);
    }
}

// ===========================================================================
extern "C" void kernel_launch(void* const* d_in, const int* in_sizes, int n_in,
                              void* d_out, int out_size)
{
    const float* x          = (const float*)d_in[0];
    const int*   edge_index = (const int*)  d_in[1];
    const float* edge_attr  = (const float*)d_in[2];
    const float* W1  = (const float*)d_in[3];
    const float* b1  = (const float*)d_in[4];
    const float* W2  = (const float*)d_in[5];
    const float* b2  = (const float*)d_in[6];
    const float* W3  = (const float*)d_in[7];
    const float* b3  = (const float*)d_in[8];
    const float* root = (const float*)d_in[9];
    const float* bias = (const float*)d_in[10];
    const float* Wi1 = (const float*)d_in[11];
    const float* bi1 = (const float*)d_in[12];
    const float* Wi2 = (const float*)d_in[13];
    const float* bi2 = (const float*)d_in[14];
    const float* Wj1 = (const float*)d_in[15];
    const float* bj1 = (const float*)d_in[16];
    const float* Wj2 = (const float*)d_in[17];
    const float* bj2 = (const float*)d_in[18];

    int N = in_sizes[0] / 8;  if (N > NMAX) N = NMAX;
    int E = in_sizes[1] / 2;  if (E > EMAX) E = EMAX;
    float* out = (float*)d_out;

    cudaFuncSetAttribute(wedge_gemm_kernel,
                         cudaFuncAttributeMaxDynamicSharedMemorySize, G_SMEM);

    int node_blocks = (N * 16 + 255) / 256;
    int edge_blocks = (E + 7) / 8;
    int gemm_blocks = (E + 127) / 128;

    // 1) Edge MLP stages 1-2 -> e2 fp32
    edge_stage12_kernel<<<edge_blocks, 256>>>(edge_attr, W1, b1, W2, b2, E);
    // 2) W3 tf32 limb split
    w3_split_kernel<<<64, 256>>>(W3);
    // 3) Stage-3 GEMM on legacy tensor cores (tf32 2-limb, 3 products) -> Wedge
    wedge_gemm_kernel<<<gemm_blocks, 256, G_SMEM>>>(b3, E);

    // 4) h0
    init_h_kernel<<<node_blocks, 256>>>(x, N);

    // 5) Three propagation rounds
    int in_slot = 0;
    int out_slots[3] = {1, 2, 1};
    for (int t = 0; t < 3; ++t) {
        int o = out_slots[t];
        node_init_kernel<<<node_blocks, 256>>>(in_slot, o, root, bias, N);
        msg_kernel<<<edge_blocks, 256>>>(in_slot, o, edge_index, E);
        in_slot = o;
    }

    // 6) Gated readout -> scalar
    zero_out_kernel<<<1, 32>>>(out);
    readout_kernel<<<(N + 7) / 8, 256>>>(in_slot, Wi1, bi1, Wi2, bi2,
                                         Wj1, bj1, Wj2, bj2, out, N);
}

// round 8
// speedup vs baseline: 3.0081x; 1.5073x over previous
#include <cuda_runtime.h>
#include <math.h>
#include <stdint.h>

// Problem constants (fixed by the dataset)
#define NMAX 100000
#define EMAX 800000

// Scratch (device globals: allocation-free per harness rules)
__device__ float  g_Wedge[(size_t)EMAX * 256];   // 819 MB per-edge 16x16 matrices
__device__ float  g_h[3][NMAX * 16];             // slot0 = h0, 1/2 ping-pong
__device__ float  g_e2f[(size_t)EMAX * 64];      // e2 fp32 (stage-2 output), 205 MB
__device__ float2 g_Btf[64 * 256];               // W3 as tf32 limb pairs {hi, lo}

// ---------------------------------------------------------------------------
// tf32 helpers (mma.sync is sm_80+, compiles for plain compute_100)
// ---------------------------------------------------------------------------
__device__ __forceinline__ void tf32_split(float x, uint32_t& hi, uint32_t& lo) {
    asm("cvt.rna.tf32.f32 %0, %1;" : "=r"(hi) : "f"(x));
    float r = x - __uint_as_float(hi);
    asm("cvt.rna.tf32.f32 %0, %1;" : "=r"(lo) : "f"(r));
}

__device__ __forceinline__ void mma_tf32(float* c, const uint32_t* a,
                                         uint32_t b0, uint32_t b1) {
    asm volatile(
        "mma.sync.aligned.m16n8k8.row.col.f32.tf32.tf32.f32 "
        "{%0,%1,%2,%3}, {%4,%5,%6,%7}, {%8,%9}, {%0,%1,%2,%3};"
        : "+f"(c[0]), "+f"(c[1]), "+f"(c[2]), "+f"(c[3])
        : "r"(a[0]), "r"(a[1]), "r"(a[2]), "r"(a[3]), "r"(b0), "r"(b1));
}

// ---------------------------------------------------------------------------
// Stage 1+2 of edge MLP, THREAD-per-edge (FMA-pipe bound).
// h1 (64 floats) staged per-thread in smem column (stride 256 => own bank).
// Dynamic smem: h1s 65536 B + W2s 16384 B = 81920 B.
// ---------------------------------------------------------------------------
#define S12_SMEM (65536 + 16384)

__global__ __launch_bounds__(256)
void edge_stage12_kernel(const float* __restrict__ edge_attr,
                         const float* __restrict__ W1, const float* __restrict__ b1,
                         const float* __restrict__ W2, const float* __restrict__ b2,
                         int E)
{
    extern __shared__ float dsm[];
    float* h1s = dsm;            // [64][256] per-thread columns
    float* W2s = dsm + 16384;    // [64][64] k-major
    __shared__ float W1s[256], b1s[64], b2s[64];

    int tid = threadIdx.x;
    for (int i = tid; i < 4096; i += 256) W2s[i] = W2[i];
    if (tid < 256) W1s[tid] = W1[tid];
    if (tid < 64) { b1s[tid] = b1[tid]; b2s[tid] = b2[tid]; }
    __syncthreads();

    int e = blockIdx.x * 256 + tid;
    if (e >= E) return;

    // stage 1: 4 -> 64
    float4 a = ((const float4*)edge_attr)[e];
    const float4* W1s4 = (const float4*)W1s;
    const float4* b1s4 = (const float4*)b1s;
#pragma unroll
    for (int m4 = 0; m4 < 16; ++m4) {
        float4 w0 = W1s4[m4];           // k=0 row
        float4 w1 = W1s4[16 + m4];      // k=1
        float4 w2 = W1s4[32 + m4];      // k=2
        float4 w3 = W1s4[48 + m4];      // k=3
        float4 bb = b1s4[m4];
        float v0 = bb.x + a.x * w0.x + a.y * w1.x + a.z * w2.x + a.w * w3.x;
        float v1 = bb.y + a.x * w0.y + a.y * w1.y + a.z * w2.y + a.w * w3.y;
        float v2 = bb.z + a.x * w0.z + a.y * w1.z + a.z * w2.z + a.w * w3.z;
        float v3 = bb.w + a.x * w0.w + a.y * w1.w + a.z * w2.w + a.w * w3.w;
        h1s[(m4 * 4 + 0) * 256 + tid] = fmaxf(v0, 0.f);
        h1s[(m4 * 4 + 1) * 256 + tid] = fmaxf(v1, 0.f);
        h1s[(m4 * 4 + 2) * 256 + tid] = fmaxf(v2, 0.f);
        h1s[(m4 * 4 + 3) * 256 + tid] = fmaxf(v3, 0.f);
    }

    // stage 2: 64 -> 64, 4 chunks of 16 outputs
    const float4* W2s4 = (const float4*)W2s;
    float4* e2out = (float4*)(g_e2f + (size_t)e * 64);
#pragma unroll
    for (int c = 0; c < 4; ++c) {
        float acc[16];
#pragma unroll
        for (int j = 0; j < 16; ++j) acc[j] = b2s[c * 16 + j];
#pragma unroll 8
        for (int k = 0; k < 64; ++k) {
            float hk = h1s[k * 256 + tid];
            float4 w0 = W2s4[k * 16 + c * 4 + 0];
            float4 w1 = W2s4[k * 16 + c * 4 + 1];
            float4 w2 = W2s4[k * 16 + c * 4 + 2];
            float4 w3 = W2s4[k * 16 + c * 4 + 3];
            acc[0]  += hk * w0.x;  acc[1]  += hk * w0.y;
            acc[2]  += hk * w0.z;  acc[3]  += hk * w0.w;
            acc[4]  += hk * w1.x;  acc[5]  += hk * w1.y;
            acc[6]  += hk * w1.z;  acc[7]  += hk * w1.w;
            acc[8]  += hk * w2.x;  acc[9]  += hk * w2.y;
            acc[10] += hk * w2.z;  acc[11] += hk * w2.w;
            acc[12] += hk * w3.x;  acc[13] += hk * w3.y;
            acc[14] += hk * w3.z;  acc[15] += hk * w3.w;
        }
#pragma unroll
        for (int j4 = 0; j4 < 4; ++j4) {
            e2out[c * 4 + j4] = make_float4(fmaxf(acc[j4*4+0], 0.f),
                                            fmaxf(acc[j4*4+1], 0.f),
                                            fmaxf(acc[j4*4+2], 0.f),
                                            fmaxf(acc[j4*4+3], 0.f));
        }
    }
}

// W3 [64,256] fp32 -> tf32 limb pairs (same k-major layout)
__global__ void w3_split_kernel(const float* __restrict__ W3)
{
    int idx = blockIdx.x * blockDim.x + threadIdx.x;
    if (idx >= 64 * 256) return;
    uint32_t hi, lo;
    tf32_split(W3[idx], hi, lo);
    g_Btf[idx] = make_float2(__uint_as_float(hi), __uint_as_float(lo));
}

// ---------------------------------------------------------------------------
// Stage 3 via mma.sync tf32 (3 limb products): Wedge = e2 @ W3 + b3
// PERSISTENT: grid=148, B fragments loaded into smem ONCE per SM.
// Warp grid 4m x 2n: warp = m32 x n128 (2 m16-tiles, n in 2 groups of 64).
// ---------------------------------------------------------------------------
// smem: Bs float2[64][260] (133120 B) | As float[128][68] (34816 B) | b3 (1024 B)
#define G_AS_OFF  133120
#define G_B3_OFF  (G_AS_OFF + 128 * 68 * 4)
#define G_SMEM    (G_B3_OFF + 256 * 4)   // 169984 B

__global__ __launch_bounds__(256, 1)
void wedge_gemm_kernel(const float* __restrict__ b3, int E, int ntiles)
{
    extern __shared__ char smem[];
    float2* Bs  = (float2*)smem;                  // [64][260] {hi,lo}
    float*  As  = (float*)(smem + G_AS_OFF);      // [128][68]
    float*  b3s = (float*)(smem + G_B3_OFF);

    int tid = threadIdx.x;
    // Load B fragments + b3 ONCE (persistent kernel)
    for (int i = tid; i < 64 * 256; i += 256) {
        int k = i >> 8, n = i & 255;
        Bs[k * 260 + n] = g_Btf[i];
    }
    if (tid < 256) b3s[tid] = b3[tid];

    int lane = tid & 31, wid = tid >> 5;
    int qr = lane >> 2, tg = lane & 3;
    int mrow = (wid & 3) * 32;            // warp's 32-row block
    int noff0 = (wid >> 2) * 128;         // warp's 128-col block
    float4* As4 = (float4*)As;

    for (int t = blockIdx.x; t < ntiles; t += gridDim.x) {
        size_t ebase = (size_t)t * 128;

        // Load A tile [128][64] -> As [128][68] (8 x LDG.128 per thread)
        __syncthreads();   // previous compute done reading As
#pragma unroll
        for (int it = 0; it < 8; ++it) {
            int i = it * 256 + tid;
            int r = i >> 4, c4 = i & 15;
            float4 v = make_float4(0.f, 0.f, 0.f, 0.f);
            if (ebase + (size_t)r < (size_t)E)
                v = ((const float4*)g_e2f)[(ebase + r) * 16 + c4];
            As4[r * 17 + c4] = v;
        }
        __syncthreads();

#pragma unroll
        for (int grp = 0; grp < 2; ++grp) {
            int noff = noff0 + grp * 64;
            float cc[2][8][4];
#pragma unroll
            for (int mt = 0; mt < 2; ++mt)
#pragma unroll
                for (int nt = 0; nt < 8; ++nt) {
                    cc[mt][nt][0] = 0.f; cc[mt][nt][1] = 0.f;
                    cc[mt][nt][2] = 0.f; cc[mt][nt][3] = 0.f;
                }

#pragma unroll
            for (int ks = 0; ks < 8; ++ks) {
                int acol = ks * 8 + tg;
                uint32_t ah[2][4], al[2][4];
#pragma unroll
                for (int mt = 0; mt < 2; ++mt) {
                    int r0 = mrow + mt * 16 + qr;
                    tf32_split(As[r0 * 68 + acol],           ah[mt][0], al[mt][0]);
                    tf32_split(As[(r0 + 8) * 68 + acol],     ah[mt][1], al[mt][1]);
                    tf32_split(As[r0 * 68 + acol + 4],       ah[mt][2], al[mt][2]);
                    tf32_split(As[(r0 + 8) * 68 + acol + 4], ah[mt][3], al[mt][3]);
                }
                const float2* brow0 = Bs + (ks * 8 + tg) * 260 + noff + qr;
                const float2* brow1 = Bs + (ks * 8 + tg + 4) * 260 + noff + qr;
#pragma unroll
                for (int nt = 0; nt < 8; ++nt) {
                    float2 b0v = brow0[nt * 8];
                    float2 b1v = brow1[nt * 8];
                    uint32_t bh0 = __float_as_uint(b0v.x), bl0 = __float_as_uint(b0v.y);
                    uint32_t bh1 = __float_as_uint(b1v.x), bl1 = __float_as_uint(b1v.y);
#pragma unroll
                    for (int mt = 0; mt < 2; ++mt) {
                        mma_tf32(cc[mt][nt], ah[mt], bh0, bh1);   // hi*hi
                        mma_tf32(cc[mt][nt], al[mt], bh0, bh1);   // lo*hi
                        mma_tf32(cc[mt][nt], ah[mt], bl0, bl1);   // hi*lo
                    }
                }
            }

            // Store C (+b3)
#pragma unroll
            for (int mt = 0; mt < 2; ++mt) {
                size_t e0 = ebase + (size_t)(mrow + mt * 16 + qr);
                size_t e1 = e0 + 8;
                bool v0 = e0 < (size_t)E, v1 = e1 < (size_t)E;
#pragma unroll
                for (int nt = 0; nt < 8; ++nt) {
                    int n0 = noff + nt * 8 + 2 * tg;
                    float bb0 = b3s[n0], bb1 = b3s[n0 + 1];
                    if (v0) *(float2*)(g_Wedge + e0 * 256 + n0) =
                                make_float2(cc[mt][nt][0] + bb0, cc[mt][nt][1] + bb1);
                    if (v1) *(float2*)(g_Wedge + e1 * 256 + n0) =
                                make_float2(cc[mt][nt][2] + bb0, cc[mt][nt][3] + bb1);
                }
            }
        }
    }
}

// ---------------------------------------------------------------------------
// h0 = [x | zeros]
// ---------------------------------------------------------------------------
__global__ void init_h_kernel(const float* __restrict__ x, int N)
{
    int idx = blockIdx.x * blockDim.x + threadIdx.x;
    if (idx >= N * 16) return;
    int n = idx >> 4, i = idx & 15;
    g_h[0][idx] = (i < 8) ? x[n * 8 + i] : 0.f;
}

// h_out = bias + h_in @ root
__global__ void node_init_kernel(int in_slot, int out_slot,
                                 const float* __restrict__ root,
                                 const float* __restrict__ bias, int N)
{
    __shared__ float rs[256];
    __shared__ float bs[16];
    int tid = threadIdx.x;
    if (tid < 256) rs[tid] = root[tid];
    if (tid < 16)  bs[tid] = bias[tid];
    __syncthreads();
    int idx = blockIdx.x * blockDim.x + tid;
    if (idx >= N * 16) return;
    int n = idx >> 4, o = idx & 15;
    const float* hr = g_h[in_slot] + n * 16;
    float acc = bs[o];
#pragma unroll
    for (int i = 0; i < 16; ++i) acc += hr[i] * rs[i * 16 + o];
    g_h[out_slot][idx] = acc;
}

// Message pass: h_out[dst] += h_in[src] @ Wedge[e]. One warp per edge.
__global__ __launch_bounds__(256)
void msg_kernel(int in_slot, int out_slot, const int* __restrict__ edge_index, int E)
{
    int lane = threadIdx.x & 31;
    int e = (blockIdx.x * 256 + threadIdx.x) >> 5;
    if (e >= E) return;
    int src = edge_index[2 * e];
    int dst = edge_index[2 * e + 1];

    const float* h_in = g_h[in_slot];
    float hv = (lane < 16) ? h_in[src * 16 + lane] : 0.f;

    const float* W = g_Wedge + (size_t)e * 256;
    int hi = lane >> 4;
    float p = 0.f;
#pragma unroll
    for (int k = 0; k < 8; ++k) {
        float w  = W[32 * k + lane];
        float hk = __shfl_sync(0xffffffffu, hv, 2 * k + hi);
        p += hk * w;
    }
    p += __shfl_xor_sync(0xffffffffu, p, 16);
    if (lane < 16) atomicAdd(&g_h[out_slot][dst * 16 + lane], p);
}

// ---------------------------------------------------------------------------
// Readout
// ---------------------------------------------------------------------------
__global__ void zero_out_kernel(float* out)
{
    if (threadIdx.x == 0 && blockIdx.x == 0) out[0] = 0.f;
}

__global__ __launch_bounds__(256)
void readout_kernel(int h_slot,
                    const float* __restrict__ Wi1, const float* __restrict__ bi1,
                    const float* __restrict__ Wi2, const float* __restrict__ bi2,
                    const float* __restrict__ Wj1, const float* __restrict__ bj1,
                    const float* __restrict__ Wj2, const float* __restrict__ bj2,
                    float* __restrict__ out, int N)
{
    __shared__ float Wi1s[4096], Wj1s[2048];
    __shared__ float bi1s[128], bj1s[128], Wi2s[128], Wj2s[128];
    __shared__ float warpsum[8];

    int tid = threadIdx.x;
    for (int i = tid; i < 4096; i += 256) Wi1s[i] = Wi1[i];
    for (int i = tid; i < 2048; i += 256) Wj1s[i] = Wj1[i];
    if (tid < 128) {
        bi1s[tid] = bi1[tid]; bj1s[tid] = bj1[tid];
        Wi2s[tid] = Wi2[tid]; Wj2s[tid] = Wj2[tid];
    }
    __syncthreads();

    int lane = tid & 31, w = tid >> 5;
    int n = blockIdx.x * 8 + w;
    float contrib = 0.f;

    if (n < N) {
        const float* h  = g_h[h_slot] + n * 16;
        const float* h0 = g_h[0] + n * 16;
        float hv  = (lane < 16) ? h[lane]  : 0.f;
        float h0v = (lane < 16) ? h0[lane] : 0.f;

        float a0 = bi1s[lane], a1 = bi1s[lane + 32], a2 = bi1s[lane + 64], a3 = bi1s[lane + 96];
#pragma unroll
        for (int c = 0; c < 32; ++c) {
            float cc = __shfl_sync(0xffffffffu, (c < 16) ? hv : h0v, c & 15);
            a0 += cc * Wi1s[c * 128 + lane];
            a1 += cc * Wi1s[c * 128 + lane + 32];
            a2 += cc * Wi1s[c * 128 + lane + 64];
            a3 += cc * Wi1s[c * 128 + lane + 96];
        }
        a0 = fmaxf(a0, 0.f); a1 = fmaxf(a1, 0.f); a2 = fmaxf(a2, 0.f); a3 = fmaxf(a3, 0.f);
        float g = a0 * Wi2s[lane] + a1 * Wi2s[lane + 32] + a2 * Wi2s[lane + 64] + a3 * Wi2s[lane + 96];

        float v0 = bj1s[lane], v1 = bj1s[lane + 32], v2 = bj1s[lane + 64], v3 = bj1s[lane + 96];
#pragma unroll
        for (int c = 0; c < 16; ++c) {
            float cc = __shfl_sync(0xffffffffu, hv, c);
            v0 += cc * Wj1s[c * 128 + lane];
            v1 += cc * Wj1s[c * 128 + lane + 32];
            v2 += cc * Wj1s[c * 128 + lane + 64];
            v3 += cc * Wj1s[c * 128 + lane + 96];
        }
        v0 = fmaxf(v0, 0.f); v1 = fmaxf(v1, 0.f); v2 = fmaxf(v2, 0.f); v3 = fmaxf(v3, 0.f);
        float vv = v0 * Wj2s[lane] + v1 * Wj2s[lane + 32] + v2 * Wj2s[lane + 64] + v3 * Wj2s[lane + 96];

#pragma unroll
        for (int s = 16; s > 0; s >>= 1) {
            g  += __shfl_xor_sync(0xffffffffu, g, s);
            vv += __shfl_xor_sync(0xffffffffu, vv, s);
        }
        if (lane == 0) {
            float gate = 1.f / (1.f + expf(-(g + bi2[0])));
            contrib = gate * (vv + bj2[0]);
        }
    }
    if (lane == 0) warpsum[w] = contrib;
    __syncthreads();
    if (tid == 0) {
        float s = 0.f;
#pragma unroll
        for (int i = 0; i < 8; ++i) s += warpsum[i];
        atomicAdd(out, s);
    }
}

// ===========================================================================
extern "C" void kernel_launch(void* const* d_in, const int* in_sizes, int n_in,
                              void* d_out, int out_size)
{
    const float* x          = (const float*)d_in[0];
    const int*   edge_index = (const int*)  d_in[1];
    const float* edge_attr  = (const float*)d_in[2];
    const float* W1  = (const float*)d_in[3];
    const float* b1  = (const float*)d_in[4];
    const float* W2  = (const float*)d_in[5];
    const float* b2  = (const float*)d_in[6];
    const float* W3  = (const float*)d_in[7];
    const float* b3  = (const float*)d_in[8];
    const float* root = (const float*)d_in[9];
    const float* bias = (const float*)d_in[10];
    const float* Wi1 = (const float*)d_in[11];
    const float* bi1 = (const float*)d_in[12];
    const float* Wi2 = (const float*)d_in[13];
    const float* bi2 = (const float*)d_in[14];
    const float* Wj1 = (const float*)d_in[15];
    const float* bj1 = (const float*)d_in[16];
    const float* Wj2 = (const float*)d_in[17];
    const float* bj2 = (const float*)d_in[18];

    int N = in_sizes[0] / 8;  if (N > NMAX) N = NMAX;
    int E = in_sizes[1] / 2;  if (E > EMAX) E = EMAX;
    float* out = (float*)d_out;

    cudaFuncSetAttribute(wedge_gemm_kernel,
                         cudaFuncAttributeMaxDynamicSharedMemorySize, G_SMEM);
    cudaFuncSetAttribute(edge_stage12_kernel,
                         cudaFuncAttributeMaxDynamicSharedMemorySize, S12_SMEM);

    int node_blocks = (N * 16 + 255) / 256;
    int edge_blocks = (E + 7) / 8;
    int s12_blocks  = (E + 255) / 256;
    int ntiles      = (E + 127) / 128;
    int gemm_grid   = ntiles < 148 ? ntiles : 148;

    // 1) Edge MLP stages 1-2 -> e2 fp32 (thread-per-edge)
    edge_stage12_kernel<<<s12_blocks, 256, S12_SMEM>>>(edge_attr, W1, b1, W2, b2, E);
    // 2) W3 tf32 limb split
    w3_split_kernel<<<64, 256>>>(W3);
    // 3) Stage-3 GEMM (persistent tf32 3-limb) -> Wedge
    wedge_gemm_kernel<<<gemm_grid, 256, G_SMEM>>>(b3, E, ntiles);

    // 4) h0
    init_h_kernel<<<node_blocks, 256>>>(x, N);

    // 5) Three propagation rounds
    int in_slot = 0;
    int out_slots[3] = {1, 2, 1};
    for (int t = 0; t < 3; ++t) {
        int o = out_slots[t];
        node_init_kernel<<<node_blocks, 256>>>(in_slot, o, root, bias, N);
        msg_kernel<<<edge_blocks, 256>>>(in_slot, o, edge_index, E);
        in_slot = o;
    }

    // 6) Gated readout -> scalar
    zero_out_kernel<<<1, 32>>>(out);
    readout_kernel<<<(N + 7) / 8, 256>>>(in_slot, Wi1, bi1, Wi2, bi2,
                                         Wj1, bj1, Wj2, bj2, out, N);
}

// round 9
// speedup vs baseline: 3.2851x; 1.0921x over previous
#include <cuda_runtime.h>
#include <cuda_bf16.h>
#include <math.h>
#include <stdint.h>

// Problem constants (fixed by the dataset)
#define NMAX 100000
#define EMAX 800000

// Scratch (device globals: allocation-free per harness rules)
__device__ float  g_Wedge[(size_t)EMAX * 256];     // 819 MB per-edge 16x16 matrices
__device__ float  g_h[3][NMAX * 16];               // slot0 = h0, 1/2 ping-pong
__device__ __nv_bfloat16 g_e2b0[(size_t)EMAX * 64]; // e2 bf16 limb hi (k-major)
__device__ __nv_bfloat16 g_e2b1[(size_t)EMAX * 64]; // e2 bf16 limb lo
__device__ __nv_bfloat16 g_Bb0[256 * 64];           // W3^T limb hi (n-major)
__device__ __nv_bfloat16 g_Bb1[256 * 64];           // W3^T limb lo

// ---------------------------------------------------------------------------
// bf16 helpers (mma.sync m16n8k16 is sm_80+, compiles for plain compute_100)
// ---------------------------------------------------------------------------
__device__ __forceinline__ void mma_bf16(float* c, const uint32_t* a,
                                         uint32_t b0, uint32_t b1) {
    asm volatile(
        "mma.sync.aligned.m16n8k16.row.col.f32.bf16.bf16.f32 "
        "{%0,%1,%2,%3}, {%4,%5,%6,%7}, {%8,%9}, {%0,%1,%2,%3};"
        : "+f"(c[0]), "+f"(c[1]), "+f"(c[2]), "+f"(c[3])
        : "r"(a[0]), "r"(a[1]), "r"(a[2]), "r"(a[3]), "r"(b0), "r"(b1));
}

__device__ __forceinline__ uint32_t pack_bf2(float v0, float v1,
                                             float& r0, float& r1) {
    __nv_bfloat16 h0 = __float2bfloat16(v0);
    __nv_bfloat16 h1 = __float2bfloat16(v1);
    r0 = v0 - __bfloat162float(h0);
    r1 = v1 - __bfloat162float(h1);
    __nv_bfloat162 t = __halves2bfloat162(h0, h1);
    return *reinterpret_cast<uint32_t*>(&t);
}
__device__ __forceinline__ uint32_t pack_bf2_only(float v0, float v1) {
    __nv_bfloat16 h0 = __float2bfloat16(v0);
    __nv_bfloat16 h1 = __float2bfloat16(v1);
    __nv_bfloat162 t = __halves2bfloat162(h0, h1);
    return *reinterpret_cast<uint32_t*>(&t);
}

// ---------------------------------------------------------------------------
// Stage 1+2 of edge MLP, THREAD-per-edge (FMA-pipe bound), emitting e2 as
// two bf16 limb planes. h1 staged per-thread in smem column (stride 256).
// Dynamic smem: h1s 65536 B + W2s 16384 B = 81920 B.
// ---------------------------------------------------------------------------
#define S12_SMEM (65536 + 16384)

__global__ __launch_bounds__(256)
void edge_stage12_kernel(const float* __restrict__ edge_attr,
                         const float* __restrict__ W1, const float* __restrict__ b1,
                         const float* __restrict__ W2, const float* __restrict__ b2,
                         int E)
{
    extern __shared__ float dsm[];
    float* h1s = dsm;            // [64][256] per-thread columns
    float* W2s = dsm + 16384;    // [64][64] k-major
    __shared__ float W1s[256], b1s[64], b2s[64];

    int tid = threadIdx.x;
    for (int i = tid; i < 4096; i += 256) W2s[i] = W2[i];
    if (tid < 256) W1s[tid] = W1[tid];
    if (tid < 64) { b1s[tid] = b1[tid]; b2s[tid] = b2[tid]; }
    __syncthreads();

    int e = blockIdx.x * 256 + tid;
    if (e >= E) return;

    // stage 1: 4 -> 64
    float4 a = ((const float4*)edge_attr)[e];
    const float4* W1s4 = (const float4*)W1s;
    const float4* b1s4 = (const float4*)b1s;
#pragma unroll
    for (int m4 = 0; m4 < 16; ++m4) {
        float4 w0 = W1s4[m4];
        float4 w1 = W1s4[16 + m4];
        float4 w2 = W1s4[32 + m4];
        float4 w3 = W1s4[48 + m4];
        float4 bb = b1s4[m4];
        float v0 = bb.x + a.x * w0.x + a.y * w1.x + a.z * w2.x + a.w * w3.x;
        float v1 = bb.y + a.x * w0.y + a.y * w1.y + a.z * w2.y + a.w * w3.y;
        float v2 = bb.z + a.x * w0.z + a.y * w1.z + a.z * w2.z + a.w * w3.z;
        float v3 = bb.w + a.x * w0.w + a.y * w1.w + a.z * w2.w + a.w * w3.w;
        h1s[(m4 * 4 + 0) * 256 + tid] = fmaxf(v0, 0.f);
        h1s[(m4 * 4 + 1) * 256 + tid] = fmaxf(v1, 0.f);
        h1s[(m4 * 4 + 2) * 256 + tid] = fmaxf(v2, 0.f);
        h1s[(m4 * 4 + 3) * 256 + tid] = fmaxf(v3, 0.f);
    }

    // stage 2: 64 -> 64, 4 chunks of 16 outputs; emit bf16 limb pairs
    const float4* W2s4 = (const float4*)W2s;
    uint4* out0 = (uint4*)(g_e2b0 + (size_t)e * 64);
    uint4* out1 = (uint4*)(g_e2b1 + (size_t)e * 64);
#pragma unroll
    for (int c = 0; c < 4; ++c) {
        float acc[16];
#pragma unroll
        for (int j = 0; j < 16; ++j) acc[j] = b2s[c * 16 + j];
#pragma unroll 8
        for (int k = 0; k < 64; ++k) {
            float hk = h1s[k * 256 + tid];
            float4 w0 = W2s4[k * 16 + c * 4 + 0];
            float4 w1 = W2s4[k * 16 + c * 4 + 1];
            float4 w2 = W2s4[k * 16 + c * 4 + 2];
            float4 w3 = W2s4[k * 16 + c * 4 + 3];
            acc[0]  += hk * w0.x;  acc[1]  += hk * w0.y;
            acc[2]  += hk * w0.z;  acc[3]  += hk * w0.w;
            acc[4]  += hk * w1.x;  acc[5]  += hk * w1.y;
            acc[6]  += hk * w1.z;  acc[7]  += hk * w1.w;
            acc[8]  += hk * w2.x;  acc[9]  += hk * w2.y;
            acc[10] += hk * w2.z;  acc[11] += hk * w2.w;
            acc[12] += hk * w3.x;  acc[13] += hk * w3.y;
            acc[14] += hk * w3.z;  acc[15] += hk * w3.w;
        }
        uint32_t w0p[8], w1p[8];
#pragma unroll
        for (int j = 0; j < 8; ++j) {
            float v0 = fmaxf(acc[2 * j],     0.f);
            float v1 = fmaxf(acc[2 * j + 1], 0.f);
            float r0, r1;
            w0p[j] = pack_bf2(v0, v1, r0, r1);
            w1p[j] = pack_bf2_only(r0, r1);
        }
        out0[c * 2 + 0] = make_uint4(w0p[0], w0p[1], w0p[2], w0p[3]);
        out0[c * 2 + 1] = make_uint4(w0p[4], w0p[5], w0p[6], w0p[7]);
        out1[c * 2 + 0] = make_uint4(w1p[0], w1p[1], w1p[2], w1p[3]);
        out1[c * 2 + 1] = make_uint4(w1p[4], w1p[5], w1p[6], w1p[7]);
    }
}

// W3 [64,256] fp32 -> n-major bf16 limb planes
__global__ void w3_split_kernel(const float* __restrict__ W3)
{
    int idx = blockIdx.x * blockDim.x + threadIdx.x;
    if (idx >= 64 * 256) return;
    int k = idx >> 8, n = idx & 255;
    float v = W3[idx];
    __nv_bfloat16 h = __float2bfloat16(v);
    float r = v - __bfloat162float(h);
    g_Bb0[n * 64 + k] = h;
    g_Bb1[n * 64 + k] = __float2bfloat16(r);
}

// ---------------------------------------------------------------------------
// Stage 3 via mma.sync bf16 m16n8k16, 2-limb x 3 products: Wedge = e2@W3 + b3
// PERSISTENT: grid<=148, B limbs loaded into smem ONCE per SM.
// Warp grid 4m x 2n: warp = m32 x n128 (2 m16-tiles, n in 2 groups of 64).
// Row stride 72 bf16 (36 words): fragment banks = 4*qr+tg (conflict-free).
// ---------------------------------------------------------------------------
#define GB_BS0  0
#define GB_BS1  36864
#define GB_AS0  73728
#define GB_AS1  92160
#define GB_B3   110592
#define GB_SMEM 111616

__global__ __launch_bounds__(256, 1)
void wedge_gemm_kernel(const float* __restrict__ b3, int E, int ntiles)
{
    extern __shared__ char smem[];
    uint32_t* Bs0 = (uint32_t*)(smem + GB_BS0);   // [256][36] words
    uint32_t* Bs1 = (uint32_t*)(smem + GB_BS1);
    uint32_t* As0 = (uint32_t*)(smem + GB_AS0);   // [128][36] words
    uint32_t* As1 = (uint32_t*)(smem + GB_AS1);
    float*    b3s = (float*)(smem + GB_B3);

    int tid = threadIdx.x;
    // Load B limbs + b3 ONCE (persistent kernel); conflict-free fill
    for (int i = tid; i < 256 * 32; i += 256) {
        int r = i >> 5, w = i & 31;
        Bs0[r * 36 + w] = ((const uint32_t*)g_Bb0)[r * 32 + w];
        Bs1[r * 36 + w] = ((const uint32_t*)g_Bb1)[r * 32 + w];
    }
    if (tid < 256) b3s[tid] = b3[tid];

    int lane = tid & 31, wid = tid >> 5;
    int qr = lane >> 2, tg = lane & 3;
    int mrow  = (wid & 3) * 32;           // warp's 32-row block
    int noff0 = (wid >> 2) * 128;         // warp's 128-col block

    for (int t = blockIdx.x; t < ntiles; t += gridDim.x) {
        size_t ebase = (size_t)t * 128;

        __syncthreads();   // previous compute done reading As
        for (int i = tid; i < 128 * 32; i += 256) {
            int r = i >> 5, w = i & 31;
            uint32_t v0 = 0u, v1 = 0u;
            if (ebase + (size_t)r < (size_t)E) {
                v0 = ((const uint32_t*)g_e2b0)[(ebase + r) * 32 + w];
                v1 = ((const uint32_t*)g_e2b1)[(ebase + r) * 32 + w];
            }
            As0[r * 36 + w] = v0;
            As1[r * 36 + w] = v1;
        }
        __syncthreads();

#pragma unroll
        for (int grp = 0; grp < 2; ++grp) {
            int noff = noff0 + grp * 64;
            float cc[2][8][4];
#pragma unroll
            for (int mt = 0; mt < 2; ++mt)
#pragma unroll
                for (int nt = 0; nt < 8; ++nt) {
                    cc[mt][nt][0] = 0.f; cc[mt][nt][1] = 0.f;
                    cc[mt][nt][2] = 0.f; cc[mt][nt][3] = 0.f;
                }

#pragma unroll
            for (int ks = 0; ks < 4; ++ks) {       // K=64 in 4 k16 steps
                int kofs = ks * 8 + tg;
                uint32_t a0[2][4], a1[2][4];
#pragma unroll
                for (int mt = 0; mt < 2; ++mt) {
                    int r0 = mrow + mt * 16 + qr;
                    a0[mt][0] = As0[r0 * 36 + kofs];
                    a0[mt][1] = As0[(r0 + 8) * 36 + kofs];
                    a0[mt][2] = As0[r0 * 36 + kofs + 4];
                    a0[mt][3] = As0[(r0 + 8) * 36 + kofs + 4];
                    a1[mt][0] = As1[r0 * 36 + kofs];
                    a1[mt][1] = As1[(r0 + 8) * 36 + kofs];
                    a1[mt][2] = As1[r0 * 36 + kofs + 4];
                    a1[mt][3] = As1[(r0 + 8) * 36 + kofs + 4];
                }
#pragma unroll
                for (int nt = 0; nt < 8; ++nt) {
                    int n = noff + nt * 8 + qr;
                    uint32_t b00 = Bs0[n * 36 + kofs];
                    uint32_t b01 = Bs0[n * 36 + kofs + 4];
                    uint32_t b10 = Bs1[n * 36 + kofs];
                    uint32_t b11 = Bs1[n * 36 + kofs + 4];
#pragma unroll
                    for (int mt = 0; mt < 2; ++mt) {
                        mma_bf16(cc[mt][nt], a0[mt], b00, b01);  // hi*hi
                        mma_bf16(cc[mt][nt], a1[mt], b00, b01);  // lo*hi
                        mma_bf16(cc[mt][nt], a0[mt], b10, b11);  // hi*lo
                    }
                }
            }

            // Store C (+b3)
#pragma unroll
            for (int mt = 0; mt < 2; ++mt) {
                size_t e0 = ebase + (size_t)(mrow + mt * 16 + qr);
                size_t e1 = e0 + 8;
                bool v0 = e0 < (size_t)E, v1 = e1 < (size_t)E;
#pragma unroll
                for (int nt = 0; nt < 8; ++nt) {
                    int n0 = noff + nt * 8 + 2 * tg;
                    float bb0 = b3s[n0], bb1 = b3s[n0 + 1];
                    if (v0) *(float2*)(g_Wedge + e0 * 256 + n0) =
                                make_float2(cc[mt][nt][0] + bb0, cc[mt][nt][1] + bb1);
                    if (v1) *(float2*)(g_Wedge + e1 * 256 + n0) =
                                make_float2(cc[mt][nt][2] + bb0, cc[mt][nt][3] + bb1);
                }
            }
        }
    }
}

// ---------------------------------------------------------------------------
// h0 = [x | zeros]
// ---------------------------------------------------------------------------
__global__ void init_h_kernel(const float* __restrict__ x, int N)
{
    int idx = blockIdx.x * blockDim.x + threadIdx.x;
    if (idx >= N * 16) return;
    int n = idx >> 4, i = idx & 15;
    g_h[0][idx] = (i < 8) ? x[n * 8 + i] : 0.f;
}

// h_out = bias + h_in @ root
__global__ void node_init_kernel(int in_slot, int out_slot,
                                 const float* __restrict__ root,
                                 const float* __restrict__ bias, int N)
{
    __shared__ float rs[256];
    __shared__ float bs[16];
    int tid = threadIdx.x;
    if (tid < 256) rs[tid] = root[tid];
    if (tid < 16)  bs[tid] = bias[tid];
    __syncthreads();
    int idx = blockIdx.x * blockDim.x + tid;
    if (idx >= N * 16) return;
    int n = idx >> 4, o = idx & 15;
    const float* hr = g_h[in_slot] + n * 16;
    float acc = bs[o];
#pragma unroll
    for (int i = 0; i < 16; ++i) acc += hr[i] * rs[i * 16 + o];
    g_h[out_slot][idx] = acc;
}

// Message pass: h_out[dst] += h_in[src] @ Wedge[e]. One warp per edge.
__global__ __launch_bounds__(256)
void msg_kernel(int in_slot, int out_slot, const int* __restrict__ edge_index, int E)
{
    int lane = threadIdx.x & 31;
    int e = (blockIdx.x * 256 + threadIdx.x) >> 5;
    if (e >= E) return;
    int src = edge_index[2 * e];
    int dst = edge_index[2 * e + 1];

    const float* h_in = g_h[in_slot];
    float hv = (lane < 16) ? h_in[src * 16 + lane] : 0.f;

    const float* W = g_Wedge + (size_t)e * 256;
    int hi = lane >> 4;
    float p = 0.f;
#pragma unroll
    for (int k = 0; k < 8; ++k) {
        float w  = W[32 * k + lane];
        float hk = __shfl_sync(0xffffffffu, hv, 2 * k + hi);
        p += hk * w;
    }
    p += __shfl_xor_sync(0xffffffffu, p, 16);
    if (lane < 16) atomicAdd(&g_h[out_slot][dst * 16 + lane], p);
}

// ---------------------------------------------------------------------------
// Readout
// ---------------------------------------------------------------------------
__global__ void zero_out_kernel(float* out)
{
    if (threadIdx.x == 0 && blockIdx.x == 0) out[0] = 0.f;
}

__global__ __launch_bounds__(256)
void readout_kernel(int h_slot,
                    const float* __restrict__ Wi1, const float* __restrict__ bi1,
                    const float* __restrict__ Wi2, const float* __restrict__ bi2,
                    const float* __restrict__ Wj1, const float* __restrict__ bj1,
                    const float* __restrict__ Wj2, const float* __restrict__ bj2,
                    float* __restrict__ out, int N)
{
    __shared__ float Wi1s[4096], Wj1s[2048];
    __shared__ float bi1s[128], bj1s[128], Wi2s[128], Wj2s[128];
    __shared__ float warpsum[8];

    int tid = threadIdx.x;
    for (int i = tid; i < 4096; i += 256) Wi1s[i] = Wi1[i];
    for (int i = tid; i < 2048; i += 256) Wj1s[i] = Wj1[i];
    if (tid < 128) {
        bi1s[tid] = bi1[tid]; bj1s[tid] = bj1[tid];
        Wi2s[tid] = Wi2[tid]; Wj2s[tid] = Wj2[tid];
    }
    __syncthreads();

    int lane = tid & 31, w = tid >> 5;
    int n = blockIdx.x * 8 + w;
    float contrib = 0.f;

    if (n < N) {
        const float* h  = g_h[h_slot] + n * 16;
        const float* h0 = g_h[0] + n * 16;
        float hv  = (lane < 16) ? h[lane]  : 0.f;
        float h0v = (lane < 16) ? h0[lane] : 0.f;

        float a0 = bi1s[lane], a1 = bi1s[lane + 32], a2 = bi1s[lane + 64], a3 = bi1s[lane + 96];
#pragma unroll
        for (int c = 0; c < 32; ++c) {
            float cc = __shfl_sync(0xffffffffu, (c < 16) ? hv : h0v, c & 15);
            a0 += cc * Wi1s[c * 128 + lane];
            a1 += cc * Wi1s[c * 128 + lane + 32];
            a2 += cc * Wi1s[c * 128 + lane + 64];
            a3 += cc * Wi1s[c * 128 + lane + 96];
        }
        a0 = fmaxf(a0, 0.f); a1 = fmaxf(a1, 0.f); a2 = fmaxf(a2, 0.f); a3 = fmaxf(a3, 0.f);
        float g = a0 * Wi2s[lane] + a1 * Wi2s[lane + 32] + a2 * Wi2s[lane + 64] + a3 * Wi2s[lane + 96];

        float v0 = bj1s[lane], v1 = bj1s[lane + 32], v2 = bj1s[lane + 64], v3 = bj1s[lane + 96];
#pragma unroll
        for (int c = 0; c < 16; ++c) {
            float cc = __shfl_sync(0xffffffffu, hv, c);
            v0 += cc * Wj1s[c * 128 + lane];
            v1 += cc * Wj1s[c * 128 + lane + 32];
            v2 += cc * Wj1s[c * 128 + lane + 64];
            v3 += cc * Wj1s[c * 128 + lane + 96];
        }
        v0 = fmaxf(v0, 0.f); v1 = fmaxf(v1, 0.f); v2 = fmaxf(v2, 0.f); v3 = fmaxf(v3, 0.f);
        float vv = v0 * Wj2s[lane] + v1 * Wj2s[lane + 32] + v2 * Wj2s[lane + 64] + v3 * Wj2s[lane + 96];

#pragma unroll
        for (int s = 16; s > 0; s >>= 1) {
            g  += __shfl_xor_sync(0xffffffffu, g, s);
            vv += __shfl_xor_sync(0xffffffffu, vv, s);
        }
        if (lane == 0) {
            float gate = 1.f / (1.f + expf(-(g + bi2[0])));
            contrib = gate * (vv + bj2[0]);
        }
    }
    if (lane == 0) warpsum[w] = contrib;
    __syncthreads();
    if (tid == 0) {
        float s = 0.f;
#pragma unroll
        for (int i = 0; i < 8; ++i) s += warpsum[i];
        atomicAdd(out, s);
    }
}

// ===========================================================================
extern "C" void kernel_launch(void* const* d_in, const int* in_sizes, int n_in,
                              void* d_out, int out_size)
{
    const float* x          = (const float*)d_in[0];
    const int*   edge_index = (const int*)  d_in[1];
    const float* edge_attr  = (const float*)d_in[2];
    const float* W1  = (const float*)d_in[3];
    const float* b1  = (const float*)d_in[4];
    const float* W2  = (const float*)d_in[5];
    const float* b2  = (const float*)d_in[6];
    const float* W3  = (const float*)d_in[7];
    const float* b3  = (const float*)d_in[8];
    const float* root = (const float*)d_in[9];
    const float* bias = (const float*)d_in[10];
    const float* Wi1 = (const float*)d_in[11];
    const float* bi1 = (const float*)d_in[12];
    const float* Wi2 = (const float*)d_in[13];
    const float* bi2 = (const float*)d_in[14];
    const float* Wj1 = (const float*)d_in[15];
    const float* bj1 = (const float*)d_in[16];
    const float* Wj2 = (const float*)d_in[17];
    const float* bj2 = (const float*)d_in[18];

    int N = in_sizes[0] / 8;  if (N > NMAX) N = NMAX;
    int E = in_sizes[1] / 2;  if (E > EMAX) E = EMAX;
    float* out = (float*)d_out;

    cudaFuncSetAttribute(wedge_gemm_kernel,
                         cudaFuncAttributeMaxDynamicSharedMemorySize, GB_SMEM);
    cudaFuncSetAttribute(edge_stage12_kernel,
                         cudaFuncAttributeMaxDynamicSharedMemorySize, S12_SMEM);

    int node_blocks = (N * 16 + 255) / 256;
    int edge_blocks = (E + 7) / 8;
    int s12_blocks  = (E + 255) / 256;
    int ntiles      = (E + 127) / 128;
    int gemm_grid   = ntiles < 148 ? ntiles : 148;

    // 1) Edge MLP stages 1-2 -> e2 bf16 limb planes (thread-per-edge)
    edge_stage12_kernel<<<s12_blocks, 256, S12_SMEM>>>(edge_attr, W1, b1, W2, b2, E);
    // 2) W3 bf16 limb split (n-major)
    w3_split_kernel<<<64, 256>>>(W3);
    // 3) Stage-3 GEMM (persistent bf16 2-limb, 3 products) -> Wedge
    wedge_gemm_kernel<<<gemm_grid, 256, GB_SMEM>>>(b3, E, ntiles);

    // 4) h0
    init_h_kernel<<<node_blocks, 256>>>(x, N);

    // 5) Three propagation rounds
    int in_slot = 0;
    int out_slots[3] = {1, 2, 1};
    for (int t = 0; t < 3; ++t) {
        int o = out_slots[t];
        node_init_kernel<<<node_blocks, 256>>>(in_slot, o, root, bias, N);
        msg_kernel<<<edge_blocks, 256>>>(in_slot, o, edge_index, E);
        in_slot = o;
    }

    // 6) Gated readout -> scalar
    zero_out_kernel<<<1, 32>>>(out);
    readout_kernel<<<(N + 7) / 8, 256>>>(in_slot, Wi1, bi1, Wi2, bi2,
                                         Wj1, bj1, Wj2, bj2, out, N);
}

// round 10
// speedup vs baseline: 4.6399x; 1.4124x over previous
#include <cuda_runtime.h>
#include <cuda_bf16.h>
#include <math.h>
#include <stdint.h>

// Problem constants (fixed by the dataset)
#define NMAX 100000
#define EMAX 800000

// Scratch (device globals: allocation-free per harness rules)
__device__ float  g_Wedge[(size_t)EMAX * 256];      // 819 MB per-edge 16x16 matrices
__device__ float  g_h[3][NMAX * 16];                // slot0 = h0, 1/2 ping-pong
__device__ __nv_bfloat16 g_W3b0[256 * 64];          // W3^T limb hi (n-major)
__device__ __nv_bfloat16 g_W3b1[256 * 64];          // W3^T limb lo
__device__ __nv_bfloat16 g_W2b0[64 * 64];           // W2^T limb hi (n-major)
__device__ __nv_bfloat16 g_W2b1[64 * 64];           // W2^T limb lo

// ---------------------------------------------------------------------------
// bf16 helpers (mma.sync m16n8k16 is sm_80+, compiles for plain compute_100)
// ---------------------------------------------------------------------------
__device__ __forceinline__ void mma_bf16(float* c, const uint32_t* a,
                                         uint32_t b0, uint32_t b1) {
    asm volatile(
        "mma.sync.aligned.m16n8k16.row.col.f32.bf16.bf16.f32 "
        "{%0,%1,%2,%3}, {%4,%5,%6,%7}, {%8,%9}, {%0,%1,%2,%3};"
        : "+f"(c[0]), "+f"(c[1]), "+f"(c[2]), "+f"(c[3])
        : "r"(a[0]), "r"(a[1]), "r"(a[2]), "r"(a[3]), "r"(b0), "r"(b1));
}

__device__ __forceinline__ uint32_t pack_bf2(float v0, float v1,
                                             float& r0, float& r1) {
    __nv_bfloat16 h0 = __float2bfloat16(v0);
    __nv_bfloat16 h1 = __float2bfloat16(v1);
    r0 = v0 - __bfloat162float(h0);
    r1 = v1 - __bfloat162float(h1);
    __nv_bfloat162 t = __halves2bfloat162(h0, h1);
    return *reinterpret_cast<uint32_t*>(&t);
}
__device__ __forceinline__ uint32_t pack_bf2_only(float v0, float v1) {
    __nv_bfloat16 h0 = __float2bfloat16(v0);
    __nv_bfloat16 h1 = __float2bfloat16(v1);
    __nv_bfloat162 t = __halves2bfloat162(h0, h1);
    return *reinterpret_cast<uint32_t*>(&t);
}

// Weight splits: W [64, Nout] fp32 row-major -> n-major bf16 limb planes
__global__ void w3_split_kernel(const float* __restrict__ W3)
{
    int idx = blockIdx.x * blockDim.x + threadIdx.x;
    if (idx >= 64 * 256) return;
    int k = idx >> 8, n = idx & 255;
    float v = W3[idx];
    __nv_bfloat16 h = __float2bfloat16(v);
    g_W3b0[n * 64 + k] = h;
    g_W3b1[n * 64 + k] = __float2bfloat16(v - __bfloat162float(h));
}
__global__ void w2_split_kernel(const float* __restrict__ W2)
{
    int idx = blockIdx.x * blockDim.x + threadIdx.x;
    if (idx >= 64 * 64) return;
    int k = idx >> 6, n = idx & 63;
    float v = W2[idx];
    __nv_bfloat16 h = __float2bfloat16(v);
    g_W2b0[n * 64 + k] = h;
    g_W2b1[n * 64 + k] = __float2bfloat16(v - __bfloat162float(h));
}

// ---------------------------------------------------------------------------
// FUSED edge pipeline: per 256-edge tile
//   stage1 (scalar): e1 = relu(ea@W1+b1) -> warp-private smem bf16 limbs
//   MMA1:  e2 = relu(e1@W2+b2)           -> register fragments (bf16 2-limb)
//   MMA2:  Wedge = e2@W3+b3              -> gmem (bf16 2-limb, 3 products)
// Persistent, grid<=148. Warp w owns rows w*32..w*32+31; only __syncwarp in loop.
// Row stride 36 words: fragment banks 4*qr+tg, conflict-free.
// ---------------------------------------------------------------------------
#define FZ_E1_0   0
#define FZ_E1_1   36864
#define FZ_W2_0   73728
#define FZ_W2_1   82944
#define FZ_W3_0   92160
#define FZ_W3_1   129024
#define FZ_SMEM   165888

__global__ __launch_bounds__(256, 1)
void fused_edge_kernel(const float* __restrict__ edge_attr,
                       const float* __restrict__ W1, const float* __restrict__ b1,
                       const float* __restrict__ b2, const float* __restrict__ b3,
                       int E, int ntiles)
{
    extern __shared__ char smem[];
    uint32_t* E1_0 = (uint32_t*)(smem + FZ_E1_0);   // [256][36] words
    uint32_t* E1_1 = (uint32_t*)(smem + FZ_E1_1);
    uint32_t* W2s0 = (uint32_t*)(smem + FZ_W2_0);   // [64][36]
    uint32_t* W2s1 = (uint32_t*)(smem + FZ_W2_1);
    uint32_t* W3s0 = (uint32_t*)(smem + FZ_W3_0);   // [256][36]
    uint32_t* W3s1 = (uint32_t*)(smem + FZ_W3_1);
    __shared__ float W1s[256], b1s[64], b2s[64], b3s[256];

    int tid = threadIdx.x;
    // One-time loads (persistent kernel)
    for (int i = tid; i < 64 * 32; i += 256) {
        int r = i >> 5, w = i & 31;
        W2s0[r * 36 + w] = ((const uint32_t*)g_W2b0)[r * 32 + w];
        W2s1[r * 36 + w] = ((const uint32_t*)g_W2b1)[r * 32 + w];
    }
    for (int i = tid; i < 256 * 32; i += 256) {
        int r = i >> 5, w = i & 31;
        W3s0[r * 36 + w] = ((const uint32_t*)g_W3b0)[r * 32 + w];
        W3s1[r * 36 + w] = ((const uint32_t*)g_W3b1)[r * 32 + w];
    }
    if (tid < 256) { W1s[tid] = W1[tid]; b3s[tid] = b3[tid]; }
    if (tid < 64)  { b1s[tid] = b1[tid]; b2s[tid] = b2[tid]; }
    __syncthreads();

    int lane = tid & 31, wid = tid >> 5;
    int qr = lane >> 2, tg = lane & 3;
    int mrow = wid * 32;                    // warp's 32-row block
    const float4* W1s4 = (const float4*)W1s;
    const float4* b1s4 = (const float4*)b1s;

    for (int t = blockIdx.x; t < ntiles; t += gridDim.x) {
        size_t ebase = (size_t)t * 256;

        // ---- stage 1: thread tid -> edge row tid; warp-private rows ----
        {
            size_t e = ebase + (size_t)tid;
            float4 a = make_float4(0.f, 0.f, 0.f, 0.f);
            float vm = 0.f;
            if (e < (size_t)E) { a = ((const float4*)edge_attr)[e]; vm = 1.f; }
#pragma unroll
            for (int m4 = 0; m4 < 16; ++m4) {
                float4 w0 = W1s4[m4];
                float4 w1 = W1s4[16 + m4];
                float4 w2 = W1s4[32 + m4];
                float4 w3 = W1s4[48 + m4];
                float4 bb = b1s4[m4];
                float v0 = vm * fmaxf(bb.x + a.x*w0.x + a.y*w1.x + a.z*w2.x + a.w*w3.x, 0.f);
                float v1 = vm * fmaxf(bb.y + a.x*w0.y + a.y*w1.y + a.z*w2.y + a.w*w3.y, 0.f);
                float v2 = vm * fmaxf(bb.z + a.x*w0.z + a.y*w1.z + a.z*w2.z + a.w*w3.z, 0.f);
                float v3 = vm * fmaxf(bb.w + a.x*w0.w + a.y*w1.w + a.z*w2.w + a.w*w3.w, 0.f);
                float r0, r1, r2, r3;
                uint32_t h0 = pack_bf2(v0, v1, r0, r1);
                uint32_t h1 = pack_bf2(v2, v3, r2, r3);
                E1_0[tid * 36 + 2 * m4]     = h0;
                E1_0[tid * 36 + 2 * m4 + 1] = h1;
                E1_1[tid * 36 + 2 * m4]     = pack_bf2_only(r0, r1);
                E1_1[tid * 36 + 2 * m4 + 1] = pack_bf2_only(r2, r3);
            }
        }
        __syncwarp();

        // ---- MMA1: e2 = relu(e1 @ W2 + b2), accum in registers ----
        float cc1[2][8][4];
#pragma unroll
        for (int mt = 0; mt < 2; ++mt)
#pragma unroll
            for (int nt = 0; nt < 8; ++nt) {
                cc1[mt][nt][0] = 0.f; cc1[mt][nt][1] = 0.f;
                cc1[mt][nt][2] = 0.f; cc1[mt][nt][3] = 0.f;
            }
#pragma unroll
        for (int ks = 0; ks < 4; ++ks) {
            int kofs = ks * 8 + tg;
            uint32_t a0[2][4], a1[2][4];
#pragma unroll
            for (int mt = 0; mt < 2; ++mt) {
                int r0 = mrow + mt * 16 + qr;
                a0[mt][0] = E1_0[r0 * 36 + kofs];
                a0[mt][1] = E1_0[(r0 + 8) * 36 + kofs];
                a0[mt][2] = E1_0[r0 * 36 + kofs + 4];
                a0[mt][3] = E1_0[(r0 + 8) * 36 + kofs + 4];
                a1[mt][0] = E1_1[r0 * 36 + kofs];
                a1[mt][1] = E1_1[(r0 + 8) * 36 + kofs];
                a1[mt][2] = E1_1[r0 * 36 + kofs + 4];
                a1[mt][3] = E1_1[(r0 + 8) * 36 + kofs + 4];
            }
#pragma unroll
            for (int nt = 0; nt < 8; ++nt) {
                int n = nt * 8 + qr;
                uint32_t b00 = W2s0[n * 36 + kofs];
                uint32_t b01 = W2s0[n * 36 + kofs + 4];
                uint32_t b10 = W2s1[n * 36 + kofs];
                uint32_t b11 = W2s1[n * 36 + kofs + 4];
#pragma unroll
                for (int mt = 0; mt < 2; ++mt) {
                    mma_bf16(cc1[mt][nt], a0[mt], b00, b01);
                    mma_bf16(cc1[mt][nt], a1[mt], b00, b01);
                    mma_bf16(cc1[mt][nt], a0[mt], b10, b11);
                }
            }
        }

        // ---- relu(+b2) and repack C1 fragments as A2 fragments (in regs) ----
        uint32_t a2h[2][4][4], a2l[2][4][4];
#pragma unroll
        for (int mt = 0; mt < 2; ++mt)
#pragma unroll
            for (int nt = 0; nt < 8; ++nt) {
                float bb0 = b2s[nt * 8 + 2 * tg];
                float bb1 = b2s[nt * 8 + 2 * tg + 1];
                float d0 = fmaxf(cc1[mt][nt][0] + bb0, 0.f);
                float d1 = fmaxf(cc1[mt][nt][1] + bb1, 0.f);
                float d2 = fmaxf(cc1[mt][nt][2] + bb0, 0.f);
                float d3 = fmaxf(cc1[mt][nt][3] + bb1, 0.f);
                int ks2 = nt >> 1, q = (nt & 1) * 2;
                float r0, r1, r2, r3;
                a2h[mt][ks2][q]     = pack_bf2(d0, d1, r0, r1);
                a2h[mt][ks2][q + 1] = pack_bf2(d2, d3, r2, r3);
                a2l[mt][ks2][q]     = pack_bf2_only(r0, r1);
                a2l[mt][ks2][q + 1] = pack_bf2_only(r2, r3);
            }

        // ---- MMA2: Wedge = e2 @ W3 + b3, n in 4 groups of 64 ----
#pragma unroll
        for (int grp = 0; grp < 4; ++grp) {
            int noff = grp * 64;
            float cc2[2][8][4];
#pragma unroll
            for (int mt = 0; mt < 2; ++mt)
#pragma unroll
                for (int nt = 0; nt < 8; ++nt) {
                    cc2[mt][nt][0] = 0.f; cc2[mt][nt][1] = 0.f;
                    cc2[mt][nt][2] = 0.f; cc2[mt][nt][3] = 0.f;
                }
#pragma unroll
            for (int ks = 0; ks < 4; ++ks) {
                int kofs = ks * 8 + tg;
#pragma unroll
                for (int nt = 0; nt < 8; ++nt) {
                    int n = noff + nt * 8 + qr;
                    uint32_t b00 = W3s0[n * 36 + kofs];
                    uint32_t b01 = W3s0[n * 36 + kofs + 4];
                    uint32_t b10 = W3s1[n * 36 + kofs];
                    uint32_t b11 = W3s1[n * 36 + kofs + 4];
#pragma unroll
                    for (int mt = 0; mt < 2; ++mt) {
                        mma_bf16(cc2[mt][nt], a2h[mt][ks], b00, b01);
                        mma_bf16(cc2[mt][nt], a2l[mt][ks], b00, b01);
                        mma_bf16(cc2[mt][nt], a2h[mt][ks], b10, b11);
                    }
                }
            }
            // Store (+b3)
#pragma unroll
            for (int mt = 0; mt < 2; ++mt) {
                size_t e0 = ebase + (size_t)(mrow + mt * 16 + qr);
                size_t e1 = e0 + 8;
                bool v0 = e0 < (size_t)E, v1 = e1 < (size_t)E;
#pragma unroll
                for (int nt = 0; nt < 8; ++nt) {
                    int n0 = noff + nt * 8 + 2 * tg;
                    float bb0 = b3s[n0], bb1 = b3s[n0 + 1];
                    if (v0) *(float2*)(g_Wedge + e0 * 256 + n0) =
                                make_float2(cc2[mt][nt][0] + bb0, cc2[mt][nt][1] + bb1);
                    if (v1) *(float2*)(g_Wedge + e1 * 256 + n0) =
                                make_float2(cc2[mt][nt][2] + bb0, cc2[mt][nt][3] + bb1);
                }
            }
        }
    }
}

// ---------------------------------------------------------------------------
// h0 = [x | zeros]
// ---------------------------------------------------------------------------
__global__ void init_h_kernel(const float* __restrict__ x, int N)
{
    int idx = blockIdx.x * blockDim.x + threadIdx.x;
    if (idx >= N * 16) return;
    int n = idx >> 4, i = idx & 15;
    g_h[0][idx] = (i < 8) ? x[n * 8 + i] : 0.f;
}

// h_out = bias + h_in @ root
__global__ void node_init_kernel(int in_slot, int out_slot,
                                 const float* __restrict__ root,
                                 const float* __restrict__ bias, int N)
{
    __shared__ float rs[256];
    __shared__ float bs[16];
    int tid = threadIdx.x;
    if (tid < 256) rs[tid] = root[tid];
    if (tid < 16)  bs[tid] = bias[tid];
    __syncthreads();
    int idx = blockIdx.x * blockDim.x + tid;
    if (idx >= N * 16) return;
    int n = idx >> 4, o = idx & 15;
    const float* hr = g_h[in_slot] + n * 16;
    float acc = bs[o];
#pragma unroll
    for (int i = 0; i < 16; ++i) acc += hr[i] * rs[i * 16 + o];
    g_h[out_slot][idx] = acc;
}

// Message pass: h_out[dst] += h_in[src] @ Wedge[e]. One warp per edge.
__global__ __launch_bounds__(256)
void msg_kernel(int in_slot, int out_slot, const int* __restrict__ edge_index, int E)
{
    int lane = threadIdx.x & 31;
    int e = (blockIdx.x * 256 + threadIdx.x) >> 5;
    if (e >= E) return;
    int src = edge_index[2 * e];
    int dst = edge_index[2 * e + 1];

    const float* h_in = g_h[in_slot];
    float hv = (lane < 16) ? h_in[src * 16 + lane] : 0.f;

    const float* W = g_Wedge + (size_t)e * 256;
    int hi = lane >> 4;
    float p = 0.f;
#pragma unroll
    for (int k = 0; k < 8; ++k) {
        float w  = W[32 * k + lane];
        float hk = __shfl_sync(0xffffffffu, hv, 2 * k + hi);
        p += hk * w;
    }
    p += __shfl_xor_sync(0xffffffffu, p, 16);
    if (lane < 16) atomicAdd(&g_h[out_slot][dst * 16 + lane], p);
}

// ---------------------------------------------------------------------------
// Readout
// ---------------------------------------------------------------------------
__global__ void zero_out_kernel(float* out)
{
    if (threadIdx.x == 0 && blockIdx.x == 0) out[0] = 0.f;
}

__global__ __launch_bounds__(256)
void readout_kernel(int h_slot,
                    const float* __restrict__ Wi1, const float* __restrict__ bi1,
                    const float* __restrict__ Wi2, const float* __restrict__ bi2,
                    const float* __restrict__ Wj1, const float* __restrict__ bj1,
                    const float* __restrict__ Wj2, const float* __restrict__ bj2,
                    float* __restrict__ out, int N)
{
    __shared__ float Wi1s[4096], Wj1s[2048];
    __shared__ float bi1s[128], bj1s[128], Wi2s[128], Wj2s[128];
    __shared__ float warpsum[8];

    int tid = threadIdx.x;
    for (int i = tid; i < 4096; i += 256) Wi1s[i] = Wi1[i];
    for (int i = tid; i < 2048; i += 256) Wj1s[i] = Wj1[i];
    if (tid < 128) {
        bi1s[tid] = bi1[tid]; bj1s[tid] = bj1[tid];
        Wi2s[tid] = Wi2[tid]; Wj2s[tid] = Wj2[tid];
    }
    __syncthreads();

    int lane = tid & 31, w = tid >> 5;
    int n = blockIdx.x * 8 + w;
    float contrib = 0.f;

    if (n < N) {
        const float* h  = g_h[h_slot] + n * 16;
        const float* h0 = g_h[0] + n * 16;
        float hv  = (lane < 16) ? h[lane]  : 0.f;
        float h0v = (lane < 16) ? h0[lane] : 0.f;

        float a0 = bi1s[lane], a1 = bi1s[lane + 32], a2 = bi1s[lane + 64], a3 = bi1s[lane + 96];
#pragma unroll
        for (int c = 0; c < 32; ++c) {
            float cc = __shfl_sync(0xffffffffu, (c < 16) ? hv : h0v, c & 15);
            a0 += cc * Wi1s[c * 128 + lane];
            a1 += cc * Wi1s[c * 128 + lane + 32];
            a2 += cc * Wi1s[c * 128 + lane + 64];
            a3 += cc * Wi1s[c * 128 + lane + 96];
        }
        a0 = fmaxf(a0, 0.f); a1 = fmaxf(a1, 0.f); a2 = fmaxf(a2, 0.f); a3 = fmaxf(a3, 0.f);
        float g = a0 * Wi2s[lane] + a1 * Wi2s[lane + 32] + a2 * Wi2s[lane + 64] + a3 * Wi2s[lane + 96];

        float v0 = bj1s[lane], v1 = bj1s[lane + 32], v2 = bj1s[lane + 64], v3 = bj1s[lane + 96];
#pragma unroll
        for (int c = 0; c < 16; ++c) {
            float cc = __shfl_sync(0xffffffffu, hv, c);
            v0 += cc * Wj1s[c * 128 + lane];
            v1 += cc * Wj1s[c * 128 + lane + 32];
            v2 += cc * Wj1s[c * 128 + lane + 64];
            v3 += cc * Wj1s[c * 128 + lane + 96];
        }
        v0 = fmaxf(v0, 0.f); v1 = fmaxf(v1, 0.f); v2 = fmaxf(v2, 0.f); v3 = fmaxf(v3, 0.f);
        float vv = v0 * Wj2s[lane] + v1 * Wj2s[lane + 32] + v2 * Wj2s[lane + 64] + v3 * Wj2s[lane + 96];

#pragma unroll
        for (int s = 16; s > 0; s >>= 1) {
            g  += __shfl_xor_sync(0xffffffffu, g, s);
            vv += __shfl_xor_sync(0xffffffffu, vv, s);
        }
        if (lane == 0) {
            float gate = 1.f / (1.f + expf(-(g + bi2[0])));
            contrib = gate * (vv + bj2[0]);
        }
    }
    if (lane == 0) warpsum[w] = contrib;
    __syncthreads();
    if (tid == 0) {
        float s = 0.f;
#pragma unroll
        for (int i = 0; i < 8; ++i) s += warpsum[i];
        atomicAdd(out, s);
    }
}

// ===========================================================================
extern "C" void kernel_launch(void* const* d_in, const int* in_sizes, int n_in,
                              void* d_out, int out_size)
{
    const float* x          = (const float*)d_in[0];
    const int*   edge_index = (const int*)  d_in[1];
    const float* edge_attr  = (const float*)d_in[2];
    const float* W1  = (const float*)d_in[3];
    const float* b1  = (const float*)d_in[4];
    const float* W2  = (const float*)d_in[5];
    const float* b2  = (const float*)d_in[6];
    const float* W3  = (const float*)d_in[7];
    const float* b3  = (const float*)d_in[8];
    const float* root = (const float*)d_in[9];
    const float* bias = (const float*)d_in[10];
    const float* Wi1 = (const float*)d_in[11];
    const float* bi1 = (const float*)d_in[12];
    const float* Wi2 = (const float*)d_in[13];
    const float* bi2 = (const float*)d_in[14];
    const float* Wj1 = (const float*)d_in[15];
    const float* bj1 = (const float*)d_in[16];
    const float* Wj2 = (const float*)d_in[17];
    const float* bj2 = (const float*)d_in[18];

    int N = in_sizes[0] / 8;  if (N > NMAX) N = NMAX;
    int E = in_sizes[1] / 2;  if (E > EMAX) E = EMAX;
    float* out = (float*)d_out;

    cudaFuncSetAttribute(fused_edge_kernel,
                         cudaFuncAttributeMaxDynamicSharedMemorySize, FZ_SMEM);

    int node_blocks = (N * 16 + 255) / 256;
    int edge_blocks = (E + 7) / 8;
    int ntiles      = (E + 255) / 256;
    int fused_grid  = ntiles < 148 ? ntiles : 148;

    // Launch order arranged so ncu (-s 5 -c 1) profiles the fused kernel (#6).
    w3_split_kernel<<<64, 256>>>(W3);                                   // 1
    w2_split_kernel<<<16, 256>>>(W2);                                   // 2
    init_h_kernel<<<node_blocks, 256>>>(x, N);                          // 3
    node_init_kernel<<<node_blocks, 256>>>(0, 1, root, bias, N);        // 4
    zero_out_kernel<<<1, 32>>>(out);                                    // 5
    fused_edge_kernel<<<fused_grid, 256, FZ_SMEM>>>(edge_attr, W1, b1,  // 6
                                                    b2, b3, E, ntiles);
    msg_kernel<<<edge_blocks, 256>>>(0, 1, edge_index, E);              // 7

    node_init_kernel<<<node_blocks, 256>>>(1, 2, root, bias, N);
    msg_kernel<<<edge_blocks, 256>>>(1, 2, edge_index, E);
    node_init_kernel<<<node_blocks, 256>>>(2, 1, root, bias, N);
    msg_kernel<<<edge_blocks, 256>>>(2, 1, edge_index, E);

    readout_kernel<<<(N + 7) / 8, 256>>>(1, Wi1, bi1, Wi2, bi2,
                                         Wj1, bj1, Wj2, bj2, out, N);
}

// round 11
// speedup vs baseline: 5.0476x; 1.0879x over previous
#include <cuda_runtime.h>
#include <cuda_bf16.h>
#include <cuda_fp16.h>
#include <math.h>
#include <stdint.h>

// Problem constants (fixed by the dataset)
#define NMAX 100000
#define EMAX 800000

// Scratch (device globals: allocation-free per harness rules)
__device__ __half g_Wedgeh[(size_t)EMAX * 256];     // 409 MB per-edge 16x16 (fp16)
__device__ float  g_h[3][NMAX * 16];                // slot0 = h0, 1/2 ping-pong
__device__ __nv_bfloat16 g_W3b0[256 * 64];          // W3^T limb hi (n-major)
__device__ __nv_bfloat16 g_W3b1[256 * 64];          // W3^T limb lo
__device__ __nv_bfloat16 g_W2b0[64 * 64];           // W2^T limb hi (n-major)
__device__ __nv_bfloat16 g_W2b1[64 * 64];           // W2^T limb lo

// ---------------------------------------------------------------------------
// bf16 helpers (mma.sync m16n8k16 is sm_80+, compiles for plain compute_100)
// ---------------------------------------------------------------------------
__device__ __forceinline__ void mma_bf16(float* c, const uint32_t* a,
                                         uint32_t b0, uint32_t b1) {
    asm volatile(
        "mma.sync.aligned.m16n8k16.row.col.f32.bf16.bf16.f32 "
        "{%0,%1,%2,%3}, {%4,%5,%6,%7}, {%8,%9}, {%0,%1,%2,%3};"
        : "+f"(c[0]), "+f"(c[1]), "+f"(c[2]), "+f"(c[3])
        : "r"(a[0]), "r"(a[1]), "r"(a[2]), "r"(a[3]), "r"(b0), "r"(b1));
}

__device__ __forceinline__ uint32_t pack_bf2(float v0, float v1,
                                             float& r0, float& r1) {
    __nv_bfloat16 h0 = __float2bfloat16(v0);
    __nv_bfloat16 h1 = __float2bfloat16(v1);
    r0 = v0 - __bfloat162float(h0);
    r1 = v1 - __bfloat162float(h1);
    __nv_bfloat162 t = __halves2bfloat162(h0, h1);
    return *reinterpret_cast<uint32_t*>(&t);
}
__device__ __forceinline__ uint32_t pack_bf2_only(float v0, float v1) {
    __nv_bfloat16 h0 = __float2bfloat16(v0);
    __nv_bfloat16 h1 = __float2bfloat16(v1);
    __nv_bfloat162 t = __halves2bfloat162(h0, h1);
    return *reinterpret_cast<uint32_t*>(&t);
}

// Weight splits: W [64, Nout] fp32 row-major -> n-major bf16 limb planes
__global__ void w3_split_kernel(const float* __restrict__ W3)
{
    int idx = blockIdx.x * blockDim.x + threadIdx.x;
    if (idx >= 64 * 256) return;
    int k = idx >> 8, n = idx & 255;
    float v = W3[idx];
    __nv_bfloat16 h = __float2bfloat16(v);
    g_W3b0[n * 64 + k] = h;
    g_W3b1[n * 64 + k] = __float2bfloat16(v - __bfloat162float(h));
}
__global__ void w2_split_kernel(const float* __restrict__ W2)
{
    int idx = blockIdx.x * blockDim.x + threadIdx.x;
    if (idx >= 64 * 64) return;
    int k = idx >> 6, n = idx & 63;
    float v = W2[idx];
    __nv_bfloat16 h = __float2bfloat16(v);
    g_W2b0[n * 64 + k] = h;
    g_W2b1[n * 64 + k] = __float2bfloat16(v - __bfloat162float(h));
}

// ---------------------------------------------------------------------------
// FUSED edge pipeline (512 threads, 16 warps, warp = 16 edge rows):
//   stage1 (scalar, 2 threads/row): e1 = relu(ea@W1+b1) -> smem bf16 limbs
//   MMA1:  e2 = relu(e1@W2+b2)  -> register fragments (bf16 2-limb)
//   MMA2:  Wedge = e2@W3+b3     -> gmem fp16 (bf16 2-limb, 3 products)
// Persistent, grid<=148; two __syncthreads per 256-edge tile.
// Row stride 36 words: fragment banks 4*qr+tg, conflict-free.
// ---------------------------------------------------------------------------
#define FZ_E1_0   0
#define FZ_E1_1   36864
#define FZ_W2_0   73728
#define FZ_W2_1   82944
#define FZ_W3_0   92160
#define FZ_W3_1   129024
#define FZ_SMEM   165888

__global__ __launch_bounds__(512, 1)
void fused_edge_kernel(const float* __restrict__ edge_attr,
                       const float* __restrict__ W1, const float* __restrict__ b1,
                       const float* __restrict__ b2, const float* __restrict__ b3,
                       int E, int ntiles)
{
    extern __shared__ char smem[];
    uint32_t* E1_0 = (uint32_t*)(smem + FZ_E1_0);   // [256][36] words
    uint32_t* E1_1 = (uint32_t*)(smem + FZ_E1_1);
    uint32_t* W2s0 = (uint32_t*)(smem + FZ_W2_0);   // [64][36]
    uint32_t* W2s1 = (uint32_t*)(smem + FZ_W2_1);
    uint32_t* W3s0 = (uint32_t*)(smem + FZ_W3_0);   // [256][36]
    uint32_t* W3s1 = (uint32_t*)(smem + FZ_W3_1);
    __shared__ float W1s[256], b1s[64], b2s[64], b3s[256];

    int tid = threadIdx.x;
    // One-time loads (persistent kernel)
    for (int i = tid; i < 64 * 32; i += 512) {
        int r = i >> 5, w = i & 31;
        W2s0[r * 36 + w] = ((const uint32_t*)g_W2b0)[r * 32 + w];
        W2s1[r * 36 + w] = ((const uint32_t*)g_W2b1)[r * 32 + w];
    }
    for (int i = tid; i < 256 * 32; i += 512) {
        int r = i >> 5, w = i & 31;
        W3s0[r * 36 + w] = ((const uint32_t*)g_W3b0)[r * 32 + w];
        W3s1[r * 36 + w] = ((const uint32_t*)g_W3b1)[r * 32 + w];
    }
    if (tid < 256) { W1s[tid] = W1[tid]; b3s[tid] = b3[tid]; }
    if (tid >= 256 && tid < 320)  { b1s[tid - 256] = b1[tid - 256]; b2s[tid - 256] = b2[tid - 256]; }
    __syncthreads();

    int lane = tid & 31, wid = tid >> 5;
    int qr = lane >> 2, tg = lane & 3;
    int mrow = wid * 16;                    // warp's 16-row block
    int s1row = tid >> 1, s1p = tid & 1;    // stage1: 2 threads per edge row
    const float4* W1s4 = (const float4*)W1s;
    const float4* b1s4 = (const float4*)b1s;

    for (int t = blockIdx.x; t < ntiles; t += gridDim.x) {
        size_t ebase = (size_t)t * 256;

        // ---- stage 1: thread pair (row, half) -> 32 outputs each ----
        {
            size_t e = ebase + (size_t)s1row;
            float4 a = make_float4(0.f, 0.f, 0.f, 0.f);
            float vm = 0.f;
            if (e < (size_t)E) { a = ((const float4*)edge_attr)[e]; vm = 1.f; }
#pragma unroll
            for (int m4i = 0; m4i < 8; ++m4i) {
                int m4 = s1p * 8 + m4i;
                float4 w0 = W1s4[m4];
                float4 w1 = W1s4[16 + m4];
                float4 w2 = W1s4[32 + m4];
                float4 w3 = W1s4[48 + m4];
                float4 bb = b1s4[m4];
                float v0 = vm * fmaxf(bb.x + a.x*w0.x + a.y*w1.x + a.z*w2.x + a.w*w3.x, 0.f);
                float v1 = vm * fmaxf(bb.y + a.x*w0.y + a.y*w1.y + a.z*w2.y + a.w*w3.y, 0.f);
                float v2 = vm * fmaxf(bb.z + a.x*w0.z + a.y*w1.z + a.z*w2.z + a.w*w3.z, 0.f);
                float v3 = vm * fmaxf(bb.w + a.x*w0.w + a.y*w1.w + a.z*w2.w + a.w*w3.w, 0.f);
                float r0, r1, r2, r3;
                uint32_t h0 = pack_bf2(v0, v1, r0, r1);
                uint32_t h1 = pack_bf2(v2, v3, r2, r3);
                E1_0[s1row * 36 + 2 * m4]     = h0;
                E1_0[s1row * 36 + 2 * m4 + 1] = h1;
                E1_1[s1row * 36 + 2 * m4]     = pack_bf2_only(r0, r1);
                E1_1[s1row * 36 + 2 * m4 + 1] = pack_bf2_only(r2, r3);
            }
        }
        __syncthreads();

        // ---- MMA1: e2 = relu(e1 @ W2 + b2), accum in registers ----
        float cc1[8][4];
#pragma unroll
        for (int nt = 0; nt < 8; ++nt) {
            cc1[nt][0] = 0.f; cc1[nt][1] = 0.f;
            cc1[nt][2] = 0.f; cc1[nt][3] = 0.f;
        }
#pragma unroll
        for (int ks = 0; ks < 4; ++ks) {
            int kofs = ks * 8 + tg;
            uint32_t a0[4], a1[4];
            int r0 = mrow + qr;
            a0[0] = E1_0[r0 * 36 + kofs];
            a0[1] = E1_0[(r0 + 8) * 36 + kofs];
            a0[2] = E1_0[r0 * 36 + kofs + 4];
            a0[3] = E1_0[(r0 + 8) * 36 + kofs + 4];
            a1[0] = E1_1[r0 * 36 + kofs];
            a1[1] = E1_1[(r0 + 8) * 36 + kofs];
            a1[2] = E1_1[r0 * 36 + kofs + 4];
            a1[3] = E1_1[(r0 + 8) * 36 + kofs + 4];
#pragma unroll
            for (int nt = 0; nt < 8; ++nt) {
                int n = nt * 8 + qr;
                uint32_t b00 = W2s0[n * 36 + kofs];
                uint32_t b01 = W2s0[n * 36 + kofs + 4];
                uint32_t b10 = W2s1[n * 36 + kofs];
                uint32_t b11 = W2s1[n * 36 + kofs + 4];
                mma_bf16(cc1[nt], a0, b00, b01);
                mma_bf16(cc1[nt], a1, b00, b01);
                mma_bf16(cc1[nt], a0, b10, b11);
            }
        }

        // ---- relu(+b2) and repack C1 fragments as A2 fragments (in regs) ----
        uint32_t a2h[4][4], a2l[4][4];
#pragma unroll
        for (int nt = 0; nt < 8; ++nt) {
            float bb0 = b2s[nt * 8 + 2 * tg];
            float bb1 = b2s[nt * 8 + 2 * tg + 1];
            float d0 = fmaxf(cc1[nt][0] + bb0, 0.f);
            float d1 = fmaxf(cc1[nt][1] + bb1, 0.f);
            float d2 = fmaxf(cc1[nt][2] + bb0, 0.f);
            float d3 = fmaxf(cc1[nt][3] + bb1, 0.f);
            int ks2 = nt >> 1, q = (nt & 1) * 2;
            float r0, r1, r2, r3;
            a2h[ks2][q]     = pack_bf2(d0, d1, r0, r1);
            a2h[ks2][q + 1] = pack_bf2(d2, d3, r2, r3);
            a2l[ks2][q]     = pack_bf2_only(r0, r1);
            a2l[ks2][q + 1] = pack_bf2_only(r2, r3);
        }
        __syncthreads();   // E1 fully consumed -> next tile may overwrite

        // ---- MMA2: Wedge = e2 @ W3 + b3, n in 4 groups of 64 ----
        uint32_t* outw = (uint32_t*)g_Wedgeh;
#pragma unroll
        for (int grp = 0; grp < 4; ++grp) {
            int noff = grp * 64;
            float cc2[8][4];
#pragma unroll
            for (int nt = 0; nt < 8; ++nt) {
                cc2[nt][0] = 0.f; cc2[nt][1] = 0.f;
                cc2[nt][2] = 0.f; cc2[nt][3] = 0.f;
            }
#pragma unroll
            for (int ks = 0; ks < 4; ++ks) {
                int kofs = ks * 8 + tg;
#pragma unroll
                for (int nt = 0; nt < 8; ++nt) {
                    int n = noff + nt * 8 + qr;
                    uint32_t b00 = W3s0[n * 36 + kofs];
                    uint32_t b01 = W3s0[n * 36 + kofs + 4];
                    uint32_t b10 = W3s1[n * 36 + kofs];
                    uint32_t b11 = W3s1[n * 36 + kofs + 4];
                    mma_bf16(cc2[nt], a2h[ks], b00, b01);
                    mma_bf16(cc2[nt], a2l[ks], b00, b01);
                    mma_bf16(cc2[nt], a2h[ks], b10, b11);
                }
            }
            // Store fp16 (+b3)
            size_t e0 = ebase + (size_t)(mrow + qr);
            size_t e1 = e0 + 8;
            bool v0 = e0 < (size_t)E, v1 = e1 < (size_t)E;
#pragma unroll
            for (int nt = 0; nt < 8; ++nt) {
                int n0 = noff + nt * 8 + 2 * tg;
                float bb0 = b3s[n0], bb1 = b3s[n0 + 1];
                if (v0) {
                    __half2 hv = __float22half2_rn(
                        make_float2(cc2[nt][0] + bb0, cc2[nt][1] + bb1));
                    outw[e0 * 128 + (n0 >> 1)] = *reinterpret_cast<uint32_t*>(&hv);
                }
                if (v1) {
                    __half2 hv = __float22half2_rn(
                        make_float2(cc2[nt][2] + bb0, cc2[nt][3] + bb1));
                    outw[e1 * 128 + (n0 >> 1)] = *reinterpret_cast<uint32_t*>(&hv);
                }
            }
        }
    }
}

// ---------------------------------------------------------------------------
// h0 = [x | zeros]
// ---------------------------------------------------------------------------
__global__ void init_h_kernel(const float* __restrict__ x, int N)
{
    int idx = blockIdx.x * blockDim.x + threadIdx.x;
    if (idx >= N * 16) return;
    int n = idx >> 4, i = idx & 15;
    g_h[0][idx] = (i < 8) ? x[n * 8 + i] : 0.f;
}

// h_out = bias + h_in @ root
__global__ void node_init_kernel(int in_slot, int out_slot,
                                 const float* __restrict__ root,
                                 const float* __restrict__ bias, int N)
{
    __shared__ float rs[256];
    __shared__ float bs[16];
    int tid = threadIdx.x;
    if (tid < 256) rs[tid] = root[tid];
    if (tid < 16)  bs[tid] = bias[tid];
    __syncthreads();
    int idx = blockIdx.x * blockDim.x + tid;
    if (idx >= N * 16) return;
    int n = idx >> 4, o = idx & 15;
    const float* hr = g_h[in_slot] + n * 16;
    float acc = bs[o];
#pragma unroll
    for (int i = 0; i < 16; ++i) acc += hr[i] * rs[i * 16 + o];
    g_h[out_slot][idx] = acc;
}

// Message pass: h_out[dst] += h_in[src] @ Wedge[e] (fp16). One warp per edge.
// Lane l owns output pair o0=2*(l&7), o1=o0+1 over i in {l/8 + 4j}.
__global__ __launch_bounds__(256)
void msg_kernel(int in_slot, int out_slot, const int* __restrict__ edge_index, int E)
{
    int lane = threadIdx.x & 31;
    int e = (blockIdx.x * 256 + threadIdx.x) >> 5;
    if (e >= E) return;
    int src = edge_index[2 * e];
    int dst = edge_index[2 * e + 1];

    const float* h_in = g_h[in_slot] + (size_t)src * 16;
    float hv = (lane < 16) ? h_in[lane] : 0.f;

    const uint32_t* W = (const uint32_t*)(g_Wedgeh + (size_t)e * 256);
    float p0 = 0.f, p1 = 0.f;
    int ib = lane >> 3;
#pragma unroll
    for (int j = 0; j < 4; ++j) {
        uint32_t wv = W[lane + 32 * j];
        __half2 h2 = *reinterpret_cast<__half2*>(&wv);
        float2 wf = __half22float2(h2);
        float hk = __shfl_sync(0xffffffffu, hv, ib + 4 * j);
        p0 += hk * wf.x;
        p1 += hk * wf.y;
    }
    p0 += __shfl_xor_sync(0xffffffffu, p0, 8);
    p1 += __shfl_xor_sync(0xffffffffu, p1, 8);
    p0 += __shfl_xor_sync(0xffffffffu, p0, 16);
    p1 += __shfl_xor_sync(0xffffffffu, p1, 16);
    if (lane < 8) {
        float* dsth = &g_h[out_slot][(size_t)dst * 16 + 2 * lane];
        atomicAdd(dsth, p0);
        atomicAdd(dsth + 1, p1);
    }
}

// ---------------------------------------------------------------------------
// Readout
// ---------------------------------------------------------------------------
__global__ void zero_out_kernel(float* out)
{
    if (threadIdx.x == 0 && blockIdx.x == 0) out[0] = 0.f;
}

__global__ __launch_bounds__(256)
void readout_kernel(int h_slot,
                    const float* __restrict__ Wi1, const float* __restrict__ bi1,
                    const float* __restrict__ Wi2, const float* __restrict__ bi2,
                    const float* __restrict__ Wj1, const float* __restrict__ bj1,
                    const float* __restrict__ Wj2, const float* __restrict__ bj2,
                    float* __restrict__ out, int N)
{
    __shared__ float Wi1s[4096], Wj1s[2048];
    __shared__ float bi1s[128], bj1s[128], Wi2s[128], Wj2s[128];
    __shared__ float warpsum[8];

    int tid = threadIdx.x;
    for (int i = tid; i < 4096; i += 256) Wi1s[i] = Wi1[i];
    for (int i = tid; i < 2048; i += 256) Wj1s[i] = Wj1[i];
    if (tid < 128) {
        bi1s[tid] = bi1[tid]; bj1s[tid] = bj1[tid];
        Wi2s[tid] = Wi2[tid]; Wj2s[tid] = Wj2[tid];
    }
    __syncthreads();

    int lane = tid & 31, w = tid >> 5;
    int n = blockIdx.x * 8 + w;
    float contrib = 0.f;

    if (n < N) {
        const float* h  = g_h[h_slot] + n * 16;
        const float* h0 = g_h[0] + n * 16;
        float hv  = (lane < 16) ? h[lane]  : 0.f;
        float h0v = (lane < 16) ? h0[lane] : 0.f;

        float a0 = bi1s[lane], a1 = bi1s[lane + 32], a2 = bi1s[lane + 64], a3 = bi1s[lane + 96];
#pragma unroll
        for (int c = 0; c < 32; ++c) {
            float cc = __shfl_sync(0xffffffffu, (c < 16) ? hv : h0v, c & 15);
            a0 += cc * Wi1s[c * 128 + lane];
            a1 += cc * Wi1s[c * 128 + lane + 32];
            a2 += cc * Wi1s[c * 128 + lane + 64];
            a3 += cc * Wi1s[c * 128 + lane + 96];
        }
        a0 = fmaxf(a0, 0.f); a1 = fmaxf(a1, 0.f); a2 = fmaxf(a2, 0.f); a3 = fmaxf(a3, 0.f);
        float g = a0 * Wi2s[lane] + a1 * Wi2s[lane + 32] + a2 * Wi2s[lane + 64] + a3 * Wi2s[lane + 96];

        float v0 = bj1s[lane], v1 = bj1s[lane + 32], v2 = bj1s[lane + 64], v3 = bj1s[lane + 96];
#pragma unroll
        for (int c = 0; c < 16; ++c) {
            float cc = __shfl_sync(0xffffffffu, hv, c);
            v0 += cc * Wj1s[c * 128 + lane];
            v1 += cc * Wj1s[c * 128 + lane + 32];
            v2 += cc * Wj1s[c * 128 + lane + 64];
            v3 += cc * Wj1s[c * 128 + lane + 96];
        }
        v0 = fmaxf(v0, 0.f); v1 = fmaxf(v1, 0.f); v2 = fmaxf(v2, 0.f); v3 = fmaxf(v3, 0.f);
        float vv = v0 * Wj2s[lane] + v1 * Wj2s[lane + 32] + v2 * Wj2s[lane + 64] + v3 * Wj2s[lane + 96];

#pragma unroll
        for (int s = 16; s > 0; s >>= 1) {
            g  += __shfl_xor_sync(0xffffffffu, g, s);
            vv += __shfl_xor_sync(0xffffffffu, vv, s);
        }
        if (lane == 0) {
            float gate = 1.f / (1.f + expf(-(g + bi2[0])));
            contrib = gate * (vv + bj2[0]);
        }
    }
    if (lane == 0) warpsum[w] = contrib;
    __syncthreads();
    if (tid == 0) {
        float s = 0.f;
#pragma unroll
        for (int i = 0; i < 8; ++i) s += warpsum[i];
        atomicAdd(out, s);
    }
}

// ===========================================================================
extern "C" void kernel_launch(void* const* d_in, const int* in_sizes, int n_in,
                              void* d_out, int out_size)
{
    const float* x          = (const float*)d_in[0];
    const int*   edge_index = (const int*)  d_in[1];
    const float* edge_attr  = (const float*)d_in[2];
    const float* W1  = (const float*)d_in[3];
    const float* b1  = (const float*)d_in[4];
    const float* W2  = (const float*)d_in[5];
    const float* b2  = (const float*)d_in[6];
    const float* W3  = (const float*)d_in[7];
    const float* b3  = (const float*)d_in[8];
    const float* root = (const float*)d_in[9];
    const float* bias = (const float*)d_in[10];
    const float* Wi1 = (const float*)d_in[11];
    const float* bi1 = (const float*)d_in[12];
    const float* Wi2 = (const float*)d_in[13];
    const float* bi2 = (const float*)d_in[14];
    const float* Wj1 = (const float*)d_in[15];
    const float* bj1 = (const float*)d_in[16];
    const float* Wj2 = (const float*)d_in[17];
    const float* bj2 = (const float*)d_in[18];

    int N = in_sizes[0] / 8;  if (N > NMAX) N = NMAX;
    int E = in_sizes[1] / 2;  if (E > EMAX) E = EMAX;
    float* out = (float*)d_out;

    cudaFuncSetAttribute(fused_edge_kernel,
                         cudaFuncAttributeMaxDynamicSharedMemorySize, FZ_SMEM);

    int node_blocks = (N * 16 + 255) / 256;
    int edge_blocks = (E + 7) / 8;
    int ntiles      = (E + 255) / 256;
    int fused_grid  = ntiles < 148 ? ntiles : 148;

    w3_split_kernel<<<64, 256>>>(W3);
    w2_split_kernel<<<16, 256>>>(W2);
    init_h_kernel<<<node_blocks, 256>>>(x, N);
    node_init_kernel<<<node_blocks, 256>>>(0, 1, root, bias, N);
    zero_out_kernel<<<1, 32>>>(out);
    fused_edge_kernel<<<fused_grid, 512, FZ_SMEM>>>(edge_attr, W1, b1,
                                                    b2, b3, E, ntiles);
    msg_kernel<<<edge_blocks, 256>>>(0, 1, edge_index, E);

    node_init_kernel<<<node_blocks, 256>>>(1, 2, root, bias, N);
    msg_kernel<<<edge_blocks, 256>>>(1, 2, edge_index, E);
    node_init_kernel<<<node_blocks, 256>>>(2, 1, root, bias, N);
    msg_kernel<<<edge_blocks, 256>>>(2, 1, edge_index, E);

    readout_kernel<<<(N + 7) / 8, 256>>>(1, Wi1, bi1, Wi2, bi2,
                                         Wj1, bj1, Wj2, bj2, out, N);
}

// round 12
// speedup vs baseline: 5.3295x; 1.0559x over previous
#include <cuda_runtime.h>
#include <cuda_bf16.h>
#include <cuda_fp16.h>
#include <math.h>
#include <stdint.h>

// Problem constants (fixed by the dataset)
#define NMAX 100000
#define EMAX 800000

// Scratch (device globals: allocation-free per harness rules)
__device__ __half g_Wedgeh[(size_t)EMAX * 256];     // 409 MB per-edge 16x16 (fp16)
__device__ float  g_h[3][NMAX * 16];                // slot0 = h0, 1/2 ping-pong
__device__ __nv_bfloat16 g_W3b0[256 * 64];          // W3^T limb hi (n-major)
__device__ __nv_bfloat16 g_W3b1[256 * 64];          // W3^T limb lo
__device__ __nv_bfloat16 g_W2b0[64 * 64];           // W2^T limb hi (n-major)
__device__ __nv_bfloat16 g_W2b1[64 * 64];           // W2^T limb lo

// ---------------------------------------------------------------------------
// bf16 helpers (mma.sync m16n8k16 is sm_80+, compiles for plain compute_100)
// ---------------------------------------------------------------------------
__device__ __forceinline__ void mma_bf16(float* c, const uint32_t* a,
                                         uint32_t b0, uint32_t b1) {
    asm volatile(
        "mma.sync.aligned.m16n8k16.row.col.f32.bf16.bf16.f32 "
        "{%0,%1,%2,%3}, {%4,%5,%6,%7}, {%8,%9}, {%0,%1,%2,%3};"
        : "+f"(c[0]), "+f"(c[1]), "+f"(c[2]), "+f"(c[3])
        : "r"(a[0]), "r"(a[1]), "r"(a[2]), "r"(a[3]), "r"(b0), "r"(b1));
}

__device__ __forceinline__ uint32_t pack_bf2(float v0, float v1,
                                             float& r0, float& r1) {
    __nv_bfloat16 h0 = __float2bfloat16(v0);
    __nv_bfloat16 h1 = __float2bfloat16(v1);
    r0 = v0 - __bfloat162float(h0);
    r1 = v1 - __bfloat162float(h1);
    __nv_bfloat162 t = __halves2bfloat162(h0, h1);
    return *reinterpret_cast<uint32_t*>(&t);
}
__device__ __forceinline__ uint32_t pack_bf2_only(float v0, float v1) {
    __nv_bfloat16 h0 = __float2bfloat16(v0);
    __nv_bfloat16 h1 = __float2bfloat16(v1);
    __nv_bfloat162 t = __halves2bfloat162(h0, h1);
    return *reinterpret_cast<uint32_t*>(&t);
}

// Weight splits: W [64, Nout] fp32 row-major -> n-major bf16 limb planes
__global__ void w3_split_kernel(const float* __restrict__ W3)
{
    int idx = blockIdx.x * blockDim.x + threadIdx.x;
    if (idx >= 64 * 256) return;
    int k = idx >> 8, n = idx & 255;
    float v = W3[idx];
    __nv_bfloat16 h = __float2bfloat16(v);
    g_W3b0[n * 64 + k] = h;
    g_W3b1[n * 64 + k] = __float2bfloat16(v - __bfloat162float(h));
}
__global__ void w2_split_kernel(const float* __restrict__ W2)
{
    int idx = blockIdx.x * blockDim.x + threadIdx.x;
    if (idx >= 64 * 64) return;
    int k = idx >> 6, n = idx & 63;
    float v = W2[idx];
    __nv_bfloat16 h = __float2bfloat16(v);
    g_W2b0[n * 64 + k] = h;
    g_W2b1[n * 64 + k] = __float2bfloat16(v - __bfloat162float(h));
}

// ---------------------------------------------------------------------------
// FUSED edge pipeline (256 threads, 8 warps, warp = 32 edge rows — the R10
// configuration that measured fastest; B-fragment smem reads amortized over
// 32 rows/warp):
//   stage1 (scalar): e1 = relu(ea@W1+b1) -> warp-private smem bf16 limbs
//   MMA1:  e2 = relu(e1@W2+b2)  -> register fragments (bf16 2-limb)
//   MMA2:  Wedge = e2@W3+b3     -> gmem fp16 (bf16 2-limb, 3 products)
// Persistent, grid<=148; only __syncwarp in the tile loop.
// Row stride 36 words: fragment banks 4*qr+tg, conflict-free.
// ---------------------------------------------------------------------------
#define FZ_E1_0   0
#define FZ_E1_1   36864
#define FZ_W2_0   73728
#define FZ_W2_1   82944
#define FZ_W3_0   92160
#define FZ_W3_1   129024
#define FZ_SMEM   165888

__global__ __launch_bounds__(256, 1)
void fused_edge_kernel(const float* __restrict__ edge_attr,
                       const float* __restrict__ W1, const float* __restrict__ b1,
                       const float* __restrict__ b2, const float* __restrict__ b3,
                       int E, int ntiles)
{
    extern __shared__ char smem[];
    uint32_t* E1_0 = (uint32_t*)(smem + FZ_E1_0);   // [256][36] words
    uint32_t* E1_1 = (uint32_t*)(smem + FZ_E1_1);
    uint32_t* W2s0 = (uint32_t*)(smem + FZ_W2_0);   // [64][36]
    uint32_t* W2s1 = (uint32_t*)(smem + FZ_W2_1);
    uint32_t* W3s0 = (uint32_t*)(smem + FZ_W3_0);   // [256][36]
    uint32_t* W3s1 = (uint32_t*)(smem + FZ_W3_1);
    __shared__ float W1s[256], b1s[64], b2s[64], b3s[256];

    int tid = threadIdx.x;
    // One-time loads (persistent kernel)
    for (int i = tid; i < 64 * 32; i += 256) {
        int r = i >> 5, w = i & 31;
        W2s0[r * 36 + w] = ((const uint32_t*)g_W2b0)[r * 32 + w];
        W2s1[r * 36 + w] = ((const uint32_t*)g_W2b1)[r * 32 + w];
    }
    for (int i = tid; i < 256 * 32; i += 256) {
        int r = i >> 5, w = i & 31;
        W3s0[r * 36 + w] = ((const uint32_t*)g_W3b0)[r * 32 + w];
        W3s1[r * 36 + w] = ((const uint32_t*)g_W3b1)[r * 32 + w];
    }
    if (tid < 256) { W1s[tid] = W1[tid]; b3s[tid] = b3[tid]; }
    if (tid < 64)  { b1s[tid] = b1[tid]; b2s[tid] = b2[tid]; }
    __syncthreads();

    int lane = tid & 31, wid = tid >> 5;
    int qr = lane >> 2, tg = lane & 3;
    int mrow = wid * 32;                    // warp's 32-row block
    const float4* W1s4 = (const float4*)W1s;
    const float4* b1s4 = (const float4*)b1s;

    for (int t = blockIdx.x; t < ntiles; t += gridDim.x) {
        size_t ebase = (size_t)t * 256;

        // ---- stage 1: thread tid -> edge row tid; warp-private rows ----
        {
            size_t e = ebase + (size_t)tid;
            float4 a = make_float4(0.f, 0.f, 0.f, 0.f);
            float vm = 0.f;
            if (e < (size_t)E) { a = ((const float4*)edge_attr)[e]; vm = 1.f; }
#pragma unroll
            for (int m4 = 0; m4 < 16; ++m4) {
                float4 w0 = W1s4[m4];
                float4 w1 = W1s4[16 + m4];
                float4 w2 = W1s4[32 + m4];
                float4 w3 = W1s4[48 + m4];
                float4 bb = b1s4[m4];
                float v0 = vm * fmaxf(bb.x + a.x*w0.x + a.y*w1.x + a.z*w2.x + a.w*w3.x, 0.f);
                float v1 = vm * fmaxf(bb.y + a.x*w0.y + a.y*w1.y + a.z*w2.y + a.w*w3.y, 0.f);
                float v2 = vm * fmaxf(bb.z + a.x*w0.z + a.y*w1.z + a.z*w2.z + a.w*w3.z, 0.f);
                float v3 = vm * fmaxf(bb.w + a.x*w0.w + a.y*w1.w + a.z*w2.w + a.w*w3.w, 0.f);
                float r0, r1, r2, r3;
                uint32_t h0 = pack_bf2(v0, v1, r0, r1);
                uint32_t h1 = pack_bf2(v2, v3, r2, r3);
                E1_0[tid * 36 + 2 * m4]     = h0;
                E1_0[tid * 36 + 2 * m4 + 1] = h1;
                E1_1[tid * 36 + 2 * m4]     = pack_bf2_only(r0, r1);
                E1_1[tid * 36 + 2 * m4 + 1] = pack_bf2_only(r2, r3);
            }
        }
        __syncwarp();

        // ---- MMA1: e2 = relu(e1 @ W2 + b2), accum in registers ----
        float cc1[2][8][4];
#pragma unroll
        for (int mt = 0; mt < 2; ++mt)
#pragma unroll
            for (int nt = 0; nt < 8; ++nt) {
                cc1[mt][nt][0] = 0.f; cc1[mt][nt][1] = 0.f;
                cc1[mt][nt][2] = 0.f; cc1[mt][nt][3] = 0.f;
            }
#pragma unroll
        for (int ks = 0; ks < 4; ++ks) {
            int kofs = ks * 8 + tg;
            uint32_t a0[2][4], a1[2][4];
#pragma unroll
            for (int mt = 0; mt < 2; ++mt) {
                int r0 = mrow + mt * 16 + qr;
                a0[mt][0] = E1_0[r0 * 36 + kofs];
                a0[mt][1] = E1_0[(r0 + 8) * 36 + kofs];
                a0[mt][2] = E1_0[r0 * 36 + kofs + 4];
                a0[mt][3] = E1_0[(r0 + 8) * 36 + kofs + 4];
                a1[mt][0] = E1_1[r0 * 36 + kofs];
                a1[mt][1] = E1_1[(r0 + 8) * 36 + kofs];
                a1[mt][2] = E1_1[r0 * 36 + kofs + 4];
                a1[mt][3] = E1_1[(r0 + 8) * 36 + kofs + 4];
            }
#pragma unroll
            for (int nt = 0; nt < 8; ++nt) {
                int n = nt * 8 + qr;
                uint32_t b00 = W2s0[n * 36 + kofs];
                uint32_t b01 = W2s0[n * 36 + kofs + 4];
                uint32_t b10 = W2s1[n * 36 + kofs];
                uint32_t b11 = W2s1[n * 36 + kofs + 4];
#pragma unroll
                for (int mt = 0; mt < 2; ++mt) {
                    mma_bf16(cc1[mt][nt], a0[mt], b00, b01);
                    mma_bf16(cc1[mt][nt], a1[mt], b00, b01);
                    mma_bf16(cc1[mt][nt], a0[mt], b10, b11);
                }
            }
        }

        // ---- relu(+b2) and repack C1 fragments as A2 fragments (in regs) ----
        uint32_t a2h[2][4][4], a2l[2][4][4];
#pragma unroll
        for (int mt = 0; mt < 2; ++mt)
#pragma unroll
            for (int nt = 0; nt < 8; ++nt) {
                float bb0 = b2s[nt * 8 + 2 * tg];
                float bb1 = b2s[nt * 8 + 2 * tg + 1];
                float d0 = fmaxf(cc1[mt][nt][0] + bb0, 0.f);
                float d1 = fmaxf(cc1[mt][nt][1] + bb1, 0.f);
                float d2 = fmaxf(cc1[mt][nt][2] + bb0, 0.f);
                float d3 = fmaxf(cc1[mt][nt][3] + bb1, 0.f);
                int ks2 = nt >> 1, q = (nt & 1) * 2;
                float r0, r1, r2, r3;
                a2h[mt][ks2][q]     = pack_bf2(d0, d1, r0, r1);
                a2h[mt][ks2][q + 1] = pack_bf2(d2, d3, r2, r3);
                a2l[mt][ks2][q]     = pack_bf2_only(r0, r1);
                a2l[mt][ks2][q + 1] = pack_bf2_only(r2, r3);
            }

        // ---- MMA2: Wedge = e2 @ W3 + b3, n in 4 groups of 64; fp16 store ----
        uint32_t* outw = (uint32_t*)g_Wedgeh;
#pragma unroll
        for (int grp = 0; grp < 4; ++grp) {
            int noff = grp * 64;
            float cc2[2][8][4];
#pragma unroll
            for (int mt = 0; mt < 2; ++mt)
#pragma unroll
                for (int nt = 0; nt < 8; ++nt) {
                    cc2[mt][nt][0] = 0.f; cc2[mt][nt][1] = 0.f;
                    cc2[mt][nt][2] = 0.f; cc2[mt][nt][3] = 0.f;
                }
#pragma unroll
            for (int ks = 0; ks < 4; ++ks) {
                int kofs = ks * 8 + tg;
#pragma unroll
                for (int nt = 0; nt < 8; ++nt) {
                    int n = noff + nt * 8 + qr;
                    uint32_t b00 = W3s0[n * 36 + kofs];
                    uint32_t b01 = W3s0[n * 36 + kofs + 4];
                    uint32_t b10 = W3s1[n * 36 + kofs];
                    uint32_t b11 = W3s1[n * 36 + kofs + 4];
#pragma unroll
                    for (int mt = 0; mt < 2; ++mt) {
                        mma_bf16(cc2[mt][nt], a2h[mt][ks], b00, b01);
                        mma_bf16(cc2[mt][nt], a2l[mt][ks], b00, b01);
                        mma_bf16(cc2[mt][nt], a2h[mt][ks], b10, b11);
                    }
                }
            }
            // Store fp16 (+b3)
#pragma unroll
            for (int mt = 0; mt < 2; ++mt) {
                size_t e0 = ebase + (size_t)(mrow + mt * 16 + qr);
                size_t e1 = e0 + 8;
                bool v0 = e0 < (size_t)E, v1 = e1 < (size_t)E;
#pragma unroll
                for (int nt = 0; nt < 8; ++nt) {
                    int n0 = noff + nt * 8 + 2 * tg;
                    float bb0 = b3s[n0], bb1 = b3s[n0 + 1];
                    if (v0) {
                        __half2 hv = __float22half2_rn(
                            make_float2(cc2[mt][nt][0] + bb0, cc2[mt][nt][1] + bb1));
                        outw[e0 * 128 + (n0 >> 1)] = *reinterpret_cast<uint32_t*>(&hv);
                    }
                    if (v1) {
                        __half2 hv = __float22half2_rn(
                            make_float2(cc2[mt][nt][2] + bb0, cc2[mt][nt][3] + bb1));
                        outw[e1 * 128 + (n0 >> 1)] = *reinterpret_cast<uint32_t*>(&hv);
                    }
                }
            }
        }
    }
}

// ---------------------------------------------------------------------------
// h0 = [x | zeros]
// ---------------------------------------------------------------------------
__global__ void init_h_kernel(const float* __restrict__ x, int N)
{
    int idx = blockIdx.x * blockDim.x + threadIdx.x;
    if (idx >= N * 16) return;
    int n = idx >> 4, i = idx & 15;
    g_h[0][idx] = (i < 8) ? x[n * 8 + i] : 0.f;
}

// h_out = bias + h_in @ root
__global__ void node_init_kernel(int in_slot, int out_slot,
                                 const float* __restrict__ root,
                                 const float* __restrict__ bias, int N)
{
    __shared__ float rs[256];
    __shared__ float bs[16];
    int tid = threadIdx.x;
    if (tid < 256) rs[tid] = root[tid];
    if (tid < 16)  bs[tid] = bias[tid];
    __syncthreads();
    int idx = blockIdx.x * blockDim.x + tid;
    if (idx >= N * 16) return;
    int n = idx >> 4, o = idx & 15;
    const float* hr = g_h[in_slot] + n * 16;
    float acc = bs[o];
#pragma unroll
    for (int i = 0; i < 16; ++i) acc += hr[i] * rs[i * 16 + o];
    g_h[out_slot][idx] = acc;
}

// Message pass: h_out[dst] += h_in[src] @ Wedge[e] (fp16). One warp per edge.
// Lane l owns output pair o0=2*(l&7), o1=o0+1 over i in {l/8 + 4j}.
__global__ __launch_bounds__(256)
void msg_kernel(int in_slot, int out_slot, const int* __restrict__ edge_index, int E)
{
    int lane = threadIdx.x & 31;
    int e = (blockIdx.x * 256 + threadIdx.x) >> 5;
    if (e >= E) return;
    int src = edge_index[2 * e];
    int dst = edge_index[2 * e + 1];

    const float* h_in = g_h[in_slot] + (size_t)src * 16;
    float hv = (lane < 16) ? h_in[lane] : 0.f;

    const uint32_t* W = (const uint32_t*)(g_Wedgeh + (size_t)e * 256);
    float p0 = 0.f, p1 = 0.f;
    int ib = lane >> 3;
#pragma unroll
    for (int j = 0; j < 4; ++j) {
        uint32_t wv = W[lane + 32 * j];
        __half2 h2 = *reinterpret_cast<__half2*>(&wv);
        float2 wf = __half22float2(h2);
        float hk = __shfl_sync(0xffffffffu, hv, ib + 4 * j);
        p0 += hk * wf.x;
        p1 += hk * wf.y;
    }
    p0 += __shfl_xor_sync(0xffffffffu, p0, 8);
    p1 += __shfl_xor_sync(0xffffffffu, p1, 8);
    p0 += __shfl_xor_sync(0xffffffffu, p0, 16);
    p1 += __shfl_xor_sync(0xffffffffu, p1, 16);
    if (lane < 8) {
        float* dsth = &g_h[out_slot][(size_t)dst * 16 + 2 * lane];
        atomicAdd(dsth, p0);
        atomicAdd(dsth + 1, p1);
    }
}

// ---------------------------------------------------------------------------
// Readout
// ---------------------------------------------------------------------------
__global__ void zero_out_kernel(float* out)
{
    if (threadIdx.x == 0 && blockIdx.x == 0) out[0] = 0.f;
}

__global__ __launch_bounds__(256)
void readout_kernel(int h_slot,
                    const float* __restrict__ Wi1, const float* __restrict__ bi1,
                    const float* __restrict__ Wi2, const float* __restrict__ bi2,
                    const float* __restrict__ Wj1, const float* __restrict__ bj1,
                    const float* __restrict__ Wj2, const float* __restrict__ bj2,
                    float* __restrict__ out, int N)
{
    __shared__ float Wi1s[4096], Wj1s[2048];
    __shared__ float bi1s[128], bj1s[128], Wi2s[128], Wj2s[128];
    __shared__ float warpsum[8];

    int tid = threadIdx.x;
    for (int i = tid; i < 4096; i += 256) Wi1s[i] = Wi1[i];
    for (int i = tid; i < 2048; i += 256) Wj1s[i] = Wj1[i];
    if (tid < 128) {
        bi1s[tid] = bi1[tid]; bj1s[tid] = bj1[tid];
        Wi2s[tid] = Wi2[tid]; Wj2s[tid] = Wj2[tid];
    }
    __syncthreads();

    int lane = tid & 31, w = tid >> 5;
    int n = blockIdx.x * 8 + w;
    float contrib = 0.f;

    if (n < N) {
        const float* h  = g_h[h_slot] + n * 16;
        const float* h0 = g_h[0] + n * 16;
        float hv  = (lane < 16) ? h[lane]  : 0.f;
        float h0v = (lane < 16) ? h0[lane] : 0.f;

        float a0 = bi1s[lane], a1 = bi1s[lane + 32], a2 = bi1s[lane + 64], a3 = bi1s[lane + 96];
#pragma unroll
        for (int c = 0; c < 32; ++c) {
            float cc = __shfl_sync(0xffffffffu, (c < 16) ? hv : h0v, c & 15);
            a0 += cc * Wi1s[c * 128 + lane];
            a1 += cc * Wi1s[c * 128 + lane + 32];
            a2 += cc * Wi1s[c * 128 + lane + 64];
            a3 += cc * Wi1s[c * 128 + lane + 96];
        }
        a0 = fmaxf(a0, 0.f); a1 = fmaxf(a1, 0.f); a2 = fmaxf(a2, 0.f); a3 = fmaxf(a3, 0.f);
        float g = a0 * Wi2s[lane] + a1 * Wi2s[lane + 32] + a2 * Wi2s[lane + 64] + a3 * Wi2s[lane + 96];

        float v0 = bj1s[lane], v1 = bj1s[lane + 32], v2 = bj1s[lane + 64], v3 = bj1s[lane + 96];
#pragma unroll
        for (int c = 0; c < 16; ++c) {
            float cc = __shfl_sync(0xffffffffu, hv, c);
            v0 += cc * Wj1s[c * 128 + lane];
            v1 += cc * Wj1s[c * 128 + lane + 32];
            v2 += cc * Wj1s[c * 128 + lane + 64];
            v3 += cc * Wj1s[c * 128 + lane + 96];
        }
        v0 = fmaxf(v0, 0.f); v1 = fmaxf(v1, 0.f); v2 = fmaxf(v2, 0.f); v3 = fmaxf(v3, 0.f);
        float vv = v0 * Wj2s[lane] + v1 * Wj2s[lane + 32] + v2 * Wj2s[lane + 64] + v3 * Wj2s[lane + 96];

#pragma unroll
        for (int s = 16; s > 0; s >>= 1) {
            g  += __shfl_xor_sync(0xffffffffu, g, s);
            vv += __shfl_xor_sync(0xffffffffu, vv, s);
        }
        if (lane == 0) {
            float gate = 1.f / (1.f + expf(-(g + bi2[0])));
            contrib = gate * (vv + bj2[0]);
        }
    }
    if (lane == 0) warpsum[w] = contrib;
    __syncthreads();
    if (tid == 0) {
        float s = 0.f;
#pragma unroll
        for (int i = 0; i < 8; ++i) s += warpsum[i];
        atomicAdd(out, s);
    }
}

// ===========================================================================
extern "C" void kernel_launch(void* const* d_in, const int* in_sizes, int n_in,
                              void* d_out, int out_size)
{
    const float* x          = (const float*)d_in[0];
    const int*   edge_index = (const int*)  d_in[1];
    const float* edge_attr  = (const float*)d_in[2];
    const float* W1  = (const float*)d_in[3];
    const float* b1  = (const float*)d_in[4];
    const float* W2  = (const float*)d_in[5];
    const float* b2  = (const float*)d_in[6];
    const float* W3  = (const float*)d_in[7];
    const float* b3  = (const float*)d_in[8];
    const float* root = (const float*)d_in[9];
    const float* bias = (const float*)d_in[10];
    const float* Wi1 = (const float*)d_in[11];
    const float* bi1 = (const float*)d_in[12];
    const float* Wi2 = (const float*)d_in[13];
    const float* bi2 = (const float*)d_in[14];
    const float* Wj1 = (const float*)d_in[15];
    const float* bj1 = (const float*)d_in[16];
    const float* Wj2 = (const float*)d_in[17];
    const float* bj2 = (const float*)d_in[18];

    int N = in_sizes[0] / 8;  if (N > NMAX) N = NMAX;
    int E = in_sizes[1] / 2;  if (E > EMAX) E = EMAX;
    float* out = (float*)d_out;

    cudaFuncSetAttribute(fused_edge_kernel,
                         cudaFuncAttributeMaxDynamicSharedMemorySize, FZ_SMEM);

    int node_blocks = (N * 16 + 255) / 256;
    int edge_blocks = (E + 7) / 8;
    int ntiles      = (E + 255) / 256;
    int fused_grid  = ntiles < 148 ? ntiles : 148;

    w3_split_kernel<<<64, 256>>>(W3);
    w2_split_kernel<<<16, 256>>>(W2);
    init_h_kernel<<<node_blocks, 256>>>(x, N);
    node_init_kernel<<<node_blocks, 256>>>(0, 1, root, bias, N);
    zero_out_kernel<<<1, 32>>>(out);
    fused_edge_kernel<<<fused_grid, 256, FZ_SMEM>>>(edge_attr, W1, b1,
                                                    b2, b3, E, ntiles);
    msg_kernel<<<edge_blocks, 256>>>(0, 1, edge_index, E);

    node_init_kernel<<<node_blocks, 256>>>(1, 2, root, bias, N);
    msg_kernel<<<edge_blocks, 256>>>(1, 2, edge_index, E);
    node_init_kernel<<<node_blocks, 256>>>(2, 1, root, bias, N);
    msg_kernel<<<edge_blocks, 256>>>(2, 1, edge_index, E);

    readout_kernel<<<(N + 7) / 8, 256>>>(1, Wi1, bi1, Wi2, bi2,
                                         Wj1, bj1, Wj2, bj2, out, N);
}

// round 13
// speedup vs baseline: 5.9286x; 1.1124x over previous
#include <cuda_runtime.h>
#include <cuda_bf16.h>
#include <cuda_fp16.h>
#include <math.h>
#include <stdint.h>

// Problem constants (fixed by the dataset)
#define NMAX 100000
#define EMAX 800000

// Scratch (device globals: allocation-free per harness rules)
__device__ __half g_Wedgeh[(size_t)EMAX * 256];     // 409 MB per-edge 16x16 (fp16)
__device__ float  g_h[3][NMAX * 16];                // slot0 = h0, 1/2 ping-pong
__device__ __nv_bfloat16 g_W3b0[256 * 64];          // W3^T limb hi (n-major)
__device__ __nv_bfloat16 g_W3b1[256 * 64];          // W3^T limb lo
__device__ __nv_bfloat16 g_W2b0[64 * 64];           // W2^T limb hi (n-major)
__device__ __nv_bfloat16 g_W2b1[64 * 64];           // W2^T limb lo

// ---------------------------------------------------------------------------
// bf16 helpers (mma.sync m16n8k16 is sm_80+, compiles for plain compute_100)
// ---------------------------------------------------------------------------
__device__ __forceinline__ void mma_bf16(float* c, const uint32_t* a,
                                         uint32_t b0, uint32_t b1) {
    asm volatile(
        "mma.sync.aligned.m16n8k16.row.col.f32.bf16.bf16.f32 "
        "{%0,%1,%2,%3}, {%4,%5,%6,%7}, {%8,%9}, {%0,%1,%2,%3};"
        : "+f"(c[0]), "+f"(c[1]), "+f"(c[2]), "+f"(c[3])
        : "r"(a[0]), "r"(a[1]), "r"(a[2]), "r"(a[3]), "r"(b0), "r"(b1));
}

__device__ __forceinline__ uint32_t pack_bf2(float v0, float v1,
                                             float& r0, float& r1) {
    __nv_bfloat16 h0 = __float2bfloat16(v0);
    __nv_bfloat16 h1 = __float2bfloat16(v1);
    r0 = v0 - __bfloat162float(h0);
    r1 = v1 - __bfloat162float(h1);
    __nv_bfloat162 t = __halves2bfloat162(h0, h1);
    return *reinterpret_cast<uint32_t*>(&t);
}
__device__ __forceinline__ uint32_t pack_bf2_only(float v0, float v1) {
    __nv_bfloat16 h0 = __float2bfloat16(v0);
    __nv_bfloat16 h1 = __float2bfloat16(v1);
    __nv_bfloat162 t = __halves2bfloat162(h0, h1);
    return *reinterpret_cast<uint32_t*>(&t);
}

// Weight splits: W [64, Nout] fp32 row-major -> n-major bf16 limb planes
__global__ void w3_split_kernel(const float* __restrict__ W3)
{
    int idx = blockIdx.x * blockDim.x + threadIdx.x;
    if (idx >= 64 * 256) return;
    int k = idx >> 8, n = idx & 255;
    float v = W3[idx];
    __nv_bfloat16 h = __float2bfloat16(v);
    g_W3b0[n * 64 + k] = h;
    g_W3b1[n * 64 + k] = __float2bfloat16(v - __bfloat162float(h));
}
__global__ void w2_split_kernel(const float* __restrict__ W2)
{
    int idx = blockIdx.x * blockDim.x + threadIdx.x;
    if (idx >= 64 * 64) return;
    int k = idx >> 6, n = idx & 63;
    float v = W2[idx];
    __nv_bfloat16 h = __float2bfloat16(v);
    g_W2b0[n * 64 + k] = h;
    g_W2b1[n * 64 + k] = __float2bfloat16(v - __bfloat162float(h));
}

// ---------------------------------------------------------------------------
// FUSED edge pipeline + FUSED message-pass-1 (256 threads, 8 warps,
// warp = 32 edge rows):
//   stage1 (scalar): e1 = relu(ea@W1+b1) -> warp-private smem bf16 limbs
//   MMA1:  e2 = relu(e1@W2+b2)  -> register fragments (bf16 2-limb)
//   MMA2:  Wedge = e2@W3+b3     -> gmem fp16 (bf16 2-limb, 3 products)
//   EPILOGUE: msg1 = h0[src] @ Wedge accumulated from the SAME register
//             fragments, atomically added into h slot 1 (saves msg1's
//             entire 410 MB Wedge re-read).
// Persistent, grid<=148; only __syncwarp in the tile loop.
// Row stride 36 words: fragment banks 4*qr+tg, conflict-free.
// ---------------------------------------------------------------------------
#define FZ_E1_0   0
#define FZ_E1_1   36864
#define FZ_W2_0   73728
#define FZ_W2_1   82944
#define FZ_W3_0   92160
#define FZ_W3_1   129024
#define FZ_SMEM   165888

__global__ __launch_bounds__(256, 1)
void fused_edge_kernel(const float* __restrict__ edge_attr,
                       const int* __restrict__ edge_index,
                       const float* __restrict__ W1, const float* __restrict__ b1,
                       const float* __restrict__ b2, const float* __restrict__ b3,
                       int E, int ntiles)
{
    extern __shared__ char smem[];
    uint32_t* E1_0 = (uint32_t*)(smem + FZ_E1_0);   // [256][36] words
    uint32_t* E1_1 = (uint32_t*)(smem + FZ_E1_1);
    uint32_t* W2s0 = (uint32_t*)(smem + FZ_W2_0);   // [64][36]
    uint32_t* W2s1 = (uint32_t*)(smem + FZ_W2_1);
    uint32_t* W3s0 = (uint32_t*)(smem + FZ_W3_0);   // [256][36]
    uint32_t* W3s1 = (uint32_t*)(smem + FZ_W3_1);
    __shared__ float W1s[256], b1s[64], b2s[64], b3s[256];

    int tid = threadIdx.x;
    // One-time loads (persistent kernel)
    for (int i = tid; i < 64 * 32; i += 256) {
        int r = i >> 5, w = i & 31;
        W2s0[r * 36 + w] = ((const uint32_t*)g_W2b0)[r * 32 + w];
        W2s1[r * 36 + w] = ((const uint32_t*)g_W2b1)[r * 32 + w];
    }
    for (int i = tid; i < 256 * 32; i += 256) {
        int r = i >> 5, w = i & 31;
        W3s0[r * 36 + w] = ((const uint32_t*)g_W3b0)[r * 32 + w];
        W3s1[r * 36 + w] = ((const uint32_t*)g_W3b1)[r * 32 + w];
    }
    if (tid < 256) { W1s[tid] = W1[tid]; b3s[tid] = b3[tid]; }
    if (tid < 64)  { b1s[tid] = b1[tid]; b2s[tid] = b2[tid]; }
    __syncthreads();

    int lane = tid & 31, wid = tid >> 5;
    int qr = lane >> 2, tg = lane & 3;
    int mrow = wid * 32;                    // warp's 32-row block
    const float4* W1s4 = (const float4*)W1s;
    const float4* b1s4 = (const float4*)b1s;
    const float*  h0g  = g_h[0];
    float*        h1g  = g_h[1];

    for (int t = blockIdx.x; t < ntiles; t += gridDim.x) {
        size_t ebase = (size_t)t * 256;

        // ---- stage 1: thread tid -> edge row tid; warp-private rows ----
        {
            size_t e = ebase + (size_t)tid;
            float4 a = make_float4(0.f, 0.f, 0.f, 0.f);
            float vm = 0.f;
            if (e < (size_t)E) { a = ((const float4*)edge_attr)[e]; vm = 1.f; }
#pragma unroll
            for (int m4 = 0; m4 < 16; ++m4) {
                float4 w0 = W1s4[m4];
                float4 w1 = W1s4[16 + m4];
                float4 w2 = W1s4[32 + m4];
                float4 w3 = W1s4[48 + m4];
                float4 bb = b1s4[m4];
                float v0 = vm * fmaxf(bb.x + a.x*w0.x + a.y*w1.x + a.z*w2.x + a.w*w3.x, 0.f);
                float v1 = vm * fmaxf(bb.y + a.x*w0.y + a.y*w1.y + a.z*w2.y + a.w*w3.y, 0.f);
                float v2 = vm * fmaxf(bb.z + a.x*w0.z + a.y*w1.z + a.z*w2.z + a.w*w3.z, 0.f);
                float v3 = vm * fmaxf(bb.w + a.x*w0.w + a.y*w1.w + a.z*w2.w + a.w*w3.w, 0.f);
                float r0, r1, r2, r3;
                uint32_t h0 = pack_bf2(v0, v1, r0, r1);
                uint32_t h1 = pack_bf2(v2, v3, r2, r3);
                E1_0[tid * 36 + 2 * m4]     = h0;
                E1_0[tid * 36 + 2 * m4 + 1] = h1;
                E1_1[tid * 36 + 2 * m4]     = pack_bf2_only(r0, r1);
                E1_1[tid * 36 + 2 * m4 + 1] = pack_bf2_only(r2, r3);
            }
        }
        __syncwarp();

        // ---- per-lane edge metadata for the 4 fragment rows ----
        // rows: rr=0: mrow+qr, rr=1: +8, rr=2: mrow+16+qr, rr=3: +24
        int srcs[4], dsts[4];
        bool rv[4];
        float pacc[4][4];
#pragma unroll
        for (int rr = 0; rr < 4; ++rr) {
            int row = mrow + (rr >> 1) * 16 + (rr & 1) * 8 + qr;
            size_t e = ebase + (size_t)row;
            rv[rr] = e < (size_t)E;
            srcs[rr] = rv[rr] ? edge_index[2 * e]     : 0;
            dsts[rr] = rv[rr] ? edge_index[2 * e + 1] : 0;
            pacc[rr][0] = 0.f; pacc[rr][1] = 0.f;
            pacc[rr][2] = 0.f; pacc[rr][3] = 0.f;
        }

        // ---- MMA1: e2 = relu(e1 @ W2 + b2), accum in registers ----
        float cc1[2][8][4];
#pragma unroll
        for (int mt = 0; mt < 2; ++mt)
#pragma unroll
            for (int nt = 0; nt < 8; ++nt) {
                cc1[mt][nt][0] = 0.f; cc1[mt][nt][1] = 0.f;
                cc1[mt][nt][2] = 0.f; cc1[mt][nt][3] = 0.f;
            }
#pragma unroll
        for (int ks = 0; ks < 4; ++ks) {
            int kofs = ks * 8 + tg;
            uint32_t a0[2][4], a1[2][4];
#pragma unroll
            for (int mt = 0; mt < 2; ++mt) {
                int r0 = mrow + mt * 16 + qr;
                a0[mt][0] = E1_0[r0 * 36 + kofs];
                a0[mt][1] = E1_0[(r0 + 8) * 36 + kofs];
                a0[mt][2] = E1_0[r0 * 36 + kofs + 4];
                a0[mt][3] = E1_0[(r0 + 8) * 36 + kofs + 4];
                a1[mt][0] = E1_1[r0 * 36 + kofs];
                a1[mt][1] = E1_1[(r0 + 8) * 36 + kofs];
                a1[mt][2] = E1_1[r0 * 36 + kofs + 4];
                a1[mt][3] = E1_1[(r0 + 8) * 36 + kofs + 4];
            }
#pragma unroll
            for (int nt = 0; nt < 8; ++nt) {
                int n = nt * 8 + qr;
                uint32_t b00 = W2s0[n * 36 + kofs];
                uint32_t b01 = W2s0[n * 36 + kofs + 4];
                uint32_t b10 = W2s1[n * 36 + kofs];
                uint32_t b11 = W2s1[n * 36 + kofs + 4];
#pragma unroll
                for (int mt = 0; mt < 2; ++mt) {
                    mma_bf16(cc1[mt][nt], a0[mt], b00, b01);
                    mma_bf16(cc1[mt][nt], a1[mt], b00, b01);
                    mma_bf16(cc1[mt][nt], a0[mt], b10, b11);
                }
            }
        }

        // ---- relu(+b2) and repack C1 fragments as A2 fragments (in regs) ----
        uint32_t a2h[2][4][4], a2l[2][4][4];
#pragma unroll
        for (int mt = 0; mt < 2; ++mt)
#pragma unroll
            for (int nt = 0; nt < 8; ++nt) {
                float bb0 = b2s[nt * 8 + 2 * tg];
                float bb1 = b2s[nt * 8 + 2 * tg + 1];
                float d0 = fmaxf(cc1[mt][nt][0] + bb0, 0.f);
                float d1 = fmaxf(cc1[mt][nt][1] + bb1, 0.f);
                float d2 = fmaxf(cc1[mt][nt][2] + bb0, 0.f);
                float d3 = fmaxf(cc1[mt][nt][3] + bb1, 0.f);
                int ks2 = nt >> 1, q = (nt & 1) * 2;
                float r0, r1, r2, r3;
                a2h[mt][ks2][q]     = pack_bf2(d0, d1, r0, r1);
                a2h[mt][ks2][q + 1] = pack_bf2(d2, d3, r2, r3);
                a2l[mt][ks2][q]     = pack_bf2_only(r0, r1);
                a2l[mt][ks2][q + 1] = pack_bf2_only(r2, r3);
            }

        // ---- MMA2 + msg1 epilogue: n in 4 groups of 64; fp16 store ----
        uint32_t* outw = (uint32_t*)g_Wedgeh;
#pragma unroll
        for (int grp = 0; grp < 4; ++grp) {
            int noff = grp * 64;
            float cc2[2][8][4];
#pragma unroll
            for (int mt = 0; mt < 2; ++mt)
#pragma unroll
                for (int nt = 0; nt < 8; ++nt) {
                    cc2[mt][nt][0] = 0.f; cc2[mt][nt][1] = 0.f;
                    cc2[mt][nt][2] = 0.f; cc2[mt][nt][3] = 0.f;
                }
#pragma unroll
            for (int ks = 0; ks < 4; ++ks) {
                int kofs = ks * 8 + tg;
#pragma unroll
                for (int nt = 0; nt < 8; ++nt) {
                    int n = noff + nt * 8 + qr;
                    uint32_t b00 = W3s0[n * 36 + kofs];
                    uint32_t b01 = W3s0[n * 36 + kofs + 4];
                    uint32_t b10 = W3s1[n * 36 + kofs];
                    uint32_t b11 = W3s1[n * 36 + kofs + 4];
#pragma unroll
                    for (int mt = 0; mt < 2; ++mt) {
                        mma_bf16(cc2[mt][nt], a2h[mt][ks], b00, b01);
                        mma_bf16(cc2[mt][nt], a2l[mt][ks], b00, b01);
                        mma_bf16(cc2[mt][nt], a2h[mt][ks], b10, b11);
                    }
                }
            }

            // h0[src] float4 for this grp (i = 4*grp + nt>>1), per fragment row
            float4 hv[4];
#pragma unroll
            for (int rr = 0; rr < 4; ++rr)
                hv[rr] = rv[rr]
                    ? ((const float4*)(h0g + (size_t)srcs[rr] * 16))[grp]
                    : make_float4(0.f, 0.f, 0.f, 0.f);

            // Store fp16 (+b3) and accumulate msg1 partials
#pragma unroll
            for (int mt = 0; mt < 2; ++mt) {
                size_t e0 = ebase + (size_t)(mrow + mt * 16 + qr);
                size_t e1 = e0 + 8;
                int rr0 = mt * 2, rr1 = mt * 2 + 1;
#pragma unroll
                for (int nt = 0; nt < 8; ++nt) {
                    int n0 = noff + nt * 8 + 2 * tg;
                    float bb0 = b3s[n0], bb1 = b3s[n0 + 1];
                    float w0 = cc2[mt][nt][0] + bb0;
                    float w1 = cc2[mt][nt][1] + bb1;
                    float w2v = cc2[mt][nt][2] + bb0;
                    float w3v = cc2[mt][nt][3] + bb1;
                    int s = (nt & 1) * 2;
                    float hc0 = ((const float*)&hv[rr0])[nt >> 1];
                    float hc1 = ((const float*)&hv[rr1])[nt >> 1];
                    pacc[rr0][s]     += hc0 * w0;
                    pacc[rr0][s + 1] += hc0 * w1;
                    pacc[rr1][s]     += hc1 * w2v;
                    pacc[rr1][s + 1] += hc1 * w3v;
                    if (rv[rr0]) {
                        __half2 hh = __float22half2_rn(make_float2(w0, w1));
                        outw[e0 * 128 + (n0 >> 1)] = *reinterpret_cast<uint32_t*>(&hh);
                    }
                    if (rv[rr1]) {
                        __half2 hh = __float22half2_rn(make_float2(w2v, w3v));
                        outw[e1 * 128 + (n0 >> 1)] = *reinterpret_cast<uint32_t*>(&hh);
                    }
                }
            }
        }

        // ---- flush msg1 partials: o = (s>>1)*8 + (s&1) + 2*tg ----
#pragma unroll
        for (int rr = 0; rr < 4; ++rr) {
            if (!rv[rr]) continue;
            float* dh = h1g + (size_t)dsts[rr] * 16;
            atomicAdd(dh + 2 * tg,     pacc[rr][0]);
            atomicAdd(dh + 2 * tg + 1, pacc[rr][1]);
            atomicAdd(dh + 2 * tg + 8, pacc[rr][2]);
            atomicAdd(dh + 2 * tg + 9, pacc[rr][3]);
        }
    }
}

// ---------------------------------------------------------------------------
// h0 = [x | zeros]
// ---------------------------------------------------------------------------
__global__ void init_h_kernel(const float* __restrict__ x, int N)
{
    int idx = blockIdx.x * blockDim.x + threadIdx.x;
    if (idx >= N * 16) return;
    int n = idx >> 4, i = idx & 15;
    g_h[0][idx] = (i < 8) ? x[n * 8 + i] : 0.f;
}

// h_out = bias + h_in @ root
__global__ void node_init_kernel(int in_slot, int out_slot,
                                 const float* __restrict__ root,
                                 const float* __restrict__ bias, int N)
{
    __shared__ float rs[256];
    __shared__ float bs[16];
    int tid = threadIdx.x;
    if (tid < 256) rs[tid] = root[tid];
    if (tid < 16)  bs[tid] = bias[tid];
    __syncthreads();
    int idx = blockIdx.x * blockDim.x + tid;
    if (idx >= N * 16) return;
    int n = idx >> 4, o = idx & 15;
    const float* hr = g_h[in_slot] + n * 16;
    float acc = bs[o];
#pragma unroll
    for (int i = 0; i < 16; ++i) acc += hr[i] * rs[i * 16 + o];
    g_h[out_slot][idx] = acc;
}

// Message pass: h_out[dst] += h_in[src] @ Wedge[e] (fp16). One warp per edge.
__global__ __launch_bounds__(256)
void msg_kernel(int in_slot, int out_slot, const int* __restrict__ edge_index, int E)
{
    int lane = threadIdx.x & 31;
    int e = (blockIdx.x * 256 + threadIdx.x) >> 5;
    if (e >= E) return;
    int src = edge_index[2 * e];
    int dst = edge_index[2 * e + 1];

    const float* h_in = g_h[in_slot] + (size_t)src * 16;
    float hv = (lane < 16) ? h_in[lane] : 0.f;

    const uint32_t* W = (const uint32_t*)(g_Wedgeh + (size_t)e * 256);
    float p0 = 0.f, p1 = 0.f;
    int ib = lane >> 3;
#pragma unroll
    for (int j = 0; j < 4; ++j) {
        uint32_t wv = W[lane + 32 * j];
        __half2 h2 = *reinterpret_cast<__half2*>(&wv);
        float2 wf = __half22float2(h2);
        float hk = __shfl_sync(0xffffffffu, hv, ib + 4 * j);
        p0 += hk * wf.x;
        p1 += hk * wf.y;
    }
    p0 += __shfl_xor_sync(0xffffffffu, p0, 8);
    p1 += __shfl_xor_sync(0xffffffffu, p1, 8);
    p0 += __shfl_xor_sync(0xffffffffu, p0, 16);
    p1 += __shfl_xor_sync(0xffffffffu, p1, 16);
    if (lane < 8) {
        float* dsth = &g_h[out_slot][(size_t)dst * 16 + 2 * lane];
        atomicAdd(dsth, p0);
        atomicAdd(dsth + 1, p1);
    }
}

// ---------------------------------------------------------------------------
// Readout
// ---------------------------------------------------------------------------
__global__ void zero_out_kernel(float* out)
{
    if (threadIdx.x == 0 && blockIdx.x == 0) out[0] = 0.f;
}

__global__ __launch_bounds__(256)
void readout_kernel(int h_slot,
                    const float* __restrict__ Wi1, const float* __restrict__ bi1,
                    const float* __restrict__ Wi2, const float* __restrict__ bi2,
                    const float* __restrict__ Wj1, const float* __restrict__ bj1,
                    const float* __restrict__ Wj2, const float* __restrict__ bj2,
                    float* __restrict__ out, int N)
{
    __shared__ float Wi1s[4096], Wj1s[2048];
    __shared__ float bi1s[128], bj1s[128], Wi2s[128], Wj2s[128];
    __shared__ float warpsum[8];

    int tid = threadIdx.x;
    for (int i = tid; i < 4096; i += 256) Wi1s[i] = Wi1[i];
    for (int i = tid; i < 2048; i += 256) Wj1s[i] = Wj1[i];
    if (tid < 128) {
        bi1s[tid] = bi1[tid]; bj1s[tid] = bj1[tid];
        Wi2s[tid] = Wi2[tid]; Wj2s[tid] = Wj2[tid];
    }
    __syncthreads();

    int lane = tid & 31, w = tid >> 5;
    int n = blockIdx.x * 8 + w;
    float contrib = 0.f;

    if (n < N) {
        const float* h  = g_h[h_slot] + n * 16;
        const float* h0 = g_h[0] + n * 16;
        float hv  = (lane < 16) ? h[lane]  : 0.f;
        float h0v = (lane < 16) ? h0[lane] : 0.f;

        float a0 = bi1s[lane], a1 = bi1s[lane + 32], a2 = bi1s[lane + 64], a3 = bi1s[lane + 96];
#pragma unroll
        for (int c = 0; c < 32; ++c) {
            float cc = __shfl_sync(0xffffffffu, (c < 16) ? hv : h0v, c & 15);
            a0 += cc * Wi1s[c * 128 + lane];
            a1 += cc * Wi1s[c * 128 + lane + 32];
            a2 += cc * Wi1s[c * 128 + lane + 64];
            a3 += cc * Wi1s[c * 128 + lane + 96];
        }
        a0 = fmaxf(a0, 0.f); a1 = fmaxf(a1, 0.f); a2 = fmaxf(a2, 0.f); a3 = fmaxf(a3, 0.f);
        float g = a0 * Wi2s[lane] + a1 * Wi2s[lane + 32] + a2 * Wi2s[lane + 64] + a3 * Wi2s[lane + 96];

        float v0 = bj1s[lane], v1 = bj1s[lane + 32], v2 = bj1s[lane + 64], v3 = bj1s[lane + 96];
#pragma unroll
        for (int c = 0; c < 16; ++c) {
            float cc = __shfl_sync(0xffffffffu, hv, c);
            v0 += cc * Wj1s[c * 128 + lane];
            v1 += cc * Wj1s[c * 128 + lane + 32];
            v2 += cc * Wj1s[c * 128 + lane + 64];
            v3 += cc * Wj1s[c * 128 + lane + 96];
        }
        v0 = fmaxf(v0, 0.f); v1 = fmaxf(v1, 0.f); v2 = fmaxf(v2, 0.f); v3 = fmaxf(v3, 0.f);
        float vv = v0 * Wj2s[lane] + v1 * Wj2s[lane + 32] + v2 * Wj2s[lane + 64] + v3 * Wj2s[lane + 96];

#pragma unroll
        for (int s = 16; s > 0; s >>= 1) {
            g  += __shfl_xor_sync(0xffffffffu, g, s);
            vv += __shfl_xor_sync(0xffffffffu, vv, s);
        }
        if (lane == 0) {
            float gate = 1.f / (1.f + expf(-(g + bi2[0])));
            contrib = gate * (vv + bj2[0]);
        }
    }
    if (lane == 0) warpsum[w] = contrib;
    __syncthreads();
    if (tid == 0) {
        float s = 0.f;
#pragma unroll
        for (int i = 0; i < 8; ++i) s += warpsum[i];
        atomicAdd(out, s);
    }
}

// ===========================================================================
extern "C" void kernel_launch(void* const* d_in, const int* in_sizes, int n_in,
                              void* d_out, int out_size)
{
    const float* x          = (const float*)d_in[0];
    const int*   edge_index = (const int*)  d_in[1];
    const float* edge_attr  = (const float*)d_in[2];
    const float* W1  = (const float*)d_in[3];
    const float* b1  = (const float*)d_in[4];
    const float* W2  = (const float*)d_in[5];
    const float* b2  = (const float*)d_in[6];
    const float* W3  = (const float*)d_in[7];
    const float* b3  = (const float*)d_in[8];
    const float* root = (const float*)d_in[9];
    const float* bias = (const float*)d_in[10];
    const float* Wi1 = (const float*)d_in[11];
    const float* bi1 = (const float*)d_in[12];
    const float* Wi2 = (const float*)d_in[13];
    const float* bi2 = (const float*)d_in[14];
    const float* Wj1 = (const float*)d_in[15];
    const float* bj1 = (const float*)d_in[16];
    const float* Wj2 = (const float*)d_in[17];
    const float* bj2 = (const float*)d_in[18];

    int N = in_sizes[0] / 8;  if (N > NMAX) N = NMAX;
    int E = in_sizes[1] / 2;  if (E > EMAX) E = EMAX;
    float* out = (float*)d_out;

    cudaFuncSetAttribute(fused_edge_kernel,
                         cudaFuncAttributeMaxDynamicSharedMemorySize, FZ_SMEM);

    int node_blocks = (N * 16 + 255) / 256;
    int edge_blocks = (E + 7) / 8;
    int ntiles      = (E + 255) / 256;
    int fused_grid  = ntiles < 148 ? ntiles : 148;

    w3_split_kernel<<<64, 256>>>(W3);
    w2_split_kernel<<<16, 256>>>(W2);
    init_h_kernel<<<node_blocks, 256>>>(x, N);
    node_init_kernel<<<node_blocks, 256>>>(0, 1, root, bias, N);
    zero_out_kernel<<<1, 32>>>(out);

    // Fused: edge MLP + Wedge store + message pass 1 (0 -> 1)
    fused_edge_kernel<<<fused_grid, 256, FZ_SMEM>>>(edge_attr, edge_index,
                                                    W1, b1, b2, b3, E, ntiles);

    // Passes 2 and 3
    node_init_kernel<<<node_blocks, 256>>>(1, 2, root, bias, N);
    msg_kernel<<<edge_blocks, 256>>>(1, 2, edge_index, E);
    node_init_kernel<<<node_blocks, 256>>>(2, 1, root, bias, N);
    msg_kernel<<<edge_blocks, 256>>>(2, 1, edge_index, E);

    readout_kernel<<<(N + 7) / 8, 256>>>(1, Wi1, bi1, Wi2, bi2,
                                         Wj1, bj1, Wj2, bj2, out, N);
}

// round 14
// speedup vs baseline: 6.2608x; 1.0560x over previous
#include <cuda_runtime.h>
#include <cuda_bf16.h>
#include <cuda_fp16.h>
#include <math.h>
#include <stdint.h>

// Problem constants (fixed by the dataset)
#define NMAX 100000
#define EMAX 800000

// Scratch (device globals: allocation-free per harness rules)
__device__ __half g_Wedgeh[(size_t)EMAX * 256];     // 409 MB per-edge 16x16 (fp16)
__device__ float  g_h[3][NMAX * 16];                // slot0 = h0, 1/2 ping-pong
__device__ __half g_W3h0[256 * 64];                 // W3^T fp16 limb hi (n-major)
__device__ __half g_W3h1[256 * 64];                 // W3^T fp16 limb lo
__device__ __nv_bfloat16 g_W2b0[64 * 64];           // W2^T bf16 limb hi (n-major)
__device__ __nv_bfloat16 g_W2b1[64 * 64];           // W2^T bf16 limb lo

// ---------------------------------------------------------------------------
// mma helpers (m16n8k16, sm_80+, compiles for plain compute_100)
// ---------------------------------------------------------------------------
__device__ __forceinline__ void mma_bf16(float* c, const uint32_t* a,
                                         uint32_t b0, uint32_t b1) {
    asm volatile(
        "mma.sync.aligned.m16n8k16.row.col.f32.bf16.bf16.f32 "
        "{%0,%1,%2,%3}, {%4,%5,%6,%7}, {%8,%9}, {%0,%1,%2,%3};"
        : "+f"(c[0]), "+f"(c[1]), "+f"(c[2]), "+f"(c[3])
        : "r"(a[0]), "r"(a[1]), "r"(a[2]), "r"(a[3]), "r"(b0), "r"(b1));
}
__device__ __forceinline__ void mma_f16(float* c, const uint32_t* a,
                                        uint32_t b0, uint32_t b1) {
    asm volatile(
        "mma.sync.aligned.m16n8k16.row.col.f32.f16.f16.f32 "
        "{%0,%1,%2,%3}, {%4,%5,%6,%7}, {%8,%9}, {%0,%1,%2,%3};"
        : "+f"(c[0]), "+f"(c[1]), "+f"(c[2]), "+f"(c[3])
        : "r"(a[0]), "r"(a[1]), "r"(a[2]), "r"(a[3]), "r"(b0), "r"(b1));
}

__device__ __forceinline__ uint32_t pack_bf2(float v0, float v1,
                                             float& r0, float& r1) {
    __nv_bfloat16 h0 = __float2bfloat16(v0);
    __nv_bfloat16 h1 = __float2bfloat16(v1);
    r0 = v0 - __bfloat162float(h0);
    r1 = v1 - __bfloat162float(h1);
    __nv_bfloat162 t = __halves2bfloat162(h0, h1);
    return *reinterpret_cast<uint32_t*>(&t);
}
__device__ __forceinline__ uint32_t pack_bf2_only(float v0, float v1) {
    __nv_bfloat16 h0 = __float2bfloat16(v0);
    __nv_bfloat16 h1 = __float2bfloat16(v1);
    __nv_bfloat162 t = __halves2bfloat162(h0, h1);
    return *reinterpret_cast<uint32_t*>(&t);
}
__device__ __forceinline__ uint32_t pack_h2(float v0, float v1) {
    __half2 t = __floats2half2_rn(v0, v1);
    return *reinterpret_cast<uint32_t*>(&t);
}

// W3 [64,256] fp32 -> n-major fp16 limb planes (hi, lo)
__global__ void w3_split_kernel(const float* __restrict__ W3)
{
    int idx = blockIdx.x * blockDim.x + threadIdx.x;
    if (idx >= 64 * 256) return;
    int k = idx >> 8, n = idx & 255;
    float v = W3[idx];
    __half h = __float2half_rn(v);
    g_W3h0[n * 64 + k] = h;
    g_W3h1[n * 64 + k] = __float2half_rn(v - __half2float(h));
}
// W2 [64,64] fp32 -> n-major bf16 limb planes
__global__ void w2_split_kernel(const float* __restrict__ W2)
{
    int idx = blockIdx.x * blockDim.x + threadIdx.x;
    if (idx >= 64 * 64) return;
    int k = idx >> 6, n = idx & 63;
    float v = W2[idx];
    __nv_bfloat16 h = __float2bfloat16(v);
    g_W2b0[n * 64 + k] = h;
    g_W2b1[n * 64 + k] = __float2bfloat16(v - __bfloat162float(h));
}

// ---------------------------------------------------------------------------
// FUSED edge pipeline + message-pass-1 (256 threads, 8 warps, warp = 32 rows)
//   stage1 (scalar): e1 = relu(ea@W1+b1) -> warp-private smem bf16 limbs
//   MMA1 (bf16, 3 products): e2 = relu(e1@W2+b2) -> register fragments
//   MMA2 (fp16, 2 products: a_hi*(b_hi+b_lo)): Wedge = e2@W3+b3 -> gmem fp16
//   EPILOGUE: msg1 = h0[src]@Wedge accumulated from register fragments.
// Persistent, grid<=148; only __syncwarp in the tile loop.
// ---------------------------------------------------------------------------
#define FZ_E1_0   0
#define FZ_E1_1   36864
#define FZ_W2_0   73728
#define FZ_W2_1   82944
#define FZ_W3_0   92160
#define FZ_W3_1   129024
#define FZ_SMEM   165888

__global__ __launch_bounds__(256, 1)
void fused_edge_kernel(const float* __restrict__ edge_attr,
                       const int* __restrict__ edge_index,
                       const float* __restrict__ W1, const float* __restrict__ b1,
                       const float* __restrict__ b2, const float* __restrict__ b3,
                       int E, int ntiles)
{
    extern __shared__ char smem[];
    uint32_t* E1_0 = (uint32_t*)(smem + FZ_E1_0);   // [256][36] words (bf16x2)
    uint32_t* E1_1 = (uint32_t*)(smem + FZ_E1_1);
    uint32_t* W2s0 = (uint32_t*)(smem + FZ_W2_0);   // [64][36]  (bf16x2)
    uint32_t* W2s1 = (uint32_t*)(smem + FZ_W2_1);
    uint32_t* W3s0 = (uint32_t*)(smem + FZ_W3_0);   // [256][36] (fp16x2)
    uint32_t* W3s1 = (uint32_t*)(smem + FZ_W3_1);
    __shared__ float W1s[256], b1s[64], b2s[64], b3s[256];

    int tid = threadIdx.x;
    // One-time loads (persistent kernel)
    for (int i = tid; i < 64 * 32; i += 256) {
        int r = i >> 5, w = i & 31;
        W2s0[r * 36 + w] = ((const uint32_t*)g_W2b0)[r * 32 + w];
        W2s1[r * 36 + w] = ((const uint32_t*)g_W2b1)[r * 32 + w];
    }
    for (int i = tid; i < 256 * 32; i += 256) {
        int r = i >> 5, w = i & 31;
        W3s0[r * 36 + w] = ((const uint32_t*)g_W3h0)[r * 32 + w];
        W3s1[r * 36 + w] = ((const uint32_t*)g_W3h1)[r * 32 + w];
    }
    if (tid < 256) { W1s[tid] = W1[tid]; b3s[tid] = b3[tid]; }
    if (tid < 64)  { b1s[tid] = b1[tid]; b2s[tid] = b2[tid]; }
    __syncthreads();

    int lane = tid & 31, wid = tid >> 5;
    int qr = lane >> 2, tg = lane & 3;
    int mrow = wid * 32;                    // warp's 32-row block
    const float4* W1s4 = (const float4*)W1s;
    const float4* b1s4 = (const float4*)b1s;
    const float*  h0g  = g_h[0];
    float*        h1g  = g_h[1];

    for (int t = blockIdx.x; t < ntiles; t += gridDim.x) {
        size_t ebase = (size_t)t * 256;

        // ---- stage 1: thread tid -> edge row tid; warp-private rows ----
        {
            size_t e = ebase + (size_t)tid;
            float4 a = make_float4(0.f, 0.f, 0.f, 0.f);
            float vm = 0.f;
            if (e < (size_t)E) { a = ((const float4*)edge_attr)[e]; vm = 1.f; }
#pragma unroll
            for (int m4 = 0; m4 < 16; ++m4) {
                float4 w0 = W1s4[m4];
                float4 w1 = W1s4[16 + m4];
                float4 w2 = W1s4[32 + m4];
                float4 w3 = W1s4[48 + m4];
                float4 bb = b1s4[m4];
                float v0 = vm * fmaxf(bb.x + a.x*w0.x + a.y*w1.x + a.z*w2.x + a.w*w3.x, 0.f);
                float v1 = vm * fmaxf(bb.y + a.x*w0.y + a.y*w1.y + a.z*w2.y + a.w*w3.y, 0.f);
                float v2 = vm * fmaxf(bb.z + a.x*w0.z + a.y*w1.z + a.z*w2.z + a.w*w3.z, 0.f);
                float v3 = vm * fmaxf(bb.w + a.x*w0.w + a.y*w1.w + a.z*w2.w + a.w*w3.w, 0.f);
                float r0, r1, r2, r3;
                uint32_t h0 = pack_bf2(v0, v1, r0, r1);
                uint32_t h1 = pack_bf2(v2, v3, r2, r3);
                E1_0[tid * 36 + 2 * m4]     = h0;
                E1_0[tid * 36 + 2 * m4 + 1] = h1;
                E1_1[tid * 36 + 2 * m4]     = pack_bf2_only(r0, r1);
                E1_1[tid * 36 + 2 * m4 + 1] = pack_bf2_only(r2, r3);
            }
        }
        __syncwarp();

        // ---- per-lane edge metadata for the 4 fragment rows ----
        int srcs[4], dsts[4];
        bool rv[4];
        float pacc[4][4];
#pragma unroll
        for (int rr = 0; rr < 4; ++rr) {
            int row = mrow + (rr >> 1) * 16 + (rr & 1) * 8 + qr;
            size_t e = ebase + (size_t)row;
            rv[rr] = e < (size_t)E;
            srcs[rr] = rv[rr] ? edge_index[2 * e]     : 0;
            dsts[rr] = rv[rr] ? edge_index[2 * e + 1] : 0;
            pacc[rr][0] = 0.f; pacc[rr][1] = 0.f;
            pacc[rr][2] = 0.f; pacc[rr][3] = 0.f;
        }

        // ---- MMA1: e2 = relu(e1 @ W2 + b2), bf16 2-limb 3-product ----
        float cc1[2][8][4];
#pragma unroll
        for (int mt = 0; mt < 2; ++mt)
#pragma unroll
            for (int nt = 0; nt < 8; ++nt) {
                cc1[mt][nt][0] = 0.f; cc1[mt][nt][1] = 0.f;
                cc1[mt][nt][2] = 0.f; cc1[mt][nt][3] = 0.f;
            }
#pragma unroll
        for (int ks = 0; ks < 4; ++ks) {
            int kofs = ks * 8 + tg;
            uint32_t a0[2][4], a1[2][4];
#pragma unroll
            for (int mt = 0; mt < 2; ++mt) {
                int r0 = mrow + mt * 16 + qr;
                a0[mt][0] = E1_0[r0 * 36 + kofs];
                a0[mt][1] = E1_0[(r0 + 8) * 36 + kofs];
                a0[mt][2] = E1_0[r0 * 36 + kofs + 4];
                a0[mt][3] = E1_0[(r0 + 8) * 36 + kofs + 4];
                a1[mt][0] = E1_1[r0 * 36 + kofs];
                a1[mt][1] = E1_1[(r0 + 8) * 36 + kofs];
                a1[mt][2] = E1_1[r0 * 36 + kofs + 4];
                a1[mt][3] = E1_1[(r0 + 8) * 36 + kofs + 4];
            }
#pragma unroll
            for (int nt = 0; nt < 8; ++nt) {
                int n = nt * 8 + qr;
                uint32_t b00 = W2s0[n * 36 + kofs];
                uint32_t b01 = W2s0[n * 36 + kofs + 4];
                uint32_t b10 = W2s1[n * 36 + kofs];
                uint32_t b11 = W2s1[n * 36 + kofs + 4];
#pragma unroll
                for (int mt = 0; mt < 2; ++mt) {
                    mma_bf16(cc1[mt][nt], a0[mt], b00, b01);
                    mma_bf16(cc1[mt][nt], a1[mt], b00, b01);
                    mma_bf16(cc1[mt][nt], a0[mt], b10, b11);
                }
            }
        }

        // ---- relu(+b2) and repack C1 fragments as fp16 A2 fragments ----
        uint32_t a2h[2][4][4];
#pragma unroll
        for (int mt = 0; mt < 2; ++mt)
#pragma unroll
            for (int nt = 0; nt < 8; ++nt) {
                float bb0 = b2s[nt * 8 + 2 * tg];
                float bb1 = b2s[nt * 8 + 2 * tg + 1];
                float d0 = fmaxf(cc1[mt][nt][0] + bb0, 0.f);
                float d1 = fmaxf(cc1[mt][nt][1] + bb1, 0.f);
                float d2 = fmaxf(cc1[mt][nt][2] + bb0, 0.f);
                float d3 = fmaxf(cc1[mt][nt][3] + bb1, 0.f);
                int ks2 = nt >> 1, q = (nt & 1) * 2;
                a2h[mt][ks2][q]     = pack_h2(d0, d1);
                a2h[mt][ks2][q + 1] = pack_h2(d2, d3);
            }

        // ---- MMA2 (fp16, a_hi*(b_hi+b_lo)) + msg1 epilogue ----
        uint32_t* outw = (uint32_t*)g_Wedgeh;
#pragma unroll
        for (int grp = 0; grp < 4; ++grp) {
            int noff = grp * 64;
            float cc2[2][8][4];
#pragma unroll
            for (int mt = 0; mt < 2; ++mt)
#pragma unroll
                for (int nt = 0; nt < 8; ++nt) {
                    cc2[mt][nt][0] = 0.f; cc2[mt][nt][1] = 0.f;
                    cc2[mt][nt][2] = 0.f; cc2[mt][nt][3] = 0.f;
                }
#pragma unroll
            for (int ks = 0; ks < 4; ++ks) {
                int kofs = ks * 8 + tg;
#pragma unroll
                for (int nt = 0; nt < 8; ++nt) {
                    int n = noff + nt * 8 + qr;
                    uint32_t b00 = W3s0[n * 36 + kofs];
                    uint32_t b01 = W3s0[n * 36 + kofs + 4];
                    uint32_t b10 = W3s1[n * 36 + kofs];
                    uint32_t b11 = W3s1[n * 36 + kofs + 4];
#pragma unroll
                    for (int mt = 0; mt < 2; ++mt) {
                        mma_f16(cc2[mt][nt], a2h[mt][ks], b00, b01);
                        mma_f16(cc2[mt][nt], a2h[mt][ks], b10, b11);
                    }
                }
            }

            // h0[src] float4 for this grp (i = 4*grp + nt>>1), per fragment row
            float4 hv[4];
#pragma unroll
            for (int rr = 0; rr < 4; ++rr)
                hv[rr] = rv[rr]
                    ? ((const float4*)(h0g + (size_t)srcs[rr] * 16))[grp]
                    : make_float4(0.f, 0.f, 0.f, 0.f);

            // Store fp16 (+b3) and accumulate msg1 partials
#pragma unroll
            for (int mt = 0; mt < 2; ++mt) {
                size_t e0 = ebase + (size_t)(mrow + mt * 16 + qr);
                size_t e1 = e0 + 8;
                int rr0 = mt * 2, rr1 = mt * 2 + 1;
#pragma unroll
                for (int nt = 0; nt < 8; ++nt) {
                    int n0 = noff + nt * 8 + 2 * tg;
                    float bb0 = b3s[n0], bb1 = b3s[n0 + 1];
                    float w0 = cc2[mt][nt][0] + bb0;
                    float w1 = cc2[mt][nt][1] + bb1;
                    float w2v = cc2[mt][nt][2] + bb0;
                    float w3v = cc2[mt][nt][3] + bb1;
                    int s = (nt & 1) * 2;
                    float hc0 = ((const float*)&hv[rr0])[nt >> 1];
                    float hc1 = ((const float*)&hv[rr1])[nt >> 1];
                    pacc[rr0][s]     += hc0 * w0;
                    pacc[rr0][s + 1] += hc0 * w1;
                    pacc[rr1][s]     += hc1 * w2v;
                    pacc[rr1][s + 1] += hc1 * w3v;
                    if (rv[rr0]) {
                        __half2 hh = __float22half2_rn(make_float2(w0, w1));
                        outw[e0 * 128 + (n0 >> 1)] = *reinterpret_cast<uint32_t*>(&hh);
                    }
                    if (rv[rr1]) {
                        __half2 hh = __float22half2_rn(make_float2(w2v, w3v));
                        outw[e1 * 128 + (n0 >> 1)] = *reinterpret_cast<uint32_t*>(&hh);
                    }
                }
            }
        }

        // ---- flush msg1 partials: o = (s>>1)*8 + (s&1) + 2*tg ----
#pragma unroll
        for (int rr = 0; rr < 4; ++rr) {
            if (!rv[rr]) continue;
            float* dh = h1g + (size_t)dsts[rr] * 16;
            atomicAdd(dh + 2 * tg,     pacc[rr][0]);
            atomicAdd(dh + 2 * tg + 1, pacc[rr][1]);
            atomicAdd(dh + 2 * tg + 8, pacc[rr][2]);
            atomicAdd(dh + 2 * tg + 9, pacc[rr][3]);
        }
    }
}

// ---------------------------------------------------------------------------
// h0 = [x | zeros]
// ---------------------------------------------------------------------------
__global__ void init_h_kernel(const float* __restrict__ x, int N)
{
    int idx = blockIdx.x * blockDim.x + threadIdx.x;
    if (idx >= N * 16) return;
    int n = idx >> 4, i = idx & 15;
    g_h[0][idx] = (i < 8) ? x[n * 8 + i] : 0.f;
}

// h_out = bias + h_in @ root
__global__ void node_init_kernel(int in_slot, int out_slot,
                                 const float* __restrict__ root,
                                 const float* __restrict__ bias, int N)
{
    __shared__ float rs[256];
    __shared__ float bs[16];
    int tid = threadIdx.x;
    if (tid < 256) rs[tid] = root[tid];
    if (tid < 16)  bs[tid] = bias[tid];
    __syncthreads();
    int idx = blockIdx.x * blockDim.x + tid;
    if (idx >= N * 16) return;
    int n = idx >> 4, o = idx & 15;
    const float* hr = g_h[in_slot] + n * 16;
    float acc = bs[o];
#pragma unroll
    for (int i = 0; i < 16; ++i) acc += hr[i] * rs[i * 16 + o];
    g_h[out_slot][idx] = acc;
}

// Message pass: h_out[dst] += h_in[src] @ Wedge[e] (fp16). One warp per edge.
__global__ __launch_bounds__(256)
void msg_kernel(int in_slot, int out_slot, const int* __restrict__ edge_index, int E)
{
    int lane = threadIdx.x & 31;
    int e = (blockIdx.x * 256 + threadIdx.x) >> 5;
    if (e >= E) return;
    int src = edge_index[2 * e];
    int dst = edge_index[2 * e + 1];

    const float* h_in = g_h[in_slot] + (size_t)src * 16;
    float hv = (lane < 16) ? h_in[lane] : 0.f;

    const uint32_t* W = (const uint32_t*)(g_Wedgeh + (size_t)e * 256);
    float p0 = 0.f, p1 = 0.f;
    int ib = lane >> 3;
#pragma unroll
    for (int j = 0; j < 4; ++j) {
        uint32_t wv = W[lane + 32 * j];
        __half2 h2 = *reinterpret_cast<__half2*>(&wv);
        float2 wf = __half22float2(h2);
        float hk = __shfl_sync(0xffffffffu, hv, ib + 4 * j);
        p0 += hk * wf.x;
        p1 += hk * wf.y;
    }
    p0 += __shfl_xor_sync(0xffffffffu, p0, 8);
    p1 += __shfl_xor_sync(0xffffffffu, p1, 8);
    p0 += __shfl_xor_sync(0xffffffffu, p0, 16);
    p1 += __shfl_xor_sync(0xffffffffu, p1, 16);
    if (lane < 8) {
        float* dsth = &g_h[out_slot][(size_t)dst * 16 + 2 * lane];
        atomicAdd(dsth, p0);
        atomicAdd(dsth + 1, p1);
    }
}

// ---------------------------------------------------------------------------
// Readout
// ---------------------------------------------------------------------------
__global__ void zero_out_kernel(float* out)
{
    if (threadIdx.x == 0 && blockIdx.x == 0) out[0] = 0.f;
}

__global__ __launch_bounds__(256)
void readout_kernel(int h_slot,
                    const float* __restrict__ Wi1, const float* __restrict__ bi1,
                    const float* __restrict__ Wi2, const float* __restrict__ bi2,
                    const float* __restrict__ Wj1, const float* __restrict__ bj1,
                    const float* __restrict__ Wj2, const float* __restrict__ bj2,
                    float* __restrict__ out, int N)
{
    __shared__ float Wi1s[4096], Wj1s[2048];
    __shared__ float bi1s[128], bj1s[128], Wi2s[128], Wj2s[128];
    __shared__ float warpsum[8];

    int tid = threadIdx.x;
    for (int i = tid; i < 4096; i += 256) Wi1s[i] = Wi1[i];
    for (int i = tid; i < 2048; i += 256) Wj1s[i] = Wj1[i];
    if (tid < 128) {
        bi1s[tid] = bi1[tid]; bj1s[tid] = bj1[tid];
        Wi2s[tid] = Wi2[tid]; Wj2s[tid] = Wj2[tid];
    }
    __syncthreads();

    int lane = tid & 31, w = tid >> 5;
    int n = blockIdx.x * 8 + w;
    float contrib = 0.f;

    if (n < N) {
        const float* h  = g_h[h_slot] + n * 16;
        const float* h0 = g_h[0] + n * 16;
        float hv  = (lane < 16) ? h[lane]  : 0.f;
        float h0v = (lane < 16) ? h0[lane] : 0.f;

        float a0 = bi1s[lane], a1 = bi1s[lane + 32], a2 = bi1s[lane + 64], a3 = bi1s[lane + 96];
#pragma unroll
        for (int c = 0; c < 32; ++c) {
            float cc = __shfl_sync(0xffffffffu, (c < 16) ? hv : h0v, c & 15);
            a0 += cc * Wi1s[c * 128 + lane];
            a1 += cc * Wi1s[c * 128 + lane + 32];
            a2 += cc * Wi1s[c * 128 + lane + 64];
            a3 += cc * Wi1s[c * 128 + lane + 96];
        }
        a0 = fmaxf(a0, 0.f); a1 = fmaxf(a1, 0.f); a2 = fmaxf(a2, 0.f); a3 = fmaxf(a3, 0.f);
        float g = a0 * Wi2s[lane] + a1 * Wi2s[lane + 32] + a2 * Wi2s[lane + 64] + a3 * Wi2s[lane + 96];

        float v0 = bj1s[lane], v1 = bj1s[lane + 32], v2 = bj1s[lane + 64], v3 = bj1s[lane + 96];
#pragma unroll
        for (int c = 0; c < 16; ++c) {
            float cc = __shfl_sync(0xffffffffu, hv, c);
            v0 += cc * Wj1s[c * 128 + lane];
            v1 += cc * Wj1s[c * 128 + lane + 32];
            v2 += cc * Wj1s[c * 128 + lane + 64];
            v3 += cc * Wj1s[c * 128 + lane + 96];
        }
        v0 = fmaxf(v0, 0.f); v1 = fmaxf(v1, 0.f); v2 = fmaxf(v2, 0.f); v3 = fmaxf(v3, 0.f);
        float vv = v0 * Wj2s[lane] + v1 * Wj2s[lane + 32] + v2 * Wj2s[lane + 64] + v3 * Wj2s[lane + 96];

#pragma unroll
        for (int s = 16; s > 0; s >>= 1) {
            g  += __shfl_xor_sync(0xffffffffu, g, s);
            vv += __shfl_xor_sync(0xffffffffu, vv, s);
        }
        if (lane == 0) {
            float gate = 1.f / (1.f + expf(-(g + bi2[0])));
            contrib = gate * (vv + bj2[0]);
        }
    }
    if (lane == 0) warpsum[w] = contrib;
    __syncthreads();
    if (tid == 0) {
        float s = 0.f;
#pragma unroll
        for (int i = 0; i < 8; ++i) s += warpsum[i];
        atomicAdd(out, s);
    }
}

// ===========================================================================
extern "C" void kernel_launch(void* const* d_in, const int* in_sizes, int n_in,
                              void* d_out, int out_size)
{
    const float* x          = (const float*)d_in[0];
    const int*   edge_index = (const int*)  d_in[1];
    const float* edge_attr  = (const float*)d_in[2];
    const float* W1  = (const float*)d_in[3];
    const float* b1  = (const float*)d_in[4];
    const float* W2  = (const float*)d_in[5];
    const float* b2  = (const float*)d_in[6];
    const float* W3  = (const float*)d_in[7];
    const float* b3  = (const float*)d_in[8];
    const float* root = (const float*)d_in[9];
    const float* bias = (const float*)d_in[10];
    const float* Wi1 = (const float*)d_in[11];
    const float* bi1 = (const float*)d_in[12];
    const float* Wi2 = (const float*)d_in[13];
    const float* bi2 = (const float*)d_in[14];
    const float* Wj1 = (const float*)d_in[15];
    const float* bj1 = (const float*)d_in[16];
    const float* Wj2 = (const float*)d_in[17];
    const float* bj2 = (const float*)d_in[18];

    int N = in_sizes[0] / 8;  if (N > NMAX) N = NMAX;
    int E = in_sizes[1] / 2;  if (E > EMAX) E = EMAX;
    float* out = (float*)d_out;

    cudaFuncSetAttribute(fused_edge_kernel,
                         cudaFuncAttributeMaxDynamicSharedMemorySize, FZ_SMEM);

    int node_blocks = (N * 16 + 255) / 256;
    int edge_blocks = (E + 7) / 8;
    int ntiles      = (E + 255) / 256;
    int fused_grid  = ntiles < 148 ? ntiles : 148;

    w3_split_kernel<<<64, 256>>>(W3);
    w2_split_kernel<<<16, 256>>>(W2);
    init_h_kernel<<<node_blocks, 256>>>(x, N);
    node_init_kernel<<<node_blocks, 256>>>(0, 1, root, bias, N);
    zero_out_kernel<<<1, 32>>>(out);

    // Fused: edge MLP + Wedge store + message pass 1 (0 -> 1)
    fused_edge_kernel<<<fused_grid, 256, FZ_SMEM>>>(edge_attr, edge_index,
                                                    W1, b1, b2, b3, E, ntiles);

    // Passes 2 and 3
    node_init_kernel<<<node_blocks, 256>>>(1, 2, root, bias, N);
    msg_kernel<<<edge_blocks, 256>>>(1, 2, edge_index, E);
    node_init_kernel<<<node_blocks, 256>>>(2, 1, root, bias, N);
    msg_kernel<<<edge_blocks, 256>>>(2, 1, edge_index, E);

    readout_kernel<<<(N + 7) / 8, 256>>>(1, Wi1, bi1, Wi2, bi2,
                                         Wj1, bj1, Wj2, bj2, out, N);
}

// round 15
// speedup vs baseline: 6.4994x; 1.0381x over previous
#include <cuda_runtime.h>
#include <cuda_bf16.h>
#include <cuda_fp16.h>
#include <math.h>
#include <stdint.h>

// Problem constants (fixed by the dataset)
#define NMAX 100000
#define EMAX 800000

// Scratch (device globals: allocation-free per harness rules)
__device__ __half g_Wedgeh[(size_t)EMAX * 256];     // 409 MB per-edge 16x16 (fp16)
__device__ float  g_h[3][NMAX * 16];                // slot0 = h0, 1/2 ping-pong
__device__ __half g_W3h0[256 * 64];                 // W3^T fp16 limb hi (n-major)
__device__ __half g_W3h1[256 * 64];                 // W3^T fp16 limb lo
__device__ __nv_bfloat16 g_W2b0[64 * 64];           // W2^T bf16 limb hi (n-major)
__device__ __nv_bfloat16 g_W2b1[64 * 64];           // W2^T bf16 limb lo

// ---------------------------------------------------------------------------
// mma helpers (m16n8k16, sm_80+, compiles for plain compute_100)
// ---------------------------------------------------------------------------
__device__ __forceinline__ void mma_bf16(float* c, const uint32_t* a,
                                         uint32_t b0, uint32_t b1) {
    asm volatile(
        "mma.sync.aligned.m16n8k16.row.col.f32.bf16.bf16.f32 "
        "{%0,%1,%2,%3}, {%4,%5,%6,%7}, {%8,%9}, {%0,%1,%2,%3};"
        : "+f"(c[0]), "+f"(c[1]), "+f"(c[2]), "+f"(c[3])
        : "r"(a[0]), "r"(a[1]), "r"(a[2]), "r"(a[3]), "r"(b0), "r"(b1));
}
__device__ __forceinline__ void mma_f16(float* c, const uint32_t* a,
                                        uint32_t b0, uint32_t b1) {
    asm volatile(
        "mma.sync.aligned.m16n8k16.row.col.f32.f16.f16.f32 "
        "{%0,%1,%2,%3}, {%4,%5,%6,%7}, {%8,%9}, {%0,%1,%2,%3};"
        : "+f"(c[0]), "+f"(c[1]), "+f"(c[2]), "+f"(c[3])
        : "r"(a[0]), "r"(a[1]), "r"(a[2]), "r"(a[3]), "r"(b0), "r"(b1));
}

__device__ __forceinline__ uint32_t pack_bf2(float v0, float v1,
                                             float& r0, float& r1) {
    __nv_bfloat16 h0 = __float2bfloat16(v0);
    __nv_bfloat16 h1 = __float2bfloat16(v1);
    r0 = v0 - __bfloat162float(h0);
    r1 = v1 - __bfloat162float(h1);
    __nv_bfloat162 t = __halves2bfloat162(h0, h1);
    return *reinterpret_cast<uint32_t*>(&t);
}
__device__ __forceinline__ uint32_t pack_bf2_only(float v0, float v1) {
    __nv_bfloat16 h0 = __float2bfloat16(v0);
    __nv_bfloat16 h1 = __float2bfloat16(v1);
    __nv_bfloat162 t = __halves2bfloat162(h0, h1);
    return *reinterpret_cast<uint32_t*>(&t);
}
__device__ __forceinline__ uint32_t pack_h2(float v0, float v1) {
    __half2 t = __floats2half2_rn(v0, v1);
    return *reinterpret_cast<uint32_t*>(&t);
}

// W3 [64,256] fp32 -> n-major fp16 limb planes (hi, lo)
__global__ void w3_split_kernel(const float* __restrict__ W3)
{
    int idx = blockIdx.x * blockDim.x + threadIdx.x;
    if (idx >= 64 * 256) return;
    int k = idx >> 8, n = idx & 255;
    float v = W3[idx];
    __half h = __float2half_rn(v);
    g_W3h0[n * 64 + k] = h;
    g_W3h1[n * 64 + k] = __float2half_rn(v - __half2float(h));
}
// W2 [64,64] fp32 -> n-major bf16 limb planes
__global__ void w2_split_kernel(const float* __restrict__ W2)
{
    int idx = blockIdx.x * blockDim.x + threadIdx.x;
    if (idx >= 64 * 64) return;
    int k = idx >> 6, n = idx & 63;
    float v = W2[idx];
    __nv_bfloat16 h = __float2bfloat16(v);
    g_W2b0[n * 64 + k] = h;
    g_W2b1[n * 64 + k] = __float2bfloat16(v - __bfloat162float(h));
}

// ---------------------------------------------------------------------------
// FUSED edge pipeline + message-pass-1 (256 threads, 8 warps, warp = 32 rows)
//   stage1 (scalar): e1 = relu(ea@W1+b1) -> warp-private smem bf16 limbs
//   MMA1 (bf16, 3 products): e2 = relu(e1@W2+b2) -> register fragments
//   MMA2 (fp16, 2 products: a_hi*(b_hi+b_lo)): Wedge = e2@W3+b3
//   Wedge store COALESCED via warp-private smem staging (stride 36,
//   conflict-free STS; flush as 4x128B-contiguous STG.128 per instr).
//   EPILOGUE: msg1 = h0[src]@Wedge accumulated from register fragments.
// Persistent, grid<=148; only __syncwarp in the tile loop.
// ---------------------------------------------------------------------------
#define FZ_E1_0   0
#define FZ_E1_1   36864
#define FZ_W2_0   73728
#define FZ_W2_1   82944
#define FZ_W3_0   92160
#define FZ_W3_1   129024
#define FZ_STAGE  165888
#define FZ_SMEM   202752

__global__ __launch_bounds__(256, 1)
void fused_edge_kernel(const float* __restrict__ edge_attr,
                       const int* __restrict__ edge_index,
                       const float* __restrict__ W1, const float* __restrict__ b1,
                       const float* __restrict__ b2, const float* __restrict__ b3,
                       int E, int ntiles)
{
    extern __shared__ char smem[];
    uint32_t* E1_0 = (uint32_t*)(smem + FZ_E1_0);   // [256][36] words (bf16x2)
    uint32_t* E1_1 = (uint32_t*)(smem + FZ_E1_1);
    uint32_t* W2s0 = (uint32_t*)(smem + FZ_W2_0);   // [64][36]  (bf16x2)
    uint32_t* W2s1 = (uint32_t*)(smem + FZ_W2_1);
    uint32_t* W3s0 = (uint32_t*)(smem + FZ_W3_0);   // [256][36] (fp16x2)
    uint32_t* W3s1 = (uint32_t*)(smem + FZ_W3_1);
    uint32_t* STG_S = (uint32_t*)(smem + FZ_STAGE); // [256][36] staging (fp16x2)
    __shared__ float W1s[256], b1s[64], b2s[64], b3s[256];

    int tid = threadIdx.x;
    // One-time loads (persistent kernel)
    for (int i = tid; i < 64 * 32; i += 256) {
        int r = i >> 5, w = i & 31;
        W2s0[r * 36 + w] = ((const uint32_t*)g_W2b0)[r * 32 + w];
        W2s1[r * 36 + w] = ((const uint32_t*)g_W2b1)[r * 32 + w];
    }
    for (int i = tid; i < 256 * 32; i += 256) {
        int r = i >> 5, w = i & 31;
        W3s0[r * 36 + w] = ((const uint32_t*)g_W3h0)[r * 32 + w];
        W3s1[r * 36 + w] = ((const uint32_t*)g_W3h1)[r * 32 + w];
    }
    if (tid < 256) { W1s[tid] = W1[tid]; b3s[tid] = b3[tid]; }
    if (tid < 64)  { b1s[tid] = b1[tid]; b2s[tid] = b2[tid]; }
    __syncthreads();

    int lane = tid & 31, wid = tid >> 5;
    int qr = lane >> 2, tg = lane & 3;
    int mrow = wid * 32;                    // warp's 32-row block
    const float4* W1s4 = (const float4*)W1s;
    const float4* b1s4 = (const float4*)b1s;
    const float*  h0g  = g_h[0];
    float*        h1g  = g_h[1];

    for (int t = blockIdx.x; t < ntiles; t += gridDim.x) {
        size_t ebase = (size_t)t * 256;

        // ---- stage 1: thread tid -> edge row tid; warp-private rows ----
        {
            size_t e = ebase + (size_t)tid;
            float4 a = make_float4(0.f, 0.f, 0.f, 0.f);
            float vm = 0.f;
            if (e < (size_t)E) { a = ((const float4*)edge_attr)[e]; vm = 1.f; }
#pragma unroll
            for (int m4 = 0; m4 < 16; ++m4) {
                float4 w0 = W1s4[m4];
                float4 w1 = W1s4[16 + m4];
                float4 w2 = W1s4[32 + m4];
                float4 w3 = W1s4[48 + m4];
                float4 bb = b1s4[m4];
                float v0 = vm * fmaxf(bb.x + a.x*w0.x + a.y*w1.x + a.z*w2.x + a.w*w3.x, 0.f);
                float v1 = vm * fmaxf(bb.y + a.x*w0.y + a.y*w1.y + a.z*w2.y + a.w*w3.y, 0.f);
                float v2 = vm * fmaxf(bb.z + a.x*w0.z + a.y*w1.z + a.z*w2.z + a.w*w3.z, 0.f);
                float v3 = vm * fmaxf(bb.w + a.x*w0.w + a.y*w1.w + a.z*w2.w + a.w*w3.w, 0.f);
                float r0, r1, r2, r3;
                uint32_t h0 = pack_bf2(v0, v1, r0, r1);
                uint32_t h1 = pack_bf2(v2, v3, r2, r3);
                E1_0[tid * 36 + 2 * m4]     = h0;
                E1_0[tid * 36 + 2 * m4 + 1] = h1;
                E1_1[tid * 36 + 2 * m4]     = pack_bf2_only(r0, r1);
                E1_1[tid * 36 + 2 * m4 + 1] = pack_bf2_only(r2, r3);
            }
        }
        __syncwarp();

        // ---- per-lane edge metadata for the 4 fragment rows ----
        int srcs[4], dsts[4];
        bool rv[4];
        float pacc[4][4];
#pragma unroll
        for (int rr = 0; rr < 4; ++rr) {
            int row = mrow + (rr >> 1) * 16 + (rr & 1) * 8 + qr;
            size_t e = ebase + (size_t)row;
            rv[rr] = e < (size_t)E;
            srcs[rr] = rv[rr] ? edge_index[2 * e]     : 0;
            dsts[rr] = rv[rr] ? edge_index[2 * e + 1] : 0;
            pacc[rr][0] = 0.f; pacc[rr][1] = 0.f;
            pacc[rr][2] = 0.f; pacc[rr][3] = 0.f;
        }

        // ---- MMA1: e2 = relu(e1 @ W2 + b2), bf16 2-limb 3-product ----
        float cc1[2][8][4];
#pragma unroll
        for (int mt = 0; mt < 2; ++mt)
#pragma unroll
            for (int nt = 0; nt < 8; ++nt) {
                cc1[mt][nt][0] = 0.f; cc1[mt][nt][1] = 0.f;
                cc1[mt][nt][2] = 0.f; cc1[mt][nt][3] = 0.f;
            }
#pragma unroll
        for (int ks = 0; ks < 4; ++ks) {
            int kofs = ks * 8 + tg;
            uint32_t a0[2][4], a1[2][4];
#pragma unroll
            for (int mt = 0; mt < 2; ++mt) {
                int r0 = mrow + mt * 16 + qr;
                a0[mt][0] = E1_0[r0 * 36 + kofs];
                a0[mt][1] = E1_0[(r0 + 8) * 36 + kofs];
                a0[mt][2] = E1_0[r0 * 36 + kofs + 4];
                a0[mt][3] = E1_0[(r0 + 8) * 36 + kofs + 4];
                a1[mt][0] = E1_1[r0 * 36 + kofs];
                a1[mt][1] = E1_1[(r0 + 8) * 36 + kofs];
                a1[mt][2] = E1_1[r0 * 36 + kofs + 4];
                a1[mt][3] = E1_1[(r0 + 8) * 36 + kofs + 4];
            }
#pragma unroll
            for (int nt = 0; nt < 8; ++nt) {
                int n = nt * 8 + qr;
                uint32_t b00 = W2s0[n * 36 + kofs];
                uint32_t b01 = W2s0[n * 36 + kofs + 4];
                uint32_t b10 = W2s1[n * 36 + kofs];
                uint32_t b11 = W2s1[n * 36 + kofs + 4];
#pragma unroll
                for (int mt = 0; mt < 2; ++mt) {
                    mma_bf16(cc1[mt][nt], a0[mt], b00, b01);
                    mma_bf16(cc1[mt][nt], a1[mt], b00, b01);
                    mma_bf16(cc1[mt][nt], a0[mt], b10, b11);
                }
            }
        }

        // ---- relu(+b2) and repack C1 fragments as fp16 A2 fragments ----
        uint32_t a2h[2][4][4];
#pragma unroll
        for (int mt = 0; mt < 2; ++mt)
#pragma unroll
            for (int nt = 0; nt < 8; ++nt) {
                float bb0 = b2s[nt * 8 + 2 * tg];
                float bb1 = b2s[nt * 8 + 2 * tg + 1];
                float d0 = fmaxf(cc1[mt][nt][0] + bb0, 0.f);
                float d1 = fmaxf(cc1[mt][nt][1] + bb1, 0.f);
                float d2 = fmaxf(cc1[mt][nt][2] + bb0, 0.f);
                float d3 = fmaxf(cc1[mt][nt][3] + bb1, 0.f);
                int ks2 = nt >> 1, q = (nt & 1) * 2;
                a2h[mt][ks2][q]     = pack_h2(d0, d1);
                a2h[mt][ks2][q + 1] = pack_h2(d2, d3);
            }

        // ---- MMA2 (fp16) + staged coalesced store + msg1 epilogue ----
        uint4* outw4 = (uint4*)g_Wedgeh;
#pragma unroll
        for (int grp = 0; grp < 4; ++grp) {
            int noff = grp * 64;
            float cc2[2][8][4];
#pragma unroll
            for (int mt = 0; mt < 2; ++mt)
#pragma unroll
                for (int nt = 0; nt < 8; ++nt) {
                    cc2[mt][nt][0] = 0.f; cc2[mt][nt][1] = 0.f;
                    cc2[mt][nt][2] = 0.f; cc2[mt][nt][3] = 0.f;
                }
#pragma unroll
            for (int ks = 0; ks < 4; ++ks) {
                int kofs = ks * 8 + tg;
#pragma unroll
                for (int nt = 0; nt < 8; ++nt) {
                    int n = noff + nt * 8 + qr;
                    uint32_t b00 = W3s0[n * 36 + kofs];
                    uint32_t b01 = W3s0[n * 36 + kofs + 4];
                    uint32_t b10 = W3s1[n * 36 + kofs];
                    uint32_t b11 = W3s1[n * 36 + kofs + 4];
#pragma unroll
                    for (int mt = 0; mt < 2; ++mt) {
                        mma_f16(cc2[mt][nt], a2h[mt][ks], b00, b01);
                        mma_f16(cc2[mt][nt], a2h[mt][ks], b10, b11);
                    }
                }
            }

            // h0[src] float4 for this grp (i = 4*grp + nt>>1), per fragment row
            float4 hv[4];
#pragma unroll
            for (int rr = 0; rr < 4; ++rr)
                hv[rr] = rv[rr]
                    ? ((const float4*)(h0g + (size_t)srcs[rr] * 16))[grp]
                    : make_float4(0.f, 0.f, 0.f, 0.f);

            // Stage fp16 (+b3) into smem (conflict-free) + accumulate msg1
#pragma unroll
            for (int mt = 0; mt < 2; ++mt) {
                int row0 = mrow + mt * 16 + qr;
                int rr0 = mt * 2, rr1 = mt * 2 + 1;
#pragma unroll
                for (int nt = 0; nt < 8; ++nt) {
                    int n0 = noff + nt * 8 + 2 * tg;
                    float bb0 = b3s[n0], bb1 = b3s[n0 + 1];
                    float w0 = cc2[mt][nt][0] + bb0;
                    float w1 = cc2[mt][nt][1] + bb1;
                    float w2v = cc2[mt][nt][2] + bb0;
                    float w3v = cc2[mt][nt][3] + bb1;
                    int s = (nt & 1) * 2;
                    float hc0 = ((const float*)&hv[rr0])[nt >> 1];
                    float hc1 = ((const float*)&hv[rr1])[nt >> 1];
                    pacc[rr0][s]     += hc0 * w0;
                    pacc[rr0][s + 1] += hc0 * w1;
                    pacc[rr1][s]     += hc1 * w2v;
                    pacc[rr1][s + 1] += hc1 * w3v;
                    // banks = (4*row + 4*nt + tg) mod 32 -> 32 distinct
                    STG_S[row0 * 36 + nt * 4 + tg]       = pack_h2(w0, w1);
                    STG_S[(row0 + 8) * 36 + nt * 4 + tg] = pack_h2(w2v, w3v);
                }
            }
            __syncwarp();

            // Coalesced flush: per instr 4 rows x 8 lanes = 4x128B contiguous
#pragma unroll
            for (int it = 0; it < 8; ++it) {
                int row = mrow + it * 4 + (lane >> 3);
                int w4  = lane & 7;
                size_t e = ebase + (size_t)row;
                if (e < (size_t)E) {
                    const uint32_t* sp = STG_S + row * 36 + w4 * 4;
                    uint4 v = make_uint4(sp[0], sp[1], sp[2], sp[3]);
                    outw4[e * 32 + grp * 8 + w4] = v;
                }
            }
            __syncwarp();   // staging reusable for next grp
        }

        // ---- flush msg1 partials: o = (s>>1)*8 + (s&1) + 2*tg ----
#pragma unroll
        for (int rr = 0; rr < 4; ++rr) {
            if (!rv[rr]) continue;
            float* dh = h1g + (size_t)dsts[rr] * 16;
            atomicAdd(dh + 2 * tg,     pacc[rr][0]);
            atomicAdd(dh + 2 * tg + 1, pacc[rr][1]);
            atomicAdd(dh + 2 * tg + 8, pacc[rr][2]);
            atomicAdd(dh + 2 * tg + 9, pacc[rr][3]);
        }
    }
}

// ---------------------------------------------------------------------------
// h0 = [x | zeros]
// ---------------------------------------------------------------------------
__global__ void init_h_kernel(const float* __restrict__ x, int N)
{
    int idx = blockIdx.x * blockDim.x + threadIdx.x;
    if (idx >= N * 16) return;
    int n = idx >> 4, i = idx & 15;
    g_h[0][idx] = (i < 8) ? x[n * 8 + i] : 0.f;
}

// h_out = bias + h_in @ root
__global__ void node_init_kernel(int in_slot, int out_slot,
                                 const float* __restrict__ root,
                                 const float* __restrict__ bias, int N)
{
    __shared__ float rs[256];
    __shared__ float bs[16];
    int tid = threadIdx.x;
    if (tid < 256) rs[tid] = root[tid];
    if (tid < 16)  bs[tid] = bias[tid];
    __syncthreads();
    int idx = blockIdx.x * blockDim.x + tid;
    if (idx >= N * 16) return;
    int n = idx >> 4, o = idx & 15;
    const float* hr = g_h[in_slot] + n * 16;
    float acc = bs[o];
#pragma unroll
    for (int i = 0; i < 16; ++i) acc += hr[i] * rs[i * 16 + o];
    g_h[out_slot][idx] = acc;
}

// Message pass: h_out[dst] += h_in[src] @ Wedge[e] (fp16). One warp per edge.
__global__ __launch_bounds__(256)
void msg_kernel(int in_slot, int out_slot, const int* __restrict__ edge_index, int E)
{
    int lane = threadIdx.x & 31;
    int e = (blockIdx.x * 256 + threadIdx.x) >> 5;
    if (e >= E) return;
    int src = edge_index[2 * e];
    int dst = edge_index[2 * e + 1];

    const float* h_in = g_h[in_slot] + (size_t)src * 16;
    float hv = (lane < 16) ? h_in[lane] : 0.f;

    const uint32_t* W = (const uint32_t*)(g_Wedgeh + (size_t)e * 256);
    float p0 = 0.f, p1 = 0.f;
    int ib = lane >> 3;
#pragma unroll
    for (int j = 0; j < 4; ++j) {
        uint32_t wv = W[lane + 32 * j];
        __half2 h2 = *reinterpret_cast<__half2*>(&wv);
        float2 wf = __half22float2(h2);
        float hk = __shfl_sync(0xffffffffu, hv, ib + 4 * j);
        p0 += hk * wf.x;
        p1 += hk * wf.y;
    }
    p0 += __shfl_xor_sync(0xffffffffu, p0, 8);
    p1 += __shfl_xor_sync(0xffffffffu, p1, 8);
    p0 += __shfl_xor_sync(0xffffffffu, p0, 16);
    p1 += __shfl_xor_sync(0xffffffffu, p1, 16);
    if (lane < 8) {
        float* dsth = &g_h[out_slot][(size_t)dst * 16 + 2 * lane];
        atomicAdd(dsth, p0);
        atomicAdd(dsth + 1, p1);
    }
}

// ---------------------------------------------------------------------------
// Readout
// ---------------------------------------------------------------------------
__global__ void zero_out_kernel(float* out)
{
    if (threadIdx.x == 0 && blockIdx.x == 0) out[0] = 0.f;
}

__global__ __launch_bounds__(256)
void readout_kernel(int h_slot,
                    const float* __restrict__ Wi1, const float* __restrict__ bi1,
                    const float* __restrict__ Wi2, const float* __restrict__ bi2,
                    const float* __restrict__ Wj1, const float* __restrict__ bj1,
                    const float* __restrict__ Wj2, const float* __restrict__ bj2,
                    float* __restrict__ out, int N)
{
    __shared__ float Wi1s[4096], Wj1s[2048];
    __shared__ float bi1s[128], bj1s[128], Wi2s[128], Wj2s[128];
    __shared__ float warpsum[8];

    int tid = threadIdx.x;
    for (int i = tid; i < 4096; i += 256) Wi1s[i] = Wi1[i];
    for (int i = tid; i < 2048; i += 256) Wj1s[i] = Wj1[i];
    if (tid < 128) {
        bi1s[tid] = bi1[tid]; bj1s[tid] = bj1[tid];
        Wi2s[tid] = Wi2[tid]; Wj2s[tid] = Wj2[tid];
    }
    __syncthreads();

    int lane = tid & 31, w = tid >> 5;
    int n = blockIdx.x * 8 + w;
    float contrib = 0.f;

    if (n < N) {
        const float* h  = g_h[h_slot] + n * 16;
        const float* h0 = g_h[0] + n * 16;
        float hv  = (lane < 16) ? h[lane]  : 0.f;
        float h0v = (lane < 16) ? h0[lane] : 0.f;

        float a0 = bi1s[lane], a1 = bi1s[lane + 32], a2 = bi1s[lane + 64], a3 = bi1s[lane + 96];
#pragma unroll
        for (int c = 0; c < 32; ++c) {
            float cc = __shfl_sync(0xffffffffu, (c < 16) ? hv : h0v, c & 15);
            a0 += cc * Wi1s[c * 128 + lane];
            a1 += cc * Wi1s[c * 128 + lane + 32];
            a2 += cc * Wi1s[c * 128 + lane + 64];
            a3 += cc * Wi1s[c * 128 + lane + 96];
        }
        a0 = fmaxf(a0, 0.f); a1 = fmaxf(a1, 0.f); a2 = fmaxf(a2, 0.f); a3 = fmaxf(a3, 0.f);
        float g = a0 * Wi2s[lane] + a1 * Wi2s[lane + 32] + a2 * Wi2s[lane + 64] + a3 * Wi2s[lane + 96];

        float v0 = bj1s[lane], v1 = bj1s[lane + 32], v2 = bj1s[lane + 64], v3 = bj1s[lane + 96];
#pragma unroll
        for (int c = 0; c < 16; ++c) {
            float cc = __shfl_sync(0xffffffffu, hv, c);
            v0 += cc * Wj1s[c * 128 + lane];
            v1 += cc * Wj1s[c * 128 + lane + 32];
            v2 += cc * Wj1s[c * 128 + lane + 64];
            v3 += cc * Wj1s[c * 128 + lane + 96];
        }
        v0 = fmaxf(v0, 0.f); v1 = fmaxf(v1, 0.f); v2 = fmaxf(v2, 0.f); v3 = fmaxf(v3, 0.f);
        float vv = v0 * Wj2s[lane] + v1 * Wj2s[lane + 32] + v2 * Wj2s[lane + 64] + v3 * Wj2s[lane + 96];

#pragma unroll
        for (int s = 16; s > 0; s >>= 1) {
            g  += __shfl_xor_sync(0xffffffffu, g, s);
            vv += __shfl_xor_sync(0xffffffffu, vv, s);
        }
        if (lane == 0) {
            float gate = 1.f / (1.f + expf(-(g + bi2[0])));
            contrib = gate * (vv + bj2[0]);
        }
    }
    if (lane == 0) warpsum[w] = contrib;
    __syncthreads();
    if (tid == 0) {
        float s = 0.f;
#pragma unroll
        for (int i = 0; i < 8; ++i) s += warpsum[i];
        atomicAdd(out, s);
    }
}

// ===========================================================================
extern "C" void kernel_launch(void* const* d_in, const int* in_sizes, int n_in,
                              void* d_out, int out_size)
{
    const float* x          = (const float*)d_in[0];
    const int*   edge_index = (const int*)  d_in[1];
    const float* edge_attr  = (const float*)d_in[2];
    const float* W1  = (const float*)d_in[3];
    const float* b1  = (const float*)d_in[4];
    const float* W2  = (const float*)d_in[5];
    const float* b2  = (const float*)d_in[6];
    const float* W3  = (const float*)d_in[7];
    const float* b3  = (const float*)d_in[8];
    const float* root = (const float*)d_in[9];
    const float* bias = (const float*)d_in[10];
    const float* Wi1 = (const float*)d_in[11];
    const float* bi1 = (const float*)d_in[12];
    const float* Wi2 = (const float*)d_in[13];
    const float* bi2 = (const float*)d_in[14];
    const float* Wj1 = (const float*)d_in[15];
    const float* bj1 = (const float*)d_in[16];
    const float* Wj2 = (const float*)d_in[17];
    const float* bj2 = (const float*)d_in[18];

    int N = in_sizes[0] / 8;  if (N > NMAX) N = NMAX;
    int E = in_sizes[1] / 2;  if (E > EMAX) E = EMAX;
    float* out = (float*)d_out;

    cudaFuncSetAttribute(fused_edge_kernel,
                         cudaFuncAttributeMaxDynamicSharedMemorySize, FZ_SMEM);

    int node_blocks = (N * 16 + 255) / 256;
    int edge_blocks = (E + 7) / 8;
    int ntiles      = (E + 255) / 256;
    int fused_grid  = ntiles < 148 ? ntiles : 148;

    w3_split_kernel<<<64, 256>>>(W3);
    w2_split_kernel<<<16, 256>>>(W2);
    init_h_kernel<<<node_blocks, 256>>>(x, N);
    node_init_kernel<<<node_blocks, 256>>>(0, 1, root, bias, N);
    zero_out_kernel<<<1, 32>>>(out);

    // Fused: edge MLP + coalesced Wedge store + message pass 1 (0 -> 1)
    fused_edge_kernel<<<fused_grid, 256, FZ_SMEM>>>(edge_attr, edge_index,
                                                    W1, b1, b2, b3, E, ntiles);

    // Passes 2 and 3
    node_init_kernel<<<node_blocks, 256>>>(1, 2, root, bias, N);
    msg_kernel<<<edge_blocks, 256>>>(1, 2, edge_index, E);
    node_init_kernel<<<node_blocks, 256>>>(2, 1, root, bias, N);
    msg_kernel<<<edge_blocks, 256>>>(2, 1, edge_index, E);

    readout_kernel<<<(N + 7) / 8, 256>>>(1, Wi1, bi1, Wi2, bi2,
                                         Wj1, bj1, Wj2, bj2, out, N);
}

// round 16
// speedup vs baseline: 6.7598x; 1.0401x over previous
#include <cuda_runtime.h>
#include <cuda_bf16.h>
#include <cuda_fp16.h>
#include <math.h>
#include <stdint.h>

// Problem constants (fixed by the dataset)
#define NMAX 100000
#define EMAX 800000

// Scratch (device globals: allocation-free per harness rules)
__device__ __half g_Wedgeh[(size_t)EMAX * 256];     // 409 MB per-edge 16x16 (fp16)
__device__ float  g_h[3][NMAX * 16];                // slot0 = h0, 1/2 ping-pong
__device__ __half g_W3h0[256 * 64];                 // W3^T fp16 limb hi (n-major)
__device__ __half g_W3h1[256 * 64];                 // W3^T fp16 limb lo
__device__ __half g_W2h0[64 * 64];                  // W2^T fp16 limb hi (n-major)
__device__ __half g_W2h1[64 * 64];                  // W2^T fp16 limb lo

// ---------------------------------------------------------------------------
// mma helper (m16n8k16 fp16, sm_80+, compiles for plain compute_100)
// ---------------------------------------------------------------------------
__device__ __forceinline__ void mma_f16(float* c, const uint32_t* a,
                                        uint32_t b0, uint32_t b1) {
    asm volatile(
        "mma.sync.aligned.m16n8k16.row.col.f32.f16.f16.f32 "
        "{%0,%1,%2,%3}, {%4,%5,%6,%7}, {%8,%9}, {%0,%1,%2,%3};"
        : "+f"(c[0]), "+f"(c[1]), "+f"(c[2]), "+f"(c[3])
        : "r"(a[0]), "r"(a[1]), "r"(a[2]), "r"(a[3]), "r"(b0), "r"(b1));
}

__device__ __forceinline__ uint32_t pack_h2(float v0, float v1) {
    __half2 t = __floats2half2_rn(v0, v1);
    return *reinterpret_cast<uint32_t*>(&t);
}

// W3 [64,256] fp32 -> n-major fp16 limb planes (hi, lo)
__global__ void w3_split_kernel(const float* __restrict__ W3)
{
    int idx = blockIdx.x * blockDim.x + threadIdx.x;
    if (idx >= 64 * 256) return;
    int k = idx >> 8, n = idx & 255;
    float v = W3[idx];
    __half h = __float2half_rn(v);
    g_W3h0[n * 64 + k] = h;
    g_W3h1[n * 64 + k] = __float2half_rn(v - __half2float(h));
}
// W2 [64,64] fp32 -> n-major fp16 limb planes
__global__ void w2_split_kernel(const float* __restrict__ W2)
{
    int idx = blockIdx.x * blockDim.x + threadIdx.x;
    if (idx >= 64 * 64) return;
    int k = idx >> 6, n = idx & 63;
    float v = W2[idx];
    __half h = __float2half_rn(v);
    g_W2h0[n * 64 + k] = h;
    g_W2h1[n * 64 + k] = __float2half_rn(v - __half2float(h));
}

// ---------------------------------------------------------------------------
// FUSED edge pipeline + message-pass-1 (256 threads, 8 warps, warp = 32 rows)
//   stage1 (scalar): e1 = relu(ea@W1+b1) -> warp-private smem, fp16 (1 plane)
//   MMA1 (fp16, 2 products: e1_hi*(W2_hi+W2_lo)): e2 = relu(.@W2+b2)
//   MMA2 (fp16, 2 products: e2_hi*(W3_hi+W3_lo)): Wedge = e2@W3+b3
//   Wedge store COALESCED via warp-private smem staging.
//   EPILOGUE: msg1 = h0[src]@Wedge from register fragments.
// Persistent, grid<=148; only __syncwarp in the tile loop.
// Row stride 36 words: fragment banks 4*qr+tg, conflict-free.
// ---------------------------------------------------------------------------
#define FZ_E1     0
#define FZ_W2_0   36864
#define FZ_W2_1   46080
#define FZ_W3_0   55296
#define FZ_W3_1   92160
#define FZ_STAGE  129024
#define FZ_SMEM   165888

__global__ __launch_bounds__(256, 1)
void fused_edge_kernel(const float* __restrict__ edge_attr,
                       const int* __restrict__ edge_index,
                       const float* __restrict__ W1, const float* __restrict__ b1,
                       const float* __restrict__ b2, const float* __restrict__ b3,
                       int E, int ntiles)
{
    extern __shared__ char smem[];
    uint32_t* E1s  = (uint32_t*)(smem + FZ_E1);     // [256][36] words (fp16x2)
    uint32_t* W2s0 = (uint32_t*)(smem + FZ_W2_0);   // [64][36]  (fp16x2)
    uint32_t* W2s1 = (uint32_t*)(smem + FZ_W2_1);
    uint32_t* W3s0 = (uint32_t*)(smem + FZ_W3_0);   // [256][36] (fp16x2)
    uint32_t* W3s1 = (uint32_t*)(smem + FZ_W3_1);
    uint32_t* STG_S = (uint32_t*)(smem + FZ_STAGE); // [256][36] staging (fp16x2)
    __shared__ float W1s[256], b1s[64], b2s[64], b3s[256];

    int tid = threadIdx.x;
    // One-time loads (persistent kernel)
    for (int i = tid; i < 64 * 32; i += 256) {
        int r = i >> 5, w = i & 31;
        W2s0[r * 36 + w] = ((const uint32_t*)g_W2h0)[r * 32 + w];
        W2s1[r * 36 + w] = ((const uint32_t*)g_W2h1)[r * 32 + w];
    }
    for (int i = tid; i < 256 * 32; i += 256) {
        int r = i >> 5, w = i & 31;
        W3s0[r * 36 + w] = ((const uint32_t*)g_W3h0)[r * 32 + w];
        W3s1[r * 36 + w] = ((const uint32_t*)g_W3h1)[r * 32 + w];
    }
    if (tid < 256) { W1s[tid] = W1[tid]; b3s[tid] = b3[tid]; }
    if (tid < 64)  { b1s[tid] = b1[tid]; b2s[tid] = b2[tid]; }
    __syncthreads();

    int lane = tid & 31, wid = tid >> 5;
    int qr = lane >> 2, tg = lane & 3;
    int mrow = wid * 32;                    // warp's 32-row block
    const float4* W1s4 = (const float4*)W1s;
    const float4* b1s4 = (const float4*)b1s;
    const float*  h0g  = g_h[0];
    float*        h1g  = g_h[1];

    for (int t = blockIdx.x; t < ntiles; t += gridDim.x) {
        size_t ebase = (size_t)t * 256;

        // ---- stage 1: thread tid -> edge row tid; warp-private rows ----
        {
            size_t e = ebase + (size_t)tid;
            float4 a = make_float4(0.f, 0.f, 0.f, 0.f);
            float vm = 0.f;
            if (e < (size_t)E) { a = ((const float4*)edge_attr)[e]; vm = 1.f; }
#pragma unroll
            for (int m4 = 0; m4 < 16; ++m4) {
                float4 w0 = W1s4[m4];
                float4 w1 = W1s4[16 + m4];
                float4 w2 = W1s4[32 + m4];
                float4 w3 = W1s4[48 + m4];
                float4 bb = b1s4[m4];
                float v0 = vm * fmaxf(bb.x + a.x*w0.x + a.y*w1.x + a.z*w2.x + a.w*w3.x, 0.f);
                float v1 = vm * fmaxf(bb.y + a.x*w0.y + a.y*w1.y + a.z*w2.y + a.w*w3.y, 0.f);
                float v2 = vm * fmaxf(bb.z + a.x*w0.z + a.y*w1.z + a.z*w2.z + a.w*w3.z, 0.f);
                float v3 = vm * fmaxf(bb.w + a.x*w0.w + a.y*w1.w + a.z*w2.w + a.w*w3.w, 0.f);
                E1s[tid * 36 + 2 * m4]     = pack_h2(v0, v1);
                E1s[tid * 36 + 2 * m4 + 1] = pack_h2(v2, v3);
            }
        }
        __syncwarp();

        // ---- per-lane edge metadata for the 4 fragment rows ----
        int srcs[4], dsts[4];
        bool rv[4];
        float pacc[4][4];
#pragma unroll
        for (int rr = 0; rr < 4; ++rr) {
            int row = mrow + (rr >> 1) * 16 + (rr & 1) * 8 + qr;
            size_t e = ebase + (size_t)row;
            rv[rr] = e < (size_t)E;
            srcs[rr] = rv[rr] ? edge_index[2 * e]     : 0;
            dsts[rr] = rv[rr] ? edge_index[2 * e + 1] : 0;
            pacc[rr][0] = 0.f; pacc[rr][1] = 0.f;
            pacc[rr][2] = 0.f; pacc[rr][3] = 0.f;
        }

        // ---- MMA1: e2 = relu(e1 @ W2 + b2), fp16 2-product ----
        float cc1[2][8][4];
#pragma unroll
        for (int mt = 0; mt < 2; ++mt)
#pragma unroll
            for (int nt = 0; nt < 8; ++nt) {
                cc1[mt][nt][0] = 0.f; cc1[mt][nt][1] = 0.f;
                cc1[mt][nt][2] = 0.f; cc1[mt][nt][3] = 0.f;
            }
#pragma unroll
        for (int ks = 0; ks < 4; ++ks) {
            int kofs = ks * 8 + tg;
            uint32_t a0[2][4];
#pragma unroll
            for (int mt = 0; mt < 2; ++mt) {
                int r0 = mrow + mt * 16 + qr;
                a0[mt][0] = E1s[r0 * 36 + kofs];
                a0[mt][1] = E1s[(r0 + 8) * 36 + kofs];
                a0[mt][2] = E1s[r0 * 36 + kofs + 4];
                a0[mt][3] = E1s[(r0 + 8) * 36 + kofs + 4];
            }
#pragma unroll
            for (int nt = 0; nt < 8; ++nt) {
                int n = nt * 8 + qr;
                uint32_t b00 = W2s0[n * 36 + kofs];
                uint32_t b01 = W2s0[n * 36 + kofs + 4];
                uint32_t b10 = W2s1[n * 36 + kofs];
                uint32_t b11 = W2s1[n * 36 + kofs + 4];
#pragma unroll
                for (int mt = 0; mt < 2; ++mt) {
                    mma_f16(cc1[mt][nt], a0[mt], b00, b01);
                    mma_f16(cc1[mt][nt], a0[mt], b10, b11);
                }
            }
        }

        // ---- relu(+b2) and repack C1 fragments as fp16 A2 fragments ----
        uint32_t a2h[2][4][4];
#pragma unroll
        for (int mt = 0; mt < 2; ++mt)
#pragma unroll
            for (int nt = 0; nt < 8; ++nt) {
                float bb0 = b2s[nt * 8 + 2 * tg];
                float bb1 = b2s[nt * 8 + 2 * tg + 1];
                float d0 = fmaxf(cc1[mt][nt][0] + bb0, 0.f);
                float d1 = fmaxf(cc1[mt][nt][1] + bb1, 0.f);
                float d2 = fmaxf(cc1[mt][nt][2] + bb0, 0.f);
                float d3 = fmaxf(cc1[mt][nt][3] + bb1, 0.f);
                int ks2 = nt >> 1, q = (nt & 1) * 2;
                a2h[mt][ks2][q]     = pack_h2(d0, d1);
                a2h[mt][ks2][q + 1] = pack_h2(d2, d3);
            }

        // ---- MMA2 (fp16) + staged coalesced store + msg1 epilogue ----
        uint4* outw4 = (uint4*)g_Wedgeh;
#pragma unroll
        for (int grp = 0; grp < 4; ++grp) {
            int noff = grp * 64;
            float cc2[2][8][4];
#pragma unroll
            for (int mt = 0; mt < 2; ++mt)
#pragma unroll
                for (int nt = 0; nt < 8; ++nt) {
                    cc2[mt][nt][0] = 0.f; cc2[mt][nt][1] = 0.f;
                    cc2[mt][nt][2] = 0.f; cc2[mt][nt][3] = 0.f;
                }
#pragma unroll
            for (int ks = 0; ks < 4; ++ks) {
                int kofs = ks * 8 + tg;
#pragma unroll
                for (int nt = 0; nt < 8; ++nt) {
                    int n = noff + nt * 8 + qr;
                    uint32_t b00 = W3s0[n * 36 + kofs];
                    uint32_t b01 = W3s0[n * 36 + kofs + 4];
                    uint32_t b10 = W3s1[n * 36 + kofs];
                    uint32_t b11 = W3s1[n * 36 + kofs + 4];
#pragma unroll
                    for (int mt = 0; mt < 2; ++mt) {
                        mma_f16(cc2[mt][nt], a2h[mt][ks], b00, b01);
                        mma_f16(cc2[mt][nt], a2h[mt][ks], b10, b11);
                    }
                }
            }

            // h0[src] float4 for this grp (i = 4*grp + nt>>1), per fragment row
            float4 hv[4];
#pragma unroll
            for (int rr = 0; rr < 4; ++rr)
                hv[rr] = rv[rr]
                    ? ((const float4*)(h0g + (size_t)srcs[rr] * 16))[grp]
                    : make_float4(0.f, 0.f, 0.f, 0.f);

            // Stage fp16 (+b3) into smem (conflict-free) + accumulate msg1
#pragma unroll
            for (int mt = 0; mt < 2; ++mt) {
                int row0 = mrow + mt * 16 + qr;
                int rr0 = mt * 2, rr1 = mt * 2 + 1;
#pragma unroll
                for (int nt = 0; nt < 8; ++nt) {
                    int n0 = noff + nt * 8 + 2 * tg;
                    float bb0 = b3s[n0], bb1 = b3s[n0 + 1];
                    float w0 = cc2[mt][nt][0] + bb0;
                    float w1 = cc2[mt][nt][1] + bb1;
                    float w2v = cc2[mt][nt][2] + bb0;
                    float w3v = cc2[mt][nt][3] + bb1;
                    int s = (nt & 1) * 2;
                    float hc0 = ((const float*)&hv[rr0])[nt >> 1];
                    float hc1 = ((const float*)&hv[rr1])[nt >> 1];
                    pacc[rr0][s]     += hc0 * w0;
                    pacc[rr0][s + 1] += hc0 * w1;
                    pacc[rr1][s]     += hc1 * w2v;
                    pacc[rr1][s + 1] += hc1 * w3v;
                    // banks = (4*row + 4*nt + tg) mod 32 -> 32 distinct
                    STG_S[row0 * 36 + nt * 4 + tg]       = pack_h2(w0, w1);
                    STG_S[(row0 + 8) * 36 + nt * 4 + tg] = pack_h2(w2v, w3v);
                }
            }
            __syncwarp();

            // Coalesced flush: per instr 4 rows x 8 lanes = 4x128B contiguous
#pragma unroll
            for (int it = 0; it < 8; ++it) {
                int row = mrow + it * 4 + (lane >> 3);
                int w4  = lane & 7;
                size_t e = ebase + (size_t)row;
                if (e < (size_t)E) {
                    const uint32_t* sp = STG_S + row * 36 + w4 * 4;
                    uint4 v = make_uint4(sp[0], sp[1], sp[2], sp[3]);
                    outw4[e * 32 + grp * 8 + w4] = v;
                }
            }
            __syncwarp();   // staging reusable for next grp
        }

        // ---- flush msg1 partials: o = (s>>1)*8 + (s&1) + 2*tg ----
#pragma unroll
        for (int rr = 0; rr < 4; ++rr) {
            if (!rv[rr]) continue;
            float* dh = h1g + (size_t)dsts[rr] * 16;
            atomicAdd(dh + 2 * tg,     pacc[rr][0]);
            atomicAdd(dh + 2 * tg + 1, pacc[rr][1]);
            atomicAdd(dh + 2 * tg + 8, pacc[rr][2]);
            atomicAdd(dh + 2 * tg + 9, pacc[rr][3]);
        }
    }
}

// ---------------------------------------------------------------------------
// h0 = [x | zeros]
// ---------------------------------------------------------------------------
__global__ void init_h_kernel(const float* __restrict__ x, int N)
{
    int idx = blockIdx.x * blockDim.x + threadIdx.x;
    if (idx >= N * 16) return;
    int n = idx >> 4, i = idx & 15;
    g_h[0][idx] = (i < 8) ? x[n * 8 + i] : 0.f;
}

// h_out = bias + h_in @ root
__global__ void node_init_kernel(int in_slot, int out_slot,
                                 const float* __restrict__ root,
                                 const float* __restrict__ bias, int N)
{
    __shared__ float rs[256];
    __shared__ float bs[16];
    int tid = threadIdx.x;
    if (tid < 256) rs[tid] = root[tid];
    if (tid < 16)  bs[tid] = bias[tid];
    __syncthreads();
    int idx = blockIdx.x * blockDim.x + tid;
    if (idx >= N * 16) return;
    int n = idx >> 4, o = idx & 15;
    const float* hr = g_h[in_slot] + n * 16;
    float acc = bs[o];
#pragma unroll
    for (int i = 0; i < 16; ++i) acc += hr[i] * rs[i * 16 + o];
    g_h[out_slot][idx] = acc;
}

// Message pass: h_out[dst] += h_in[src] @ Wedge[e] (fp16). One warp per edge.
__global__ __launch_bounds__(256)
void msg_kernel(int in_slot, int out_slot, const int* __restrict__ edge_index, int E)
{
    int lane = threadIdx.x & 31;
    int e = (blockIdx.x * 256 + threadIdx.x) >> 5;
    if (e >= E) return;
    int src = edge_index[2 * e];
    int dst = edge_index[2 * e + 1];

    const float* h_in = g_h[in_slot] + (size_t)src * 16;
    float hv = (lane < 16) ? h_in[lane] : 0.f;

    const uint32_t* W = (const uint32_t*)(g_Wedgeh + (size_t)e * 256);
    float p0 = 0.f, p1 = 0.f;
    int ib = lane >> 3;
#pragma unroll
    for (int j = 0; j < 4; ++j) {
        uint32_t wv = W[lane + 32 * j];
        __half2 h2 = *reinterpret_cast<__half2*>(&wv);
        float2 wf = __half22float2(h2);
        float hk = __shfl_sync(0xffffffffu, hv, ib + 4 * j);
        p0 += hk * wf.x;
        p1 += hk * wf.y;
    }
    p0 += __shfl_xor_sync(0xffffffffu, p0, 8);
    p1 += __shfl_xor_sync(0xffffffffu, p1, 8);
    p0 += __shfl_xor_sync(0xffffffffu, p0, 16);
    p1 += __shfl_xor_sync(0xffffffffu, p1, 16);
    if (lane < 8) {
        float* dsth = &g_h[out_slot][(size_t)dst * 16 + 2 * lane];
        atomicAdd(dsth, p0);
        atomicAdd(dsth + 1, p1);
    }
}

// ---------------------------------------------------------------------------
// Readout
// ---------------------------------------------------------------------------
__global__ void zero_out_kernel(float* out)
{
    if (threadIdx.x == 0 && blockIdx.x == 0) out[0] = 0.f;
}

__global__ __launch_bounds__(256)
void readout_kernel(int h_slot,
                    const float* __restrict__ Wi1, const float* __restrict__ bi1,
                    const float* __restrict__ Wi2, const float* __restrict__ bi2,
                    const float* __restrict__ Wj1, const float* __restrict__ bj1,
                    const float* __restrict__ Wj2, const float* __restrict__ bj2,
                    float* __restrict__ out, int N)
{
    __shared__ float Wi1s[4096], Wj1s[2048];
    __shared__ float bi1s[128], bj1s[128], Wi2s[128], Wj2s[128];
    __shared__ float warpsum[8];

    int tid = threadIdx.x;
    for (int i = tid; i < 4096; i += 256) Wi1s[i] = Wi1[i];
    for (int i = tid; i < 2048; i += 256) Wj1s[i] = Wj1[i];
    if (tid < 128) {
        bi1s[tid] = bi1[tid]; bj1s[tid] = bj1[tid];
        Wi2s[tid] = Wi2[tid]; Wj2s[tid] = Wj2[tid];
    }
    __syncthreads();

    int lane = tid & 31, w = tid >> 5;
    int n = blockIdx.x * 8 + w;
    float contrib = 0.f;

    if (n < N) {
        const float* h  = g_h[h_slot] + n * 16;
        const float* h0 = g_h[0] + n * 16;
        float hv  = (lane < 16) ? h[lane]  : 0.f;
        float h0v = (lane < 16) ? h0[lane] : 0.f;

        float a0 = bi1s[lane], a1 = bi1s[lane + 32], a2 = bi1s[lane + 64], a3 = bi1s[lane + 96];
#pragma unroll
        for (int c = 0; c < 32; ++c) {
            float cc = __shfl_sync(0xffffffffu, (c < 16) ? hv : h0v, c & 15);
            a0 += cc * Wi1s[c * 128 + lane];
            a1 += cc * Wi1s[c * 128 + lane + 32];
            a2 += cc * Wi1s[c * 128 + lane + 64];
            a3 += cc * Wi1s[c * 128 + lane + 96];
        }
        a0 = fmaxf(a0, 0.f); a1 = fmaxf(a1, 0.f); a2 = fmaxf(a2, 0.f); a3 = fmaxf(a3, 0.f);
        float g = a0 * Wi2s[lane] + a1 * Wi2s[lane + 32] + a2 * Wi2s[lane + 64] + a3 * Wi2s[lane + 96];

        float v0 = bj1s[lane], v1 = bj1s[lane + 32], v2 = bj1s[lane + 64], v3 = bj1s[lane + 96];
#pragma unroll
        for (int c = 0; c < 16; ++c) {
            float cc = __shfl_sync(0xffffffffu, hv, c);
            v0 += cc * Wj1s[c * 128 + lane];
            v1 += cc * Wj1s[c * 128 + lane + 32];
            v2 += cc * Wj1s[c * 128 + lane + 64];
            v3 += cc * Wj1s[c * 128 + lane + 96];
        }
        v0 = fmaxf(v0, 0.f); v1 = fmaxf(v1, 0.f); v2 = fmaxf(v2, 0.f); v3 = fmaxf(v3, 0.f);
        float vv = v0 * Wj2s[lane] + v1 * Wj2s[lane + 32] + v2 * Wj2s[lane + 64] + v3 * Wj2s[lane + 96];

#pragma unroll
        for (int s = 16; s > 0; s >>= 1) {
            g  += __shfl_xor_sync(0xffffffffu, g, s);
            vv += __shfl_xor_sync(0xffffffffu, vv, s);
        }
        if (lane == 0) {
            float gate = 1.f / (1.f + expf(-(g + bi2[0])));
            contrib = gate * (vv + bj2[0]);
        }
    }
    if (lane == 0) warpsum[w] = contrib;
    __syncthreads();
    if (tid == 0) {
        float s = 0.f;
#pragma unroll
        for (int i = 0; i < 8; ++i) s += warpsum[i];
        atomicAdd(out, s);
    }
}

// ===========================================================================
extern "C" void kernel_launch(void* const* d_in, const int* in_sizes, int n_in,
                              void* d_out, int out_size)
{
    const float* x          = (const float*)d_in[0];
    const int*   edge_index = (const int*)  d_in[1];
    const float* edge_attr  = (const float*)d_in[2];
    const float* W1  = (const float*)d_in[3];
    const float* b1  = (const float*)d_in[4];
    const float* W2  = (const float*)d_in[5];
    const float* b2  = (const float*)d_in[6];
    const float* W3  = (const float*)d_in[7];
    const float* b3  = (const float*)d_in[8];
    const float* root = (const float*)d_in[9];
    const float* bias = (const float*)d_in[10];
    const float* Wi1 = (const float*)d_in[11];
    const float* bi1 = (const float*)d_in[12];
    const float* Wi2 = (const float*)d_in[13];
    const float* bi2 = (const float*)d_in[14];
    const float* Wj1 = (const float*)d_in[15];
    const float* bj1 = (const float*)d_in[16];
    const float* Wj2 = (const float*)d_in[17];
    const float* bj2 = (const float*)d_in[18];

    int N = in_sizes[0] / 8;  if (N > NMAX) N = NMAX;
    int E = in_sizes[1] / 2;  if (E > EMAX) E = EMAX;
    float* out = (float*)d_out;

    cudaFuncSetAttribute(fused_edge_kernel,
                         cudaFuncAttributeMaxDynamicSharedMemorySize, FZ_SMEM);

    int node_blocks = (N * 16 + 255) / 256;
    int edge_blocks = (E + 7) / 8;
    int ntiles      = (E + 255) / 256;
    int fused_grid  = ntiles < 148 ? ntiles : 148;

    w3_split_kernel<<<64, 256>>>(W3);
    w2_split_kernel<<<16, 256>>>(W2);
    init_h_kernel<<<node_blocks, 256>>>(x, N);
    node_init_kernel<<<node_blocks, 256>>>(0, 1, root, bias, N);
    zero_out_kernel<<<1, 32>>>(out);

    // Fused: edge MLP + coalesced Wedge store + message pass 1 (0 -> 1)
    fused_edge_kernel<<<fused_grid, 256, FZ_SMEM>>>(edge_attr, edge_index,
                                                    W1, b1, b2, b3, E, ntiles);

    // Passes 2 and 3
    node_init_kernel<<<node_blocks, 256>>>(1, 2, root, bias, N);
    msg_kernel<<<edge_blocks, 256>>>(1, 2, edge_index, E);
    node_init_kernel<<<node_blocks, 256>>>(2, 1, root, bias, N);
    msg_kernel<<<edge_blocks, 256>>>(2, 1, edge_index, E);

    readout_kernel<<<(N + 7) / 8, 256>>>(1, Wi1, bi1, Wi2, bi2,
                                         Wj1, bj1, Wj2, bj2, out, N);
}